// round 9
// baseline (speedup 1.0000x reference)
#include <cuda_runtime.h>
#include <cuda_fp16.h>
#include <cstdint>

#define NN 100000
#define EE 3200000
#define SCAN_B 512
#define NBLK_SCAN ((NN + SCAN_B - 1) / SCAN_B)

#define TILE 64              // nodes per fused CTA
#define LDT 136              // halves per staged row (+8 pad)
#define TSLICE (TILE * LDT * 2)   // 17408 bytes per tile slice
#define K1_SMEM (TSLICE + 34816)          // A tile + W tile      = 52224
#define K2_SMEM (3 * TSLICE + 34816)      // 3 t-slices + W tile  = 87040

// -------- device scratch (no cudaMalloc allowed) --------
__device__ __half g_pxh[NN * 128];       // fp16 dis-prescaled x
__device__ __half g_ph[3][NN * 128];     // per-scale dis*LN(relu(...)) fp16
__device__ __half g_pzh[NN * 64];        // fp16 tail
__device__ float  g_wc[384 * 64];
__device__ __half g_w0h[3 * 128 * 128], g_w0l[3 * 128 * 128];
__device__ __half g_w1h[3 * 128 * 128], g_w1l[3 * 128 * 128];
__device__ __half g_wch[3 * 128 * 64],  g_wcl[3 * 128 * 64];
__device__ float  g_cbias[64];
__device__ float  g_dis[NN];
__device__ int    g_deg[NN];
__device__ int    g_rowptr[NN];
__device__ int    g_cursor[NN];
__device__ int    g_col[EE];
__device__ int    g_bsum[NBLK_SCAN + 1];

// ---------------------------------------------------------------------------
// graph prep
// ---------------------------------------------------------------------------
__global__ void zero_kernel(int* deg, int* cur, int n) {
    int i = blockIdx.x * blockDim.x + threadIdx.x;
    if (i < n) { deg[i] = 0; cur[i] = 0; }
}

__global__ void count_kernel(const int* __restrict__ dst, int* __restrict__ deg, int e) {
    int i = blockIdx.x * blockDim.x + threadIdx.x;
    if (i < e) atomicAdd(&deg[dst[i]], 1);
}

__global__ void dis_kernel(const int* __restrict__ deg, float* __restrict__ dis, int n) {
    int i = blockIdx.x * blockDim.x + threadIdx.x;
    if (i < n) dis[i] = rsqrtf((float)deg[i] + 1.0f);
}

__global__ void scan1_kernel(const int* __restrict__ deg, int* __restrict__ out,
                             int* __restrict__ bsum, int n) {
    __shared__ int sh[SCAN_B];
    int tid = threadIdx.x;
    int i = blockIdx.x * SCAN_B + tid;
    int v = (i < n) ? deg[i] : 0;
    sh[tid] = v;
    __syncthreads();
#pragma unroll
    for (int off = 1; off < SCAN_B; off <<= 1) {
        int t = (tid >= off) ? sh[tid - off] : 0;
        __syncthreads();
        sh[tid] += t;
        __syncthreads();
    }
    if (i < n) out[i] = sh[tid] - v;
    if (tid == SCAN_B - 1) bsum[blockIdx.x] = sh[tid];
}

__global__ void scan2_kernel(int* bsum, int nb) {
    if (threadIdx.x == 0 && blockIdx.x == 0) {
        int acc = 0;
        for (int i = 0; i < nb; i++) { int t = bsum[i]; bsum[i] = acc; acc += t; }
    }
}

__global__ void scan3_kernel(int* __restrict__ out, const int* __restrict__ bsum, int n) {
    int i = blockIdx.x * blockDim.x + threadIdx.x;
    if (i < n) out[i] += bsum[i / SCAN_B];
}

__global__ void fill_kernel(const int* __restrict__ src, const int* __restrict__ dst,
                            const int* __restrict__ rowptr, int* __restrict__ cur,
                            int* __restrict__ col, int e) {
    int i = blockIdx.x * blockDim.x + threadIdx.x;
    if (i < e) {
        int d = dst[i];
        int pos = rowptr[d] + atomicAdd(&cur[d], 1);
        col[pos] = src[i];
    }
}

// ---------------------------------------------------------------------------
// weight folding / conversion / prescale
// ---------------------------------------------------------------------------
__global__ void wc_kernel(const float* __restrict__ W2, const float* __restrict__ Wf,
                          float* __restrict__ Wc) {
    int r = blockIdx.x;
    int s = r >> 7, i = r & 127;
    int j = threadIdx.x;
    float acc = 0.0f;
#pragma unroll 8
    for (int k = 0; k < 64; k++)
        acc = fmaf(W2[(s * 128 + i) * 64 + k], Wf[(s * 64 + k) * 64 + j], acc);
    Wc[r * 64 + j] = acc;
}

__global__ void cbias_kernel(const float* __restrict__ b2, const float* __restrict__ Wf,
                             const float* __restrict__ bf, float* __restrict__ cb) {
    int j = threadIdx.x;
    float acc = bf[j];
#pragma unroll 8
    for (int r = 0; r < 192; r++) acc = fmaf(b2[r], Wf[r * 64 + j], acc);
    cb[j] = acc;
}

__global__ void convh_kernel(const float* __restrict__ W, __half* __restrict__ Wh,
                             __half* __restrict__ Wl, int n) {
    int i = blockIdx.x * blockDim.x + threadIdx.x;
    if (i < n) {
        float w = W[i];
        __half h = __float2half_rn(w);
        Wh[i] = h;
        Wl[i] = __float2half_rn(w - __half2float(h));
    }
}

__global__ void prescale_h_kernel(const float4* __restrict__ x, const float* __restrict__ dis,
                                  uint2* __restrict__ px, int n4) {
    int i = blockIdx.x * blockDim.x + threadIdx.x;
    if (i < n4) {
        float s = dis[i >> 5];
        float4 v = x[i];
        __half2 h0 = __floats2half2_rn(v.x * s, v.y * s);
        __half2 h1 = __floats2half2_rn(v.z * s, v.w * s);
        uint2 u;
        u.x = *(uint32_t*)&h0; u.y = *(uint32_t*)&h1;
        px[i] = u;
    }
}

// ---------------------------------------------------------------------------
// PTX helpers
// ---------------------------------------------------------------------------
__device__ __forceinline__ uint32_t smem_u32(const void* p) {
    uint32_t a;
    asm("{ .reg .u64 t; cvta.to.shared.u64 t, %1; cvt.u32.u64 %0, t; }"
        : "=r"(a) : "l"(p));
    return a;
}

#define LDSM_X4(r, addr)                                                      \
    asm volatile("ldmatrix.sync.aligned.m8n8.x4.shared.b16 {%0,%1,%2,%3}, [%4];" \
                 : "=r"((r)[0]), "=r"((r)[1]), "=r"((r)[2]), "=r"((r)[3])     \
                 : "r"(addr))

#define LDSM_X2T(r, addr)                                                     \
    asm volatile("ldmatrix.sync.aligned.m8n8.x2.trans.shared.b16 {%0,%1}, [%2];" \
                 : "=r"((r)[0]), "=r"((r)[1]) : "r"(addr))

#define MMA_F16(d, a, b)                                                      \
    asm volatile("mma.sync.aligned.m16n8k16.row.col.f32.f16.f16.f32 "         \
                 "{%0,%1,%2,%3}, {%4,%5,%6,%7}, {%8,%9}, {%0,%1,%2,%3};"      \
                 : "+f"((d)[0]), "+f"((d)[1]), "+f"((d)[2]), "+f"((d)[3])     \
                 : "r"((a)[0]), "r"((a)[1]), "r"((a)[2]), "r"((a)[3]),        \
                   "r"((b)[0]), "r"((b)[1]))

// ---------------------------------------------------------------------------
// K1: fused agg_y + GEMM0(x3 scales, fp16 hi/lo weights) + LN -> ph[3]
// One CTA = 64 nodes. smem: [ y tile 17408 | W tile 34816 ]
// ---------------------------------------------------------------------------
__global__ void __launch_bounds__(256, 2)
fused_l0_kernel(const __half* __restrict__ pxh, const float* __restrict__ dis,
                const int* __restrict__ rp, const int* __restrict__ deg,
                const int* __restrict__ col,
                const __half* __restrict__ w0h, const __half* __restrict__ w0l,
                const float* __restrict__ b0, const float* __restrict__ gamma,
                const float* __restrict__ beta,
                __half* __restrict__ ph, int n) {
    extern __shared__ char smem[];
    __shared__ float sh_b[3][128], sh_g[3][128], sh_be[3][128];
    const int WOFF = TSLICE;

    int tid = threadIdx.x, wid = tid >> 5, lane = tid & 31;
    int m0 = blockIdx.x * TILE;
    uint32_t sb = smem_u32(smem);

    if (tid < 128) {
#pragma unroll
        for (int s = 0; s < 3; s++) {
            sh_b[s][tid]  = b0[s * 128 + tid];
            sh_g[s][tid]  = gamma[(s * 3 + 0) * 128 + tid];
            sh_be[s][tid] = beta[(s * 3 + 0) * 128 + tid];
        }
    }

    // ---- gather phase: 8 nodes per warp, lane covers cols [4L,4L+4)
    const uint2* p2 = (const uint2*)pxh;
#pragma unroll 1
    for (int k = 0; k < 8; k++) {
        int vl = wid * 8 + k;
        int v = m0 + vl;
        float ax = 0.f, ay = 0.f, az = 0.f, aw = 0.f;
        if (v < n) {
            uint2 a = p2[(size_t)v * 32 + lane];
            float2 f0 = __half22float2(*(__half2*)&a.x);
            float2 f1 = __half22float2(*(__half2*)&a.y);
            ax = f0.x; ay = f0.y; az = f1.x; aw = f1.y;
            int start = rp[v], d = deg[v], c0 = 0;
            for (; c0 + 32 <= d; c0 += 32) {
                int idx = col[start + c0 + lane];
#pragma unroll 8
                for (int j = 0; j < 32; j++) {
                    int u = __shfl_sync(0xffffffffu, idx, j);
                    uint2 vv = p2[(size_t)u * 32 + lane];
                    float2 g0 = __half22float2(*(__half2*)&vv.x);
                    float2 g1 = __half22float2(*(__half2*)&vv.y);
                    ax += g0.x; ay += g0.y; az += g1.x; aw += g1.y;
                }
            }
            int m = d - c0;
            if (m > 0) {
                int idx = (lane < m) ? col[start + c0 + lane] : 0;
                for (int j = 0; j < m; j++) {
                    int u = __shfl_sync(0xffffffffu, idx, j);
                    uint2 vv = p2[(size_t)u * 32 + lane];
                    float2 g0 = __half22float2(*(__half2*)&vv.x);
                    float2 g1 = __half22float2(*(__half2*)&vv.y);
                    ax += g0.x; ay += g0.y; az += g1.x; aw += g1.y;
                }
            }
            float s = dis[v];
            ax *= s; ay *= s; az *= s; aw *= s;
        }
        __half2 h0 = __floats2half2_rn(ax, ay);
        __half2 h1 = __floats2half2_rn(az, aw);
        uint2 o;
        o.x = *(uint32_t*)&h0; o.y = *(uint32_t*)&h1;
        *(uint2*)(smem + (vl * LDT + lane * 4) * 2) = o;
    }

    // ---- MMA phase
    int warp_m = wid & 1, warp_n = wid >> 1;
    int a_r = lane & 15, a_c8 = (lane >> 4) * 8, b_r = lane & 15;
    int g = lane >> 2, q2 = (lane & 3) * 2;

    for (int s = 0; s < 3; s++) {
        float acc[2][4][4];
#pragma unroll
        for (int i = 0; i < 2; i++)
#pragma unroll
            for (int j = 0; j < 4; j++)
#pragma unroll
                for (int q = 0; q < 4; q++) acc[i][j][q] = 0.f;

#pragma unroll
        for (int p = 0; p < 2; p++) {
            __syncthreads();   // W region free (covers gather on first pass)
            const __half* Wsrc = (p ? w0l : w0h) + s * 16384;
#pragma unroll
            for (int it = 0; it < 8; it++) {
                int idx = it * 256 + tid;
                int kk = idx >> 4, u4 = idx & 15;
                *(uint4*)(smem + WOFF + (kk * LDT + u4 * 8) * 2) =
                    *(const uint4*)(Wsrc + kk * 128 + u4 * 8);
            }
            __syncthreads();
#pragma unroll
            for (int ks = 0; ks < 8; ks++) {
                uint32_t af[2][4], bf4[4][2];
#pragma unroll
                for (int mi = 0; mi < 2; mi++)
                    LDSM_X4(af[mi], sb + ((warp_m * 32 + mi * 16 + a_r) * LDT
                                          + ks * 16 + a_c8) * 2);
#pragma unroll
                for (int nj = 0; nj < 4; nj++)
                    LDSM_X2T(bf4[nj], sb + WOFF + ((ks * 16 + b_r) * LDT
                                                   + warp_n * 32 + nj * 8) * 2);
#pragma unroll
                for (int mi = 0; mi < 2; mi++)
#pragma unroll
                    for (int nj = 0; nj < 4; nj++)
                        MMA_F16(acc[mi][nj], af[mi], bf4[nj]);
            }
        }

        // exchange acc -> f32 smem (reuses W region), LN, write ph_s global
        __syncthreads();
        float* Cs = (float*)(smem + WOFF);   // [64][129]
#pragma unroll
        for (int mi = 0; mi < 2; mi++)
#pragma unroll
            for (int nj = 0; nj < 4; nj++) {
                int rl = warp_m * 32 + mi * 16 + g;
                int c = warp_n * 32 + nj * 8 + q2;
                Cs[rl * 129 + c]           = acc[mi][nj][0];
                Cs[rl * 129 + c + 1]       = acc[mi][nj][1];
                Cs[(rl + 8) * 129 + c]     = acc[mi][nj][2];
                Cs[(rl + 8) * 129 + c + 1] = acc[mi][nj][3];
            }
        __syncthreads();

        int row = tid >> 2, q = tid & 3;
        float s1 = 0.f, s2 = 0.f;
#pragma unroll
        for (int j = 0; j < 32; j++) {
            float t = fmaxf(Cs[row * 129 + q * 32 + j] + sh_b[s][q * 32 + j], 0.f);
            s1 += t; s2 += t * t;
        }
        s1 += __shfl_xor_sync(0xffffffffu, s1, 1);
        s2 += __shfl_xor_sync(0xffffffffu, s2, 1);
        s1 += __shfl_xor_sync(0xffffffffu, s1, 2);
        s2 += __shfl_xor_sync(0xffffffffu, s2, 2);
        float mu = s1 * (1.0f / 128.0f);
        float var = s2 * (1.0f / 128.0f) - mu * mu;
        float inv = rsqrtf(var + 1e-5f);

        int rg = m0 + row;
        if (rg < n) {
            float sc = dis[rg];
            __half* outp = ph + (size_t)s * NN * 128 + (size_t)rg * 128 + q * 32;
#pragma unroll
            for (int j = 0; j < 32; j += 8) {
                float o[8];
#pragma unroll
                for (int e = 0; e < 8; e++) {
                    float t = fmaxf(Cs[row * 129 + q * 32 + j + e]
                                    + sh_b[s][q * 32 + j + e], 0.f);
                    o[e] = ((t - mu) * inv * sh_g[s][q * 32 + j + e]
                            + sh_be[s][q * 32 + j + e]) * sc;
                }
                __half2 h0 = __floats2half2_rn(o[0], o[1]);
                __half2 h1 = __floats2half2_rn(o[2], o[3]);
                __half2 h2 = __floats2half2_rn(o[4], o[5]);
                __half2 h3 = __floats2half2_rn(o[6], o[7]);
                uint4 u;
                u.x = *(uint32_t*)&h0; u.y = *(uint32_t*)&h1;
                u.z = *(uint32_t*)&h2; u.w = *(uint32_t*)&h3;
                *(uint4*)(outp + j) = u;
            }
        }
        // next scale's W staging has a leading __syncthreads()
    }
}

// ---------------------------------------------------------------------------
// K2: fused agg384 (3-scale gather) + GEMM1(x3) + LN + folded-tail GEMM -> pzh
// One CTA = 64 nodes. smem: [ t0 | t1 | t2 (17408 each) | W tile 34816 ]
// ---------------------------------------------------------------------------
__global__ void __launch_bounds__(256, 2)
fused_l1_kernel(const __half* __restrict__ ph, const float* __restrict__ dis,
                const int* __restrict__ rp, const int* __restrict__ deg,
                const int* __restrict__ col,
                const __half* __restrict__ w1h, const __half* __restrict__ w1l,
                const __half* __restrict__ wch, const __half* __restrict__ wcl,
                const float* __restrict__ b1, const float* __restrict__ gamma,
                const float* __restrict__ beta,
                __half* __restrict__ pzh, int n) {
    extern __shared__ char smem[];
    __shared__ float sh_b[3][128], sh_g[3][128], sh_be[3][128];
    const int WOFF = 3 * TSLICE;

    int tid = threadIdx.x, wid = tid >> 5, lane = tid & 31;
    int m0 = blockIdx.x * TILE;
    uint32_t sb = smem_u32(smem);

    if (tid < 128) {
#pragma unroll
        for (int s = 0; s < 3; s++) {
            sh_b[s][tid]  = b1[s * 128 + tid];
            sh_g[s][tid]  = gamma[(s * 3 + 1) * 128 + tid];
            sh_be[s][tid] = beta[(s * 3 + 1) * 128 + tid];
        }
    }

    // ---- gather phase (3 scales at once)
    const uint2* q0 = (const uint2*)ph;
    const uint2* q1 = (const uint2*)(ph + (size_t)NN * 128);
    const uint2* q2p = (const uint2*)(ph + (size_t)2 * NN * 128);
#pragma unroll 1
    for (int k = 0; k < 8; k++) {
        int vl = wid * 8 + k;
        int v = m0 + vl;
        float acc[12];
#pragma unroll
        for (int i = 0; i < 12; i++) acc[i] = 0.f;
        if (v < n) {
            size_t soff = (size_t)v * 32 + lane;
            uint2 a0 = q0[soff], a1 = q1[soff], a2 = q2p[soff];
            float2 f;
            f = __half22float2(*(__half2*)&a0.x); acc[0] = f.x;  acc[1] = f.y;
            f = __half22float2(*(__half2*)&a0.y); acc[2] = f.x;  acc[3] = f.y;
            f = __half22float2(*(__half2*)&a1.x); acc[4] = f.x;  acc[5] = f.y;
            f = __half22float2(*(__half2*)&a1.y); acc[6] = f.x;  acc[7] = f.y;
            f = __half22float2(*(__half2*)&a2.x); acc[8] = f.x;  acc[9] = f.y;
            f = __half22float2(*(__half2*)&a2.y); acc[10] = f.x; acc[11] = f.y;
            int start = rp[v], d = deg[v], c0 = 0;
            for (; c0 + 32 <= d; c0 += 32) {
                int idx = col[start + c0 + lane];
#pragma unroll 4
                for (int j = 0; j < 32; j++) {
                    int u = __shfl_sync(0xffffffffu, idx, j);
                    size_t off = (size_t)u * 32 + lane;
                    uint2 v0 = q0[off], v1 = q1[off], v2 = q2p[off];
                    f = __half22float2(*(__half2*)&v0.x); acc[0] += f.x;  acc[1] += f.y;
                    f = __half22float2(*(__half2*)&v0.y); acc[2] += f.x;  acc[3] += f.y;
                    f = __half22float2(*(__half2*)&v1.x); acc[4] += f.x;  acc[5] += f.y;
                    f = __half22float2(*(__half2*)&v1.y); acc[6] += f.x;  acc[7] += f.y;
                    f = __half22float2(*(__half2*)&v2.x); acc[8] += f.x;  acc[9] += f.y;
                    f = __half22float2(*(__half2*)&v2.y); acc[10] += f.x; acc[11] += f.y;
                }
            }
            int m = d - c0;
            if (m > 0) {
                int idx = (lane < m) ? col[start + c0 + lane] : 0;
                for (int j = 0; j < m; j++) {
                    int u = __shfl_sync(0xffffffffu, idx, j);
                    size_t off = (size_t)u * 32 + lane;
                    uint2 v0 = q0[off], v1 = q1[off], v2 = q2p[off];
                    f = __half22float2(*(__half2*)&v0.x); acc[0] += f.x;  acc[1] += f.y;
                    f = __half22float2(*(__half2*)&v0.y); acc[2] += f.x;  acc[3] += f.y;
                    f = __half22float2(*(__half2*)&v1.x); acc[4] += f.x;  acc[5] += f.y;
                    f = __half22float2(*(__half2*)&v1.y); acc[6] += f.x;  acc[7] += f.y;
                    f = __half22float2(*(__half2*)&v2.x); acc[8] += f.x;  acc[9] += f.y;
                    f = __half22float2(*(__half2*)&v2.y); acc[10] += f.x; acc[11] += f.y;
                }
            }
            float sdv = dis[v];
#pragma unroll
            for (int i = 0; i < 12; i++) acc[i] *= sdv;
        }
#pragma unroll
        for (int s = 0; s < 3; s++) {
            __half2 h0 = __floats2half2_rn(acc[s * 4 + 0], acc[s * 4 + 1]);
            __half2 h1 = __floats2half2_rn(acc[s * 4 + 2], acc[s * 4 + 3]);
            uint2 o;
            o.x = *(uint32_t*)&h0; o.y = *(uint32_t*)&h1;
            *(uint2*)(smem + s * TSLICE + (vl * LDT + lane * 4) * 2) = o;
        }
    }

    // ---- per-scale GEMM1 + LN + tail-GEMM accumulation
    int warp_m = wid & 1, warp_n = wid >> 1;
    int a_r = lane & 15, a_c8 = (lane >> 4) * 8, b_r = lane & 15;
    int g = lane >> 2, q2 = (lane & 3) * 2;

    float pzacc[2][2][4];
#pragma unroll
    for (int i = 0; i < 2; i++)
#pragma unroll
        for (int j = 0; j < 2; j++)
#pragma unroll
            for (int q = 0; q < 4; q++) pzacc[i][j][q] = 0.f;

    for (int s = 0; s < 3; s++) {
        float acc[2][4][4];
#pragma unroll
        for (int i = 0; i < 2; i++)
#pragma unroll
            for (int j = 0; j < 4; j++)
#pragma unroll
                for (int q = 0; q < 4; q++) acc[i][j][q] = 0.f;

        // GEMM1: t_s @ W1_s (hi, lo)
#pragma unroll
        for (int p = 0; p < 2; p++) {
            __syncthreads();
            const __half* Wsrc = (p ? w1l : w1h) + s * 16384;
#pragma unroll
            for (int it = 0; it < 8; it++) {
                int idx = it * 256 + tid;
                int kk = idx >> 4, u4 = idx & 15;
                *(uint4*)(smem + WOFF + (kk * LDT + u4 * 8) * 2) =
                    *(const uint4*)(Wsrc + kk * 128 + u4 * 8);
            }
            __syncthreads();
#pragma unroll
            for (int ks = 0; ks < 8; ks++) {
                uint32_t af[2][4], bf4[4][2];
#pragma unroll
                for (int mi = 0; mi < 2; mi++)
                    LDSM_X4(af[mi], sb + s * TSLICE
                            + ((warp_m * 32 + mi * 16 + a_r) * LDT + ks * 16 + a_c8) * 2);
#pragma unroll
                for (int nj = 0; nj < 4; nj++)
                    LDSM_X2T(bf4[nj], sb + WOFF + ((ks * 16 + b_r) * LDT
                                                   + warp_n * 32 + nj * 8) * 2);
#pragma unroll
                for (int mi = 0; mi < 2; mi++)
#pragma unroll
                    for (int nj = 0; nj < 4; nj++)
                        MMA_F16(acc[mi][nj], af[mi], bf4[nj]);
            }
        }

        // exchange + LN -> u written back into t_s slice (fp16)
        __syncthreads();
        float* Cs = (float*)(smem + WOFF);   // [64][129] f32 = 33024 <= 34816
#pragma unroll
        for (int mi = 0; mi < 2; mi++)
#pragma unroll
            for (int nj = 0; nj < 4; nj++) {
                int rl = warp_m * 32 + mi * 16 + g;
                int c = warp_n * 32 + nj * 8 + q2;
                Cs[rl * 129 + c]           = acc[mi][nj][0];
                Cs[rl * 129 + c + 1]       = acc[mi][nj][1];
                Cs[(rl + 8) * 129 + c]     = acc[mi][nj][2];
                Cs[(rl + 8) * 129 + c + 1] = acc[mi][nj][3];
            }
        __syncthreads();

        {
            int row = tid >> 2, q = tid & 3;
            float s1 = 0.f, s2 = 0.f;
#pragma unroll
            for (int j = 0; j < 32; j++) {
                float t = fmaxf(Cs[row * 129 + q * 32 + j] + sh_b[s][q * 32 + j], 0.f);
                s1 += t; s2 += t * t;
            }
            s1 += __shfl_xor_sync(0xffffffffu, s1, 1);
            s2 += __shfl_xor_sync(0xffffffffu, s2, 1);
            s1 += __shfl_xor_sync(0xffffffffu, s1, 2);
            s2 += __shfl_xor_sync(0xffffffffu, s2, 2);
            float mu = s1 * (1.0f / 128.0f);
            float var = s2 * (1.0f / 128.0f) - mu * mu;
            float inv = rsqrtf(var + 1e-5f);
#pragma unroll
            for (int j = 0; j < 32; j += 8) {
                float o[8];
#pragma unroll
                for (int e = 0; e < 8; e++) {
                    float t = fmaxf(Cs[row * 129 + q * 32 + j + e]
                                    + sh_b[s][q * 32 + j + e], 0.f);
                    o[e] = (t - mu) * inv * sh_g[s][q * 32 + j + e]
                           + sh_be[s][q * 32 + j + e];
                }
                __half2 h0 = __floats2half2_rn(o[0], o[1]);
                __half2 h1 = __floats2half2_rn(o[2], o[3]);
                __half2 h2 = __floats2half2_rn(o[4], o[5]);
                __half2 h3 = __floats2half2_rn(o[6], o[7]);
                uint4 u;
                u.x = *(uint32_t*)&h0; u.y = *(uint32_t*)&h1;
                u.z = *(uint32_t*)&h2; u.w = *(uint32_t*)&h3;
                *(uint4*)(smem + s * TSLICE + (row * LDT + q * 32 + j) * 2) = u;
            }
        }
        __syncthreads();

        // tail GEMM: pz += u_s @ Wc_s (hi, lo); Wc staged [128][72]
#pragma unroll
        for (int p = 0; p < 2; p++) {
            const __half* Wsrc = (p ? wcl : wch) + s * 8192;
#pragma unroll
            for (int it = 0; it < 4; it++) {
                int idx = it * 256 + tid;    // 1024 uint4
                int kk = idx >> 3, u4 = idx & 7;
                *(uint4*)(smem + WOFF + (kk * 72 + u4 * 8) * 2) =
                    *(const uint4*)(Wsrc + kk * 64 + u4 * 8);
            }
            __syncthreads();
#pragma unroll
            for (int ks = 0; ks < 8; ks++) {
                uint32_t af[2][4], bft[2][2];
#pragma unroll
                for (int mi = 0; mi < 2; mi++)
                    LDSM_X4(af[mi], sb + s * TSLICE
                            + ((warp_m * 32 + mi * 16 + a_r) * LDT + ks * 16 + a_c8) * 2);
#pragma unroll
                for (int nj = 0; nj < 2; nj++)
                    LDSM_X2T(bft[nj], sb + WOFF + ((ks * 16 + b_r) * 72
                                                   + warp_n * 16 + nj * 8) * 2);
#pragma unroll
                for (int mi = 0; mi < 2; mi++)
#pragma unroll
                    for (int nj = 0; nj < 2; nj++)
                        MMA_F16(pzacc[mi][nj], af[mi], bft[nj]);
            }
            __syncthreads();
        }
    }

    // ---- pz epilogue: pzh[r, c] = fp16(pzacc * dis[r])
#pragma unroll
    for (int mi = 0; mi < 2; mi++)
#pragma unroll
        for (int nj = 0; nj < 2; nj++) {
            int c = warp_n * 16 + nj * 8 + q2;
            int r0 = m0 + warp_m * 32 + mi * 16 + g;
            if (r0 < n) {
                float s = dis[r0];
                __half2 h = __floats2half2_rn(pzacc[mi][nj][0] * s, pzacc[mi][nj][1] * s);
                *(uint32_t*)(pzh + (size_t)r0 * 64 + c) = *(uint32_t*)&h;
            }
            int r1 = r0 + 8;
            if (r1 < n) {
                float s = dis[r1];
                __half2 h = __floats2half2_rn(pzacc[mi][nj][2] * s, pzacc[mi][nj][3] * s);
                *(uint32_t*)(pzh + (size_t)r1 * 64 + c) = *(uint32_t*)&h;
            }
        }
}

// ---------------------------------------------------------------------------
// final aggregation: fp16 64-wide gather -> fp32 out + cbias
// ---------------------------------------------------------------------------
__global__ void __launch_bounds__(256)
agg64h_kernel(const uint32_t* __restrict__ p, const float* __restrict__ dis,
              const int* __restrict__ rowptr, const int* __restrict__ deg,
              const int* __restrict__ col, const float* __restrict__ cbias,
              float2* __restrict__ out, int n) {
    int w = (blockIdx.x * blockDim.x + threadIdx.x) >> 5;
    if (w >= n) return;
    int lane = threadIdx.x & 31;
    int start = rowptr[w], d = deg[w];
    uint32_t a = p[(size_t)w * 32 + lane];
    float2 f = __half22float2(*(__half2*)&a);
    float ax = f.x, ay = f.y;

    int c0 = 0;
    for (; c0 + 32 <= d; c0 += 32) {
        int idx = col[start + c0 + lane];
#pragma unroll 8
        for (int j = 0; j < 32; j++) {
            int u = __shfl_sync(0xffffffffu, idx, j);
            uint32_t v = p[(size_t)u * 32 + lane];
            float2 g = __half22float2(*(__half2*)&v);
            ax += g.x; ay += g.y;
        }
    }
    int m = d - c0;
    if (m > 0) {
        int idx = (lane < m) ? col[start + c0 + lane] : 0;
        for (int j = 0; j < m; j++) {
            int u = __shfl_sync(0xffffffffu, idx, j);
            uint32_t v = p[(size_t)u * 32 + lane];
            float2 g = __half22float2(*(__half2*)&v);
            ax += g.x; ay += g.y;
        }
    }
    float s = dis[w];
    float2 o = {ax * s + cbias[lane * 2], ay * s + cbias[lane * 2 + 1]};
    out[(size_t)w * 32 + lane] = o;
}

// ---------------------------------------------------------------------------
extern "C" void kernel_launch(void* const* d_in, const int* in_sizes, int n_in,
                              void* d_out, int out_size) {
    const float* x     = (const float*)d_in[0];
    const int*   ei    = (const int*)d_in[1];
    const float* W0    = (const float*)d_in[2];
    const float* b0    = (const float*)d_in[3];
    const float* W1    = (const float*)d_in[4];
    const float* b1    = (const float*)d_in[5];
    const float* W2    = (const float*)d_in[6];
    const float* b2    = (const float*)d_in[7];
    const float* gamma = (const float*)d_in[8];
    const float* beta  = (const float*)d_in[9];
    const float* Wf    = (const float*)d_in[10];
    const float* bf    = (const float*)d_in[11];
    float* out = (float*)d_out;

    const int N = in_sizes[0] / 128;
    const int E = in_sizes[1] / 2;
    const int* src = ei;
    const int* dst = ei + E;

    __half *pxh, *ph, *pzh, *w0h, *w0l, *w1h, *w1l, *wch, *wcl;
    float *wc, *cbias, *dis;
    int *deg, *rp, *cur, *col, *bsum;
    cudaGetSymbolAddress((void**)&pxh,   g_pxh);
    cudaGetSymbolAddress((void**)&ph,    g_ph);
    cudaGetSymbolAddress((void**)&pzh,   g_pzh);
    cudaGetSymbolAddress((void**)&wc,    g_wc);
    cudaGetSymbolAddress((void**)&w0h,   g_w0h);
    cudaGetSymbolAddress((void**)&w0l,   g_w0l);
    cudaGetSymbolAddress((void**)&w1h,   g_w1h);
    cudaGetSymbolAddress((void**)&w1l,   g_w1l);
    cudaGetSymbolAddress((void**)&wch,   g_wch);
    cudaGetSymbolAddress((void**)&wcl,   g_wcl);
    cudaGetSymbolAddress((void**)&cbias, g_cbias);
    cudaGetSymbolAddress((void**)&dis,   g_dis);
    cudaGetSymbolAddress((void**)&deg,   g_deg);
    cudaGetSymbolAddress((void**)&rp,    g_rowptr);
    cudaGetSymbolAddress((void**)&cur,   g_cursor);
    cudaGetSymbolAddress((void**)&col,   g_col);
    cudaGetSymbolAddress((void**)&bsum,  g_bsum);

    static bool inited = false;
    static cudaStream_t st1, st2;
    static cudaEvent_t evRoot, evDis, evPre, evW;
    if (!inited) {
        cudaStreamCreateWithFlags(&st1, cudaStreamNonBlocking);
        cudaStreamCreateWithFlags(&st2, cudaStreamNonBlocking);
        cudaEventCreateWithFlags(&evRoot, cudaEventDisableTiming);
        cudaEventCreateWithFlags(&evDis, cudaEventDisableTiming);
        cudaEventCreateWithFlags(&evPre, cudaEventDisableTiming);
        cudaEventCreateWithFlags(&evW,  cudaEventDisableTiming);
        cudaFuncSetAttribute(fused_l0_kernel,
                             cudaFuncAttributeMaxDynamicSharedMemorySize, K1_SMEM);
        cudaFuncSetAttribute(fused_l1_kernel,
                             cudaFuncAttributeMaxDynamicSharedMemorySize, K2_SMEM);
        inited = true;
    }

    const int TB = 256;
    int nB = (N + TB - 1) / TB;
    int eB = (E + TB - 1) / TB;
    int nbScan = (N + SCAN_B - 1) / SCAN_B;
    int aggB = (N * 32 + TB - 1) / TB;
    int fB = (N + TILE - 1) / TILE;

    cudaStream_t s0 = 0;

    // capture fork for st1 (weights)
    zero_kernel<<<nB, TB, 0, s0>>>(deg, cur, N);
    cudaEventRecord(evRoot, s0);
    cudaStreamWaitEvent(st1, evRoot, 0);

    // weight folding + fp16 hi/lo conversion on st1
    wc_kernel<<<384, 64, 0, st1>>>(W2, Wf, wc);
    cbias_kernel<<<1, 64, 0, st1>>>(b2, Wf, bf, cbias);
    convh_kernel<<<(3 * 128 * 128 + 255) / 256, 256, 0, st1>>>(W0, w0h, w0l, 3 * 128 * 128);
    convh_kernel<<<(3 * 128 * 128 + 255) / 256, 256, 0, st1>>>(W1, w1h, w1l, 3 * 128 * 128);
    convh_kernel<<<(3 * 128 * 64 + 255) / 256, 256, 0, st1>>>(wc, wch, wcl, 3 * 128 * 64);
    cudaEventRecord(evW, st1);

    // graph prep on s0
    count_kernel<<<eB, TB, 0, s0>>>(dst, deg, E);
    dis_kernel<<<nB, TB, 0, s0>>>(deg, dis, N);
    cudaEventRecord(evDis, s0);

    // prescale on st2 (fork via evDis), concurrent with scan/fill
    cudaStreamWaitEvent(st2, evDis, 0);
    prescale_h_kernel<<<(N * 32 + TB - 1) / TB, TB, 0, st2>>>(
        (const float4*)x, dis, (uint2*)pxh, N * 32);
    cudaEventRecord(evPre, st2);

    scan1_kernel<<<nbScan, SCAN_B, 0, s0>>>(deg, rp, bsum, N);
    scan2_kernel<<<1, 32, 0, s0>>>(bsum, nbScan);
    scan3_kernel<<<nB, TB, 0, s0>>>(rp, bsum, N);
    fill_kernel<<<eB, TB, 0, s0>>>(src, dst, rp, cur, col, E);

    // joins: fused kernels need weights + prescaled x + CSR
    cudaStreamWaitEvent(s0, evW, 0);
    cudaStreamWaitEvent(s0, evPre, 0);

    // K1: agg_y + GEMM0 + LN -> ph[3]
    fused_l0_kernel<<<fB, 256, K1_SMEM, s0>>>(
        pxh, dis, rp, deg, col, w0h, w0l, b0, gamma, beta, ph, N);

    // K2: agg384 + GEMM1 + LN + tail GEMM -> pzh
    fused_l1_kernel<<<fB, 256, K2_SMEM, s0>>>(
        ph, dis, rp, deg, col, w1h, w1l, wch, wcl, b1, gamma, beta, pzh, N);

    // final aggregation -> out
    agg64h_kernel<<<aggB, TB, 0, s0>>>((const uint32_t*)pzh, dis, rp, deg, col,
                                       cbias, (float2*)out, N);
}

// round 10
// speedup vs baseline: 1.4160x; 1.4160x over previous
#include <cuda_runtime.h>
#include <cuda_fp16.h>
#include <cstdint>

#define NN 100000
#define EE 3200000
#define SCAN_B 512
#define NBLK_SCAN ((NN + SCAN_B - 1) / SCAN_B)

// -------- device scratch (no cudaMalloc allowed) --------
__device__ __half g_pxh[NN * 128];       // fp16 dis-prescaled x
__device__ __half g_yh[NN * 128];        // y = A_hat x (fp16)
__device__ __half g_ph[3][NN * 128];     // per-scale dis*LN(relu(...)) fp16
__device__ __half g_th[3][NN * 128];     // per-scale t_s = A_hat ph_s (fp16)
__device__ __half g_hcath[NN * 384];     // fp16 concat
__device__ __half g_pzh[NN * 64];        // fp16 tail
__device__ float  g_wc[384 * 64];
__device__ __half g_w0h[3 * 128 * 128], g_w0l[3 * 128 * 128];
__device__ __half g_w1h[3 * 128 * 128], g_w1l[3 * 128 * 128];
__device__ __half g_wch[384 * 64],      g_wcl[384 * 64];
__device__ float  g_cbias[64];
__device__ float  g_dis[NN];
__device__ int    g_deg[NN];
__device__ int    g_rowptr[NN];
__device__ int    g_cursor[NN];
__device__ int    g_col[EE];
__device__ int    g_bsum[NBLK_SCAN + 1];

// ---------------------------------------------------------------------------
// graph prep
// ---------------------------------------------------------------------------
__global__ void zero_kernel(int* deg, int* cur, int n) {
    int i = blockIdx.x * blockDim.x + threadIdx.x;
    if (i < n) { deg[i] = 0; cur[i] = 0; }
}

__global__ void count_kernel(const int* __restrict__ dst, int* __restrict__ deg, int e) {
    int i = blockIdx.x * blockDim.x + threadIdx.x;
    if (i < e) atomicAdd(&deg[dst[i]], 1);
}

__global__ void dis_kernel(const int* __restrict__ deg, float* __restrict__ dis, int n) {
    int i = blockIdx.x * blockDim.x + threadIdx.x;
    if (i < n) dis[i] = rsqrtf((float)deg[i] + 1.0f);
}

__global__ void scan1_kernel(const int* __restrict__ deg, int* __restrict__ out,
                             int* __restrict__ bsum, int n) {
    __shared__ int sh[SCAN_B];
    int tid = threadIdx.x;
    int i = blockIdx.x * SCAN_B + tid;
    int v = (i < n) ? deg[i] : 0;
    sh[tid] = v;
    __syncthreads();
#pragma unroll
    for (int off = 1; off < SCAN_B; off <<= 1) {
        int t = (tid >= off) ? sh[tid - off] : 0;
        __syncthreads();
        sh[tid] += t;
        __syncthreads();
    }
    if (i < n) out[i] = sh[tid] - v;
    if (tid == SCAN_B - 1) bsum[blockIdx.x] = sh[tid];
}

__global__ void scan2_kernel(int* bsum, int nb) {
    if (threadIdx.x == 0 && blockIdx.x == 0) {
        int acc = 0;
        for (int i = 0; i < nb; i++) { int t = bsum[i]; bsum[i] = acc; acc += t; }
    }
}

__global__ void scan3_kernel(int* __restrict__ out, const int* __restrict__ bsum, int n) {
    int i = blockIdx.x * blockDim.x + threadIdx.x;
    if (i < n) out[i] += bsum[i / SCAN_B];
}

__global__ void fill_kernel(const int* __restrict__ src, const int* __restrict__ dst,
                            const int* __restrict__ rowptr, int* __restrict__ cur,
                            int* __restrict__ col, int e) {
    int i = blockIdx.x * blockDim.x + threadIdx.x;
    if (i < e) {
        int d = dst[i];
        int pos = rowptr[d] + atomicAdd(&cur[d], 1);
        col[pos] = src[i];
    }
}

// ---------------------------------------------------------------------------
// weight folding / conversion / prescale
// ---------------------------------------------------------------------------
__global__ void wc_kernel(const float* __restrict__ W2, const float* __restrict__ Wf,
                          float* __restrict__ Wc) {
    int r = blockIdx.x;
    int s = r >> 7, i = r & 127;
    int j = threadIdx.x;
    float acc = 0.0f;
#pragma unroll 8
    for (int k = 0; k < 64; k++)
        acc = fmaf(W2[(s * 128 + i) * 64 + k], Wf[(s * 64 + k) * 64 + j], acc);
    Wc[r * 64 + j] = acc;
}

__global__ void cbias_kernel(const float* __restrict__ b2, const float* __restrict__ Wf,
                             const float* __restrict__ bf, float* __restrict__ cb) {
    int j = threadIdx.x;
    float acc = bf[j];
#pragma unroll 8
    for (int r = 0; r < 192; r++) acc = fmaf(b2[r], Wf[r * 64 + j], acc);
    cb[j] = acc;
}

__global__ void convh_kernel(const float* __restrict__ W, __half* __restrict__ Wh,
                             __half* __restrict__ Wl, int n) {
    int i = blockIdx.x * blockDim.x + threadIdx.x;
    if (i < n) {
        float w = W[i];
        __half h = __float2half_rn(w);
        Wh[i] = h;
        Wl[i] = __float2half_rn(w - __half2float(h));
    }
}

__global__ void prescale_h_kernel(const float4* __restrict__ x, const float* __restrict__ dis,
                                  uint2* __restrict__ px, int n4) {
    int i = blockIdx.x * blockDim.x + threadIdx.x;
    if (i < n4) {
        float s = dis[i >> 5];
        float4 v = x[i];
        __half2 h0 = __floats2half2_rn(v.x * s, v.y * s);
        __half2 h1 = __floats2half2_rn(v.z * s, v.w * s);
        uint2 u;
        u.x = *(uint32_t*)&h0; u.y = *(uint32_t*)&h1;
        px[i] = u;
    }
}

// ---------------------------------------------------------------------------
// fp16 tensor-core GEMM: A exactly fp16, W split fp16 hi/lo (2 MMA passes)
// EPI 1: LN(relu(acc+bias))            -> fp16 C (ldo/coloff)
// EPI 2: acc * dis[row]                -> fp16 C (row stride BN)
// EPI 3: LN(relu(acc+bias)) * dis[row] -> fp16 C (ldo/coloff)
// ---------------------------------------------------------------------------
__device__ __forceinline__ uint32_t smem_u32(const void* p) {
    uint32_t a;
    asm("{ .reg .u64 t; cvta.to.shared.u64 t, %1; cvt.u32.u64 %0, t; }"
        : "=r"(a) : "l"(p));
    return a;
}

#define LDSM_X4(r, addr)                                                      \
    asm volatile("ldmatrix.sync.aligned.m8n8.x4.shared.b16 {%0,%1,%2,%3}, [%4];" \
                 : "=r"((r)[0]), "=r"((r)[1]), "=r"((r)[2]), "=r"((r)[3])     \
                 : "r"(addr))

#define LDSM_X2T(r, addr)                                                     \
    asm volatile("ldmatrix.sync.aligned.m8n8.x2.trans.shared.b16 {%0,%1}, [%2];" \
                 : "=r"((r)[0]), "=r"((r)[1]) : "r"(addr))

#define MMA_F16(d, a, b)                                                      \
    asm volatile("mma.sync.aligned.m16n8k16.row.col.f32.f16.f16.f32 "         \
                 "{%0,%1,%2,%3}, {%4,%5,%6,%7}, {%8,%9}, {%0,%1,%2,%3};"      \
                 : "+f"((d)[0]), "+f"((d)[1]), "+f"((d)[2]), "+f"((d)[3])     \
                 : "r"((a)[0]), "r"((a)[1]), "r"((a)[2]), "r"((a)[3]),        \
                   "r"((b)[0]), "r"((b)[1]))

template <int KDIM, int BN, int EPI>
__global__ void __launch_bounds__(256)
tgemm_h_kernel(const __half* __restrict__ A, const __half* __restrict__ Wh,
               const __half* __restrict__ Wl,
               const float* __restrict__ dis, const float* __restrict__ bias,
               const float* __restrict__ gamma, const float* __restrict__ beta,
               __half* __restrict__ C, int ldo, int coloff, int nrows) {
    constexpr int LDA = 136;
    constexpr int LDB = BN + 8;
    constexpr int WN = BN / 32;
    constexpr int WM = 8 / WN;
    constexpr int WROWS = 128 / WM;
    constexpr int MI = WROWS / 16;
    constexpr int NJ = 4;
    constexpr int ABYTES = 128 * LDA * 2;
    constexpr int BBYTES = 128 * LDB * 2;
    constexpr int AH = 0, BH = ABYTES, BL = BH + BBYTES;
    constexpr int NU4 = BN / 8;

    extern __shared__ char smem[];
    __shared__ float sh_bias[128], sh_g[128], sh_b[128];

    int tid = threadIdx.x, wid = tid >> 5, lane = tid & 31;
    int warp_m = wid % WM, warp_n = wid / WM;
    int m0 = blockIdx.x * 128;
    uint32_t sb = smem_u32(smem);

    if (EPI != 2 && tid < 128) {
        sh_bias[tid] = bias[tid];
        sh_g[tid] = gamma[tid];
        sh_b[tid] = beta[tid];
    }

    float acc[MI][NJ][4];
#pragma unroll
    for (int i = 0; i < MI; i++)
#pragma unroll
        for (int j = 0; j < NJ; j++)
#pragma unroll
            for (int k = 0; k < 4; k++) acc[i][j][k] = 0.0f;

    int a_r = lane & 15, a_c8 = (lane >> 4) * 8;
    int b_r = lane & 15;

    for (int kc = 0; kc < KDIM / 128; kc++) {
        if (kc) __syncthreads();
#pragma unroll
        for (int it = 0; it < 8; it++) {
            int idx = it * 256 + tid;
            int row = idx >> 4, u4 = idx & 15;
            int rg = m0 + row;
            uint4 v = make_uint4(0u, 0u, 0u, 0u);
            if (rg < nrows)
                v = *(const uint4*)(A + (size_t)rg * KDIM + kc * 128 + u4 * 8);
            *(uint4*)(smem + AH + (row * LDA + u4 * 8) * 2) = v;
        }
#pragma unroll
        for (int it = 0; it < (128 * NU4) / 256; it++) {
            int idx = it * 256 + tid;
            int k = idx / NU4, u4 = idx % NU4;
            size_t goff = (size_t)(kc * 128 + k) * BN + u4 * 8;
            int soff = (k * LDB + u4 * 8) * 2;
            *(uint4*)(smem + BH + soff) = *(const uint4*)(Wh + goff);
            *(uint4*)(smem + BL + soff) = *(const uint4*)(Wl + goff);
        }
        __syncthreads();

#pragma unroll
        for (int p = 0; p < 2; p++) {
            uint32_t bB = sb + (p ? BL : BH);
#pragma unroll
            for (int ks = 0; ks < 8; ks++) {
                uint32_t af[MI][4], bf_[NJ][2];
#pragma unroll
                for (int mi = 0; mi < MI; mi++) {
                    uint32_t ad = sb + AH +
                        ((warp_m * WROWS + mi * 16 + a_r) * LDA + ks * 16 + a_c8) * 2;
                    LDSM_X4(af[mi], ad);
                }
#pragma unroll
                for (int nj = 0; nj < NJ; nj++) {
                    uint32_t bd = bB +
                        ((ks * 16 + b_r) * LDB + warp_n * 32 + nj * 8) * 2;
                    LDSM_X2T(bf_[nj], bd);
                }
#pragma unroll
                for (int mi = 0; mi < MI; mi++)
#pragma unroll
                    for (int nj = 0; nj < NJ; nj++)
                        MMA_F16(acc[mi][nj], af[mi], bf_[nj]);
            }
        }
    }

    int g = lane >> 2, q2 = (lane & 3) * 2;

    if (EPI == 2) {
#pragma unroll
        for (int mi = 0; mi < MI; mi++) {
#pragma unroll
            for (int nj = 0; nj < NJ; nj++) {
                int n = warp_n * 32 + nj * 8 + q2;
                int r0 = m0 + warp_m * WROWS + mi * 16 + g;
                if (r0 < nrows) {
                    float s = dis[r0];
                    __half2 h = __floats2half2_rn(acc[mi][nj][0] * s, acc[mi][nj][1] * s);
                    *(uint32_t*)(C + (size_t)r0 * BN + n) = *(uint32_t*)&h;
                }
                int r1 = r0 + 8;
                if (r1 < nrows) {
                    float s = dis[r1];
                    __half2 h = __floats2half2_rn(acc[mi][nj][2] * s, acc[mi][nj][3] * s);
                    *(uint32_t*)(C + (size_t)r1 * BN + n) = *(uint32_t*)&h;
                }
            }
        }
        return;
    }

    // LN epilogue via padded f32 smem buffer (reuses staging region)
    __syncthreads();
    float* Cs = (float*)smem;   // [128][129]
#pragma unroll
    for (int mi = 0; mi < MI; mi++)
#pragma unroll
        for (int nj = 0; nj < NJ; nj++) {
            int rl = warp_m * WROWS + mi * 16 + g;
            int n = warp_n * 32 + nj * 8 + q2;
            Cs[rl * 129 + n]           = acc[mi][nj][0];
            Cs[rl * 129 + n + 1]       = acc[mi][nj][1];
            Cs[(rl + 8) * 129 + n]     = acc[mi][nj][2];
            Cs[(rl + 8) * 129 + n + 1] = acc[mi][nj][3];
        }
    __syncthreads();

    int row = tid >> 1, half = tid & 1;
    float v[64];
    float s1 = 0.0f, s2 = 0.0f;
#pragma unroll
    for (int j = 0; j < 64; j++) {
        float t = fmaxf(Cs[row * 129 + half * 64 + j] + sh_bias[half * 64 + j], 0.0f);
        v[j] = t; s1 += t; s2 += t * t;
    }
    s1 += __shfl_xor_sync(0xffffffffu, s1, 1);
    s2 += __shfl_xor_sync(0xffffffffu, s2, 1);
    float mu = s1 * (1.0f / 128.0f);
    float var = s2 * (1.0f / 128.0f) - mu * mu;
    float inv = rsqrtf(var + 1e-5f);

    int rg = m0 + row;
    if (rg >= nrows) return;

    float sc = (EPI == 3) ? dis[rg] : 1.0f;
    __half* outp = C + (size_t)rg * ldo + coloff + half * 64;
#pragma unroll
    for (int j = 0; j < 64; j += 8) {
        float o[8];
#pragma unroll
        for (int q = 0; q < 8; q++)
            o[q] = ((v[j + q] - mu) * inv * sh_g[half * 64 + j + q]
                    + sh_b[half * 64 + j + q]) * sc;
        __half2 h0 = __floats2half2_rn(o[0], o[1]);
        __half2 h1 = __floats2half2_rn(o[2], o[3]);
        __half2 h2 = __floats2half2_rn(o[4], o[5]);
        __half2 h3 = __floats2half2_rn(o[6], o[7]);
        uint4 u;
        u.x = *(uint32_t*)&h0; u.y = *(uint32_t*)&h1;
        u.z = *(uint32_t*)&h2; u.w = *(uint32_t*)&h3;
        *(uint4*)(outp + j) = u;
    }
}

#define SMEMH_128 (34816 * 3)                       // 104448
#define SMEMH_64  (34816 + 2 * (128 * 72 * 2))      // 71680

// ---------------------------------------------------------------------------
// aggregation (warp per node)
// ---------------------------------------------------------------------------
// fp16 in (128-wide), fp16 out
__global__ void __launch_bounds__(256)
agg128hh_kernel(const __half* __restrict__ p, const float* __restrict__ dis,
                const int* __restrict__ rowptr, const int* __restrict__ deg,
                const int* __restrict__ col, __half* __restrict__ out, int n) {
    int w = (blockIdx.x * blockDim.x + threadIdx.x) >> 5;
    if (w >= n) return;
    int lane = threadIdx.x & 31;
    const uint2* p2 = (const uint2*)p;
    int start = rowptr[w], d = deg[w];
    uint2 a = p2[(size_t)w * 32 + lane];
    float2 f0 = __half22float2(*(__half2*)&a.x);
    float2 f1 = __half22float2(*(__half2*)&a.y);
    float ax = f0.x, ay = f0.y, az = f1.x, aw = f1.y;

    int c0 = 0;
    for (; c0 + 32 <= d; c0 += 32) {
        int idx = col[start + c0 + lane];
#pragma unroll 8
        for (int j = 0; j < 32; j++) {
            int u = __shfl_sync(0xffffffffu, idx, j);
            uint2 v = p2[(size_t)u * 32 + lane];
            float2 g0 = __half22float2(*(__half2*)&v.x);
            float2 g1 = __half22float2(*(__half2*)&v.y);
            ax += g0.x; ay += g0.y; az += g1.x; aw += g1.y;
        }
    }
    int m = d - c0;
    if (m > 0) {
        int idx = (lane < m) ? col[start + c0 + lane] : 0;
        for (int j = 0; j < m; j++) {
            int u = __shfl_sync(0xffffffffu, idx, j);
            uint2 v = p2[(size_t)u * 32 + lane];
            float2 g0 = __half22float2(*(__half2*)&v.x);
            float2 g1 = __half22float2(*(__half2*)&v.y);
            ax += g0.x; ay += g0.y; az += g1.x; aw += g1.y;
        }
    }
    float s = dis[w];
    __half2 h0 = __floats2half2_rn(ax * s, ay * s);
    __half2 h1 = __floats2half2_rn(az * s, aw * s);
    uint2 o;
    o.x = *(uint32_t*)&h0; o.y = *(uint32_t*)&h1;
    ((uint2*)out)[(size_t)w * 32 + lane] = o;
}

// fp16 payload, 64-wide rows: final output fp32 + cbias
__global__ void __launch_bounds__(256)
agg64h_kernel(const uint32_t* __restrict__ p, const float* __restrict__ dis,
              const int* __restrict__ rowptr, const int* __restrict__ deg,
              const int* __restrict__ col, const float* __restrict__ cbias,
              float2* __restrict__ out, int n) {
    int w = (blockIdx.x * blockDim.x + threadIdx.x) >> 5;
    if (w >= n) return;
    int lane = threadIdx.x & 31;
    int start = rowptr[w], d = deg[w];
    uint32_t a = p[(size_t)w * 32 + lane];
    float2 f = __half22float2(*(__half2*)&a);
    float ax = f.x, ay = f.y;

    int c0 = 0;
    for (; c0 + 32 <= d; c0 += 32) {
        int idx = col[start + c0 + lane];
#pragma unroll 8
        for (int j = 0; j < 32; j++) {
            int u = __shfl_sync(0xffffffffu, idx, j);
            uint32_t v = p[(size_t)u * 32 + lane];
            float2 g = __half22float2(*(__half2*)&v);
            ax += g.x; ay += g.y;
        }
    }
    int m = d - c0;
    if (m > 0) {
        int idx = (lane < m) ? col[start + c0 + lane] : 0;
        for (int j = 0; j < m; j++) {
            int u = __shfl_sync(0xffffffffu, idx, j);
            uint32_t v = p[(size_t)u * 32 + lane];
            float2 g = __half22float2(*(__half2*)&v);
            ax += g.x; ay += g.y;
        }
    }
    float s = dis[w];
    float2 o = {ax * s + cbias[lane * 2], ay * s + cbias[lane * 2 + 1]};
    out[(size_t)w * 32 + lane] = o;
}

// ---------------------------------------------------------------------------
extern "C" void kernel_launch(void* const* d_in, const int* in_sizes, int n_in,
                              void* d_out, int out_size) {
    const float* x     = (const float*)d_in[0];
    const int*   ei    = (const int*)d_in[1];
    const float* W0    = (const float*)d_in[2];
    const float* b0    = (const float*)d_in[3];
    const float* W1    = (const float*)d_in[4];
    const float* b1    = (const float*)d_in[5];
    const float* W2    = (const float*)d_in[6];
    const float* b2    = (const float*)d_in[7];
    const float* gamma = (const float*)d_in[8];
    const float* beta  = (const float*)d_in[9];
    const float* Wf    = (const float*)d_in[10];
    const float* bf    = (const float*)d_in[11];
    float* out = (float*)d_out;

    const int N = in_sizes[0] / 128;
    const int E = in_sizes[1] / 2;
    const int* src = ei;
    const int* dst = ei + E;

    __half *pxh, *yh, *ph, *th, *hcath, *pzh;
    __half *w0h, *w0l, *w1h, *w1l, *wch, *wcl;
    float *wc, *cbias, *dis;
    int *deg, *rp, *cur, *col, *bsum;
    cudaGetSymbolAddress((void**)&pxh,   g_pxh);
    cudaGetSymbolAddress((void**)&yh,    g_yh);
    cudaGetSymbolAddress((void**)&ph,    g_ph);
    cudaGetSymbolAddress((void**)&th,    g_th);
    cudaGetSymbolAddress((void**)&hcath, g_hcath);
    cudaGetSymbolAddress((void**)&pzh,   g_pzh);
    cudaGetSymbolAddress((void**)&wc,    g_wc);
    cudaGetSymbolAddress((void**)&w0h,   g_w0h);
    cudaGetSymbolAddress((void**)&w0l,   g_w0l);
    cudaGetSymbolAddress((void**)&w1h,   g_w1h);
    cudaGetSymbolAddress((void**)&w1l,   g_w1l);
    cudaGetSymbolAddress((void**)&wch,   g_wch);
    cudaGetSymbolAddress((void**)&wcl,   g_wcl);
    cudaGetSymbolAddress((void**)&cbias, g_cbias);
    cudaGetSymbolAddress((void**)&dis,   g_dis);
    cudaGetSymbolAddress((void**)&deg,   g_deg);
    cudaGetSymbolAddress((void**)&rp,    g_rowptr);
    cudaGetSymbolAddress((void**)&cur,   g_cursor);
    cudaGetSymbolAddress((void**)&col,   g_col);
    cudaGetSymbolAddress((void**)&bsum,  g_bsum);

    static bool inited = false;
    static cudaStream_t st1, st2;
    static cudaEvent_t evRoot, evDis, evPre, evW, evY, ev1, ev2;
    if (!inited) {
        cudaStreamCreateWithFlags(&st1, cudaStreamNonBlocking);
        cudaStreamCreateWithFlags(&st2, cudaStreamNonBlocking);
        cudaEventCreateWithFlags(&evRoot, cudaEventDisableTiming);
        cudaEventCreateWithFlags(&evDis, cudaEventDisableTiming);
        cudaEventCreateWithFlags(&evPre, cudaEventDisableTiming);
        cudaEventCreateWithFlags(&evW,  cudaEventDisableTiming);
        cudaEventCreateWithFlags(&evY,  cudaEventDisableTiming);
        cudaEventCreateWithFlags(&ev1,  cudaEventDisableTiming);
        cudaEventCreateWithFlags(&ev2,  cudaEventDisableTiming);
        cudaFuncSetAttribute(tgemm_h_kernel<128, 128, 3>,
                             cudaFuncAttributeMaxDynamicSharedMemorySize, SMEMH_128);
        cudaFuncSetAttribute(tgemm_h_kernel<128, 128, 1>,
                             cudaFuncAttributeMaxDynamicSharedMemorySize, SMEMH_128);
        cudaFuncSetAttribute(tgemm_h_kernel<384, 64, 2>,
                             cudaFuncAttributeMaxDynamicSharedMemorySize, SMEMH_64);
        inited = true;
    }

    const int TB = 256;
    int nB = (N + TB - 1) / TB;
    int eB = (E + TB - 1) / TB;
    int nbScan = (N + SCAN_B - 1) / SCAN_B;
    int aggB = (N * 32 + TB - 1) / TB;
    int gB = (N + 127) / 128;

    cudaStream_t s0 = 0;

    // --- capture fork for st1 (weights) ---
    zero_kernel<<<nB, TB, 0, s0>>>(deg, cur, N);
    cudaEventRecord(evRoot, s0);
    cudaStreamWaitEvent(st1, evRoot, 0);

    // --- weight folding + fp16 hi/lo conversion on st1 ---
    wc_kernel<<<384, 64, 0, st1>>>(W2, Wf, wc);
    cbias_kernel<<<1, 64, 0, st1>>>(b2, Wf, bf, cbias);
    convh_kernel<<<(3 * 128 * 128 + 255) / 256, 256, 0, st1>>>(W0, w0h, w0l, 3 * 128 * 128);
    convh_kernel<<<(3 * 128 * 128 + 255) / 256, 256, 0, st1>>>(W1, w1h, w1l, 3 * 128 * 128);
    convh_kernel<<<(384 * 64 + 255) / 256, 256, 0, st1>>>(wc, wch, wcl, 384 * 64);
    cudaEventRecord(evW, st1);

    // --- graph prep on s0 ---
    count_kernel<<<eB, TB, 0, s0>>>(dst, deg, E);
    dis_kernel<<<nB, TB, 0, s0>>>(deg, dis, N);
    cudaEventRecord(evDis, s0);

    // prescale on st2 (fork via evDis), concurrent with scan/fill
    cudaStreamWaitEvent(st2, evDis, 0);
    prescale_h_kernel<<<(N * 32 + TB - 1) / TB, TB, 0, st2>>>(
        (const float4*)x, dis, (uint2*)pxh, N * 32);
    cudaEventRecord(evPre, st2);

    scan1_kernel<<<nbScan, SCAN_B, 0, s0>>>(deg, rp, bsum, N);
    scan2_kernel<<<1, 32, 0, s0>>>(bsum, nbScan);
    scan3_kernel<<<nB, TB, 0, s0>>>(rp, bsum, N);
    fill_kernel<<<eB, TB, 0, s0>>>(src, dst, rp, cur, col, E);

    // --- shared layer-0 aggregation: yh = A_hat x (fp16 in/out) ---
    cudaStreamWaitEvent(s0, evPre, 0);
    agg128hh_kernel<<<aggB, TB, 0, s0>>>(pxh, dis, rp, deg, col, yh, N);
    cudaEventRecord(evY, s0);

    // --- per-scale independent chains on 3 streams:
    //     GEMM0_s -> agg128_s -> GEMM1_s   (GEMMs hide under other chains' aggs)
    cudaStreamWaitEvent(s0, evW, 0);
    cudaStreamWaitEvent(st1, evY, 0);
    cudaStreamWaitEvent(st2, evY, 0);
    cudaStreamWaitEvent(st2, evW, 0);
    cudaStream_t chain[3] = {s0, st1, st2};
    for (int s = 0; s < 3; s++) {
        cudaStream_t cs = chain[s];
        __half* ph_s = ph + (size_t)s * NN * 128;
        __half* t_s  = th + (size_t)s * NN * 128;
        tgemm_h_kernel<128, 128, 3><<<gB, 256, SMEMH_128, cs>>>(
            yh, w0h + s * 16384, w0l + s * 16384, dis, b0 + s * 128,
            gamma + (s * 3 + 0) * 128, beta + (s * 3 + 0) * 128,
            ph_s, 128, 0, N);
        agg128hh_kernel<<<aggB, TB, 0, cs>>>(ph_s, dis, rp, deg, col, t_s, N);
        tgemm_h_kernel<128, 128, 1><<<gB, 256, SMEMH_128, cs>>>(
            t_s, w1h + s * 16384, w1l + s * 16384, dis, b1 + s * 128,
            gamma + (s * 3 + 1) * 128, beta + (s * 3 + 1) * 128,
            hcath, 384, s * 128, N);
    }
    cudaEventRecord(ev1, st1);
    cudaEventRecord(ev2, st2);
    cudaStreamWaitEvent(s0, ev1, 0);
    cudaStreamWaitEvent(s0, ev2, 0);

    // --- folded tail: pzh = dis * (hcath @ Wc); out = agg + cbias ---
    tgemm_h_kernel<384, 64, 2><<<gB, 256, SMEMH_64, s0>>>(
        hcath, wch, wcl, dis, nullptr, nullptr, nullptr, pzh, 64, 0, N);
    agg64h_kernel<<<aggB, TB, 0, s0>>>((const uint32_t*)pzh, dis, rp, deg, col,
                                       cbias, (float2*)out, N);
}

// round 12
// speedup vs baseline: 1.5010x; 1.0601x over previous
#include <cuda_runtime.h>
#include <cuda_fp16.h>
#include <cstdint>

#define NN 100000
#define EE 3200000
#define SCAN_B 512
#define NBLK_SCAN ((NN + SCAN_B - 1) / SCAN_B)

// -------- device scratch (no cudaMalloc allowed) --------
__device__ __half g_pxh[NN * 128];       // fp16 dis-prescaled x
__device__ __half g_yh[NN * 128];        // y = A_hat x (fp16)
__device__ __half g_ph[3][NN * 128];     // per-scale dis*LN(relu(...)) fp16
__device__ __half g_th[3][NN * 128];     // per-scale t_s (fp16)
__device__ __half g_hcath[NN * 384];     // fp16 concat
__device__ __half g_pzh[NN * 64];        // fp16 tail
__device__ float  g_wc[384 * 64];
__device__ __half g_w0h[3 * 128 * 128];
__device__ __half g_w1h[3 * 128 * 128];
__device__ __half g_wch[384 * 64], g_wcl[384 * 64];
__device__ float  g_cbias[64];
__device__ float  g_dis[NN];
__device__ int    g_deg[NN];
__device__ int    g_rowptr[NN];
__device__ int    g_cursor[NN];
__device__ int    g_col[EE];
__device__ int    g_bsum[NBLK_SCAN + 1];

// ---------------------------------------------------------------------------
// graph prep
// ---------------------------------------------------------------------------
__global__ void zero_kernel(int* deg, int* cur, int n) {
    int i = blockIdx.x * blockDim.x + threadIdx.x;
    if (i < n) { deg[i] = 0; cur[i] = 0; }
}

__global__ void count_kernel(const int* __restrict__ dst, int* __restrict__ deg, int e) {
    int i = blockIdx.x * blockDim.x + threadIdx.x;
    if (i < e) atomicAdd(&deg[dst[i]], 1);
}

// exclusive scan phase 1 + fused dis = rsqrt(deg+1)
__global__ void scan1_kernel(const int* __restrict__ deg, int* __restrict__ out,
                             int* __restrict__ bsum, float* __restrict__ dis, int n) {
    __shared__ int sh[SCAN_B];
    int tid = threadIdx.x;
    int i = blockIdx.x * SCAN_B + tid;
    int v = (i < n) ? deg[i] : 0;
    if (i < n) dis[i] = rsqrtf((float)v + 1.0f);
    sh[tid] = v;
    __syncthreads();
#pragma unroll
    for (int off = 1; off < SCAN_B; off <<= 1) {
        int t = (tid >= off) ? sh[tid - off] : 0;
        __syncthreads();
        sh[tid] += t;
        __syncthreads();
    }
    if (i < n) out[i] = sh[tid] - v;
    if (tid == SCAN_B - 1) bsum[blockIdx.x] = sh[tid];
}

__global__ void scan2_kernel(int* bsum, int nb) {
    if (threadIdx.x == 0 && blockIdx.x == 0) {
        int acc = 0;
        for (int i = 0; i < nb; i++) { int t = bsum[i]; bsum[i] = acc; acc += t; }
    }
}

__global__ void scan3_kernel(int* __restrict__ out, const int* __restrict__ bsum, int n) {
    int i = blockIdx.x * blockDim.x + threadIdx.x;
    if (i < n) out[i] += bsum[i / SCAN_B];
}

__global__ void fill_kernel(const int* __restrict__ src, const int* __restrict__ dst,
                            const int* __restrict__ rowptr, int* __restrict__ cur,
                            int* __restrict__ col, int e) {
    int i = blockIdx.x * blockDim.x + threadIdx.x;
    if (i < e) {
        int d = dst[i];
        int pos = rowptr[d] + atomicAdd(&cur[d], 1);
        col[pos] = src[i];
    }
}

// ---------------------------------------------------------------------------
// weight folding / conversion / prescale
// ---------------------------------------------------------------------------
__global__ void wc_kernel(const float* __restrict__ W2, const float* __restrict__ Wf,
                          float* __restrict__ Wc) {
    int r = blockIdx.x;
    int s = r >> 7, i = r & 127;
    int j = threadIdx.x;
    float acc = 0.0f;
#pragma unroll 8
    for (int k = 0; k < 64; k++)
        acc = fmaf(W2[(s * 128 + i) * 64 + k], Wf[(s * 64 + k) * 64 + j], acc);
    Wc[r * 64 + j] = acc;
}

__global__ void cbias_kernel(const float* __restrict__ b2, const float* __restrict__ Wf,
                             const float* __restrict__ bf, float* __restrict__ cb) {
    int j = threadIdx.x;
    float acc = bf[j];
#pragma unroll 8
    for (int r = 0; r < 192; r++) acc = fmaf(b2[r], Wf[r * 64 + j], acc);
    cb[j] = acc;
}

// fp32 -> fp16 (hi only)
__global__ void convs_kernel(const float* __restrict__ W, __half* __restrict__ Wh, int n) {
    int i = blockIdx.x * blockDim.x + threadIdx.x;
    if (i < n) Wh[i] = __float2half_rn(W[i]);
}

// fp32 -> fp16 hi + lo residual (tail weights)
__global__ void convh_kernel(const float* __restrict__ W, __half* __restrict__ Wh,
                             __half* __restrict__ Wl, int n) {
    int i = blockIdx.x * blockDim.x + threadIdx.x;
    if (i < n) {
        float w = W[i];
        __half h = __float2half_rn(w);
        Wh[i] = h;
        Wl[i] = __float2half_rn(w - __half2float(h));
    }
}

__global__ void prescale_h_kernel(const float4* __restrict__ x, const float* __restrict__ dis,
                                  uint2* __restrict__ px, int n4) {
    int i = blockIdx.x * blockDim.x + threadIdx.x;
    if (i < n4) {
        float s = dis[i >> 5];
        float4 v = x[i];
        __half2 h0 = __floats2half2_rn(v.x * s, v.y * s);
        __half2 h1 = __floats2half2_rn(v.z * s, v.w * s);
        uint2 u;
        u.x = *(uint32_t*)&h0; u.y = *(uint32_t*)&h1;
        px[i] = u;
    }
}

// ---------------------------------------------------------------------------
// fp16 tensor-core GEMM. LO=true adds a W-residual pass (tail only).
// EPI 1: LN(relu(acc+bias))            -> fp16 C (ldo/coloff)
// EPI 2: acc * dis[row]                -> fp16 C (row stride BN)
// EPI 3: LN(relu(acc+bias)) * dis[row] -> fp16 C (ldo/coloff)
// rows: [rbase + bid*128, ...), bounded by nrows
// ---------------------------------------------------------------------------
__device__ __forceinline__ uint32_t smem_u32(const void* p) {
    uint32_t a;
    asm("{ .reg .u64 t; cvta.to.shared.u64 t, %1; cvt.u32.u64 %0, t; }"
        : "=r"(a) : "l"(p));
    return a;
}

#define LDSM_X4(r, addr)                                                      \
    asm volatile("ldmatrix.sync.aligned.m8n8.x4.shared.b16 {%0,%1,%2,%3}, [%4];" \
                 : "=r"((r)[0]), "=r"((r)[1]), "=r"((r)[2]), "=r"((r)[3])     \
                 : "r"(addr))

#define LDSM_X2T(r, addr)                                                     \
    asm volatile("ldmatrix.sync.aligned.m8n8.x2.trans.shared.b16 {%0,%1}, [%2];" \
                 : "=r"((r)[0]), "=r"((r)[1]) : "r"(addr))

#define MMA_F16(d, a, b)                                                      \
    asm volatile("mma.sync.aligned.m16n8k16.row.col.f32.f16.f16.f32 "         \
                 "{%0,%1,%2,%3}, {%4,%5,%6,%7}, {%8,%9}, {%0,%1,%2,%3};"      \
                 : "+f"((d)[0]), "+f"((d)[1]), "+f"((d)[2]), "+f"((d)[3])     \
                 : "r"((a)[0]), "r"((a)[1]), "r"((a)[2]), "r"((a)[3]),        \
                   "r"((b)[0]), "r"((b)[1]))

template <int KDIM, int BN, int EPI, bool LO>
__global__ void __launch_bounds__(256)
tgemm_h_kernel(const __half* __restrict__ A, const __half* __restrict__ Wh,
               const __half* __restrict__ Wl,
               const float* __restrict__ dis, const float* __restrict__ bias,
               const float* __restrict__ gamma, const float* __restrict__ beta,
               __half* __restrict__ C, int ldo, int coloff, int rbase, int nrows) {
    constexpr int LDA = 136;
    constexpr int LDB = BN + 8;
    constexpr int WN = BN / 32;
    constexpr int WM = 8 / WN;
    constexpr int WROWS = 128 / WM;
    constexpr int MI = WROWS / 16;
    constexpr int NJ = 4;
    constexpr int ABYTES = 128 * LDA * 2;
    constexpr int BBYTES = 128 * LDB * 2;
    constexpr int AH = 0, BH = ABYTES, BL = BH + BBYTES;   // BL used iff LO
    constexpr int NU4 = BN / 8;
    constexpr int NPASS = LO ? 2 : 1;

    extern __shared__ char smem[];
    __shared__ float sh_bias[128], sh_g[128], sh_b[128];

    int tid = threadIdx.x, wid = tid >> 5, lane = tid & 31;
    int warp_m = wid % WM, warp_n = wid / WM;
    int m0 = rbase + blockIdx.x * 128;
    uint32_t sb = smem_u32(smem);

    if (EPI != 2 && tid < 128) {
        sh_bias[tid] = bias[tid];
        sh_g[tid] = gamma[tid];
        sh_b[tid] = beta[tid];
    }

    float acc[MI][NJ][4];
#pragma unroll
    for (int i = 0; i < MI; i++)
#pragma unroll
        for (int j = 0; j < NJ; j++)
#pragma unroll
            for (int k = 0; k < 4; k++) acc[i][j][k] = 0.0f;

    int a_r = lane & 15, a_c8 = (lane >> 4) * 8;
    int b_r = lane & 15;

    for (int kc = 0; kc < KDIM / 128; kc++) {
        if (kc) __syncthreads();
#pragma unroll
        for (int it = 0; it < 8; it++) {
            int idx = it * 256 + tid;
            int row = idx >> 4, u4 = idx & 15;
            int rg = m0 + row;
            uint4 v = make_uint4(0u, 0u, 0u, 0u);
            if (rg < nrows)
                v = *(const uint4*)(A + (size_t)rg * KDIM + kc * 128 + u4 * 8);
            *(uint4*)(smem + AH + (row * LDA + u4 * 8) * 2) = v;
        }
#pragma unroll
        for (int it = 0; it < (128 * NU4) / 256; it++) {
            int idx = it * 256 + tid;
            int k = idx / NU4, u4 = idx % NU4;
            size_t goff = (size_t)(kc * 128 + k) * BN + u4 * 8;
            int soff = (k * LDB + u4 * 8) * 2;
            *(uint4*)(smem + BH + soff) = *(const uint4*)(Wh + goff);
            if (LO)
                *(uint4*)(smem + BL + soff) = *(const uint4*)(Wl + goff);
        }
        __syncthreads();

#pragma unroll
        for (int p = 0; p < NPASS; p++) {
            uint32_t bB = sb + (p ? BL : BH);
#pragma unroll
            for (int ks = 0; ks < 8; ks++) {
                uint32_t af[MI][4], bf_[NJ][2];
#pragma unroll
                for (int mi = 0; mi < MI; mi++) {
                    uint32_t ad = sb + AH +
                        ((warp_m * WROWS + mi * 16 + a_r) * LDA + ks * 16 + a_c8) * 2;
                    LDSM_X4(af[mi], ad);
                }
#pragma unroll
                for (int nj = 0; nj < NJ; nj++) {
                    uint32_t bd = bB +
                        ((ks * 16 + b_r) * LDB + warp_n * 32 + nj * 8) * 2;
                    LDSM_X2T(bf_[nj], bd);
                }
#pragma unroll
                for (int mi = 0; mi < MI; mi++)
#pragma unroll
                    for (int nj = 0; nj < NJ; nj++)
                        MMA_F16(acc[mi][nj], af[mi], bf_[nj]);
            }
        }
    }

    int g = lane >> 2, q2 = (lane & 3) * 2;

    if (EPI == 2) {
#pragma unroll
        for (int mi = 0; mi < MI; mi++) {
#pragma unroll
            for (int nj = 0; nj < NJ; nj++) {
                int n = warp_n * 32 + nj * 8 + q2;
                int r0 = m0 + warp_m * WROWS + mi * 16 + g;
                if (r0 < nrows) {
                    float s = dis[r0];
                    __half2 h = __floats2half2_rn(acc[mi][nj][0] * s, acc[mi][nj][1] * s);
                    *(uint32_t*)(C + (size_t)r0 * BN + n) = *(uint32_t*)&h;
                }
                int r1 = r0 + 8;
                if (r1 < nrows) {
                    float s = dis[r1];
                    __half2 h = __floats2half2_rn(acc[mi][nj][2] * s, acc[mi][nj][3] * s);
                    *(uint32_t*)(C + (size_t)r1 * BN + n) = *(uint32_t*)&h;
                }
            }
        }
        return;
    }

    // LN epilogue via padded f32 smem buffer (reuses staging region)
    __syncthreads();
    float* Cs = (float*)smem;   // [128][129] = 66048 <= 69632
#pragma unroll
    for (int mi = 0; mi < MI; mi++)
#pragma unroll
        for (int nj = 0; nj < NJ; nj++) {
            int rl = warp_m * WROWS + mi * 16 + g;
            int n = warp_n * 32 + nj * 8 + q2;
            Cs[rl * 129 + n]           = acc[mi][nj][0];
            Cs[rl * 129 + n + 1]       = acc[mi][nj][1];
            Cs[(rl + 8) * 129 + n]     = acc[mi][nj][2];
            Cs[(rl + 8) * 129 + n + 1] = acc[mi][nj][3];
        }
    __syncthreads();

    int row = tid >> 1, half = tid & 1;
    float v[64];
    float s1 = 0.0f, s2 = 0.0f;
#pragma unroll
    for (int j = 0; j < 64; j++) {
        float t = fmaxf(Cs[row * 129 + half * 64 + j] + sh_bias[half * 64 + j], 0.0f);
        v[j] = t; s1 += t; s2 += t * t;
    }
    s1 += __shfl_xor_sync(0xffffffffu, s1, 1);
    s2 += __shfl_xor_sync(0xffffffffu, s2, 1);
    float mu = s1 * (1.0f / 128.0f);
    float var = s2 * (1.0f / 128.0f) - mu * mu;
    float inv = rsqrtf(var + 1e-5f);

    int rg = m0 + row;
    if (rg >= nrows) return;

    float sc = (EPI == 3) ? dis[rg] : 1.0f;
    __half* outp = C + (size_t)rg * ldo + coloff + half * 64;
#pragma unroll
    for (int j = 0; j < 64; j += 8) {
        float o[8];
#pragma unroll
        for (int q = 0; q < 8; q++)
            o[q] = ((v[j + q] - mu) * inv * sh_g[half * 64 + j + q]
                    + sh_b[half * 64 + j + q]) * sc;
        __half2 h0 = __floats2half2_rn(o[0], o[1]);
        __half2 h1 = __floats2half2_rn(o[2], o[3]);
        __half2 h2 = __floats2half2_rn(o[4], o[5]);
        __half2 h3 = __floats2half2_rn(o[6], o[7]);
        uint4 u;
        u.x = *(uint32_t*)&h0; u.y = *(uint32_t*)&h1;
        u.z = *(uint32_t*)&h2; u.w = *(uint32_t*)&h3;
        *(uint4*)(outp + j) = u;
    }
}

#define SMEM_1P (34816 * 2)                         // 69632 (A + Wh)
#define SMEM_TAIL (34816 + 2 * (128 * 72 * 2))      // 71680

// ---------------------------------------------------------------------------
// aggregation (warp per node), node range [base, nend)
// ---------------------------------------------------------------------------
__global__ void __launch_bounds__(256)
agg128hh_kernel(const __half* __restrict__ p, const float* __restrict__ dis,
                const int* __restrict__ rowptr, const int* __restrict__ deg,
                const int* __restrict__ col, __half* __restrict__ out,
                int base, int nend) {
    int w = base + ((blockIdx.x * blockDim.x + threadIdx.x) >> 5);
    if (w >= nend) return;
    int lane = threadIdx.x & 31;
    const uint2* p2 = (const uint2*)p;
    int start = rowptr[w], d = deg[w];
    uint2 a = p2[(size_t)w * 32 + lane];
    float2 f0 = __half22float2(*(__half2*)&a.x);
    float2 f1 = __half22float2(*(__half2*)&a.y);
    float ax = f0.x, ay = f0.y, az = f1.x, aw = f1.y;

    int c0 = 0;
    for (; c0 + 32 <= d; c0 += 32) {
        int idx = col[start + c0 + lane];
#pragma unroll 8
        for (int j = 0; j < 32; j++) {
            int u = __shfl_sync(0xffffffffu, idx, j);
            uint2 v = p2[(size_t)u * 32 + lane];
            float2 g0 = __half22float2(*(__half2*)&v.x);
            float2 g1 = __half22float2(*(__half2*)&v.y);
            ax += g0.x; ay += g0.y; az += g1.x; aw += g1.y;
        }
    }
    int m = d - c0;
    if (m > 0) {
        int idx = (lane < m) ? col[start + c0 + lane] : 0;
        for (int j = 0; j < m; j++) {
            int u = __shfl_sync(0xffffffffu, idx, j);
            uint2 v = p2[(size_t)u * 32 + lane];
            float2 g0 = __half22float2(*(__half2*)&v.x);
            float2 g1 = __half22float2(*(__half2*)&v.y);
            ax += g0.x; ay += g0.y; az += g1.x; aw += g1.y;
        }
    }
    float s = dis[w];
    __half2 h0 = __floats2half2_rn(ax * s, ay * s);
    __half2 h1 = __floats2half2_rn(az * s, aw * s);
    uint2 o;
    o.x = *(uint32_t*)&h0; o.y = *(uint32_t*)&h1;
    ((uint2*)out)[(size_t)w * 32 + lane] = o;
}

// fp16 payload, 64-wide rows: final output fp32 + cbias
__global__ void __launch_bounds__(256)
agg64h_kernel(const uint32_t* __restrict__ p, const float* __restrict__ dis,
              const int* __restrict__ rowptr, const int* __restrict__ deg,
              const int* __restrict__ col, const float* __restrict__ cbias,
              float2* __restrict__ out, int n) {
    int w = (blockIdx.x * blockDim.x + threadIdx.x) >> 5;
    if (w >= n) return;
    int lane = threadIdx.x & 31;
    int start = rowptr[w], d = deg[w];
    uint32_t a = p[(size_t)w * 32 + lane];
    float2 f = __half22float2(*(__half2*)&a);
    float ax = f.x, ay = f.y;

    int c0 = 0;
    for (; c0 + 32 <= d; c0 += 32) {
        int idx = col[start + c0 + lane];
#pragma unroll 8
        for (int j = 0; j < 32; j++) {
            int u = __shfl_sync(0xffffffffu, idx, j);
            uint32_t v = p[(size_t)u * 32 + lane];
            float2 g = __half22float2(*(__half2*)&v);
            ax += g.x; ay += g.y;
        }
    }
    int m = d - c0;
    if (m > 0) {
        int idx = (lane < m) ? col[start + c0 + lane] : 0;
        for (int j = 0; j < m; j++) {
            int u = __shfl_sync(0xffffffffu, idx, j);
            uint32_t v = p[(size_t)u * 32 + lane];
            float2 g = __half22float2(*(__half2*)&v);
            ax += g.x; ay += g.y;
        }
    }
    float s = dis[w];
    float2 o = {ax * s + cbias[lane * 2], ay * s + cbias[lane * 2 + 1]};
    out[(size_t)w * 32 + lane] = o;
}

// ---------------------------------------------------------------------------
extern "C" void kernel_launch(void* const* d_in, const int* in_sizes, int n_in,
                              void* d_out, int out_size) {
    const float* x     = (const float*)d_in[0];
    const int*   ei    = (const int*)d_in[1];
    const float* W0    = (const float*)d_in[2];
    const float* b0    = (const float*)d_in[3];
    const float* W1    = (const float*)d_in[4];
    const float* b1    = (const float*)d_in[5];
    const float* W2    = (const float*)d_in[6];
    const float* b2    = (const float*)d_in[7];
    const float* gamma = (const float*)d_in[8];
    const float* beta  = (const float*)d_in[9];
    const float* Wf    = (const float*)d_in[10];
    const float* bf    = (const float*)d_in[11];
    float* out = (float*)d_out;

    const int N = in_sizes[0] / 128;
    const int E = in_sizes[1] / 2;
    const int* src = ei;
    const int* dst = ei + E;

    __half *pxh, *yh, *ph, *th, *hcath, *pzh, *w0h, *w1h, *wch, *wcl;
    float *wc, *cbias, *dis;
    int *deg, *rp, *cur, *col, *bsum;
    cudaGetSymbolAddress((void**)&pxh,   g_pxh);
    cudaGetSymbolAddress((void**)&yh,    g_yh);
    cudaGetSymbolAddress((void**)&ph,    g_ph);
    cudaGetSymbolAddress((void**)&th,    g_th);
    cudaGetSymbolAddress((void**)&hcath, g_hcath);
    cudaGetSymbolAddress((void**)&pzh,   g_pzh);
    cudaGetSymbolAddress((void**)&wc,    g_wc);
    cudaGetSymbolAddress((void**)&w0h,   g_w0h);
    cudaGetSymbolAddress((void**)&w1h,   g_w1h);
    cudaGetSymbolAddress((void**)&wch,   g_wch);
    cudaGetSymbolAddress((void**)&wcl,   g_wcl);
    cudaGetSymbolAddress((void**)&cbias, g_cbias);
    cudaGetSymbolAddress((void**)&dis,   g_dis);
    cudaGetSymbolAddress((void**)&deg,   g_deg);
    cudaGetSymbolAddress((void**)&rp,    g_rowptr);
    cudaGetSymbolAddress((void**)&cur,   g_cursor);
    cudaGetSymbolAddress((void**)&col,   g_col);
    cudaGetSymbolAddress((void**)&bsum,  g_bsum);

    // resource envelope identical to the R9 config that passed the mem guard:
    // 2 created streams + legacy default, 8 events.
    static bool inited = false;
    static cudaStream_t st1, st2;
    static cudaEvent_t evRoot, evDis, evPre, evW, evY0, evY1, ev1, ev2;
    if (!inited) {
        cudaStreamCreateWithFlags(&st1, cudaStreamNonBlocking);
        cudaStreamCreateWithFlags(&st2, cudaStreamNonBlocking);
        cudaEventCreateWithFlags(&evRoot, cudaEventDisableTiming);
        cudaEventCreateWithFlags(&evDis, cudaEventDisableTiming);
        cudaEventCreateWithFlags(&evPre, cudaEventDisableTiming);
        cudaEventCreateWithFlags(&evW,  cudaEventDisableTiming);
        cudaEventCreateWithFlags(&evY0, cudaEventDisableTiming);
        cudaEventCreateWithFlags(&evY1, cudaEventDisableTiming);
        cudaEventCreateWithFlags(&ev1,  cudaEventDisableTiming);
        cudaEventCreateWithFlags(&ev2,  cudaEventDisableTiming);
        cudaFuncSetAttribute(tgemm_h_kernel<128, 128, 3, false>,
                             cudaFuncAttributeMaxDynamicSharedMemorySize, SMEM_1P);
        cudaFuncSetAttribute(tgemm_h_kernel<128, 128, 1, false>,
                             cudaFuncAttributeMaxDynamicSharedMemorySize, SMEM_1P);
        cudaFuncSetAttribute(tgemm_h_kernel<384, 64, 2, true>,
                             cudaFuncAttributeMaxDynamicSharedMemorySize, SMEM_TAIL);
        inited = true;
    }

    const int TB = 256;
    int nB = (N + TB - 1) / TB;
    int eB = (E + TB - 1) / TB;
    int nbScan = (N + SCAN_B - 1) / SCAN_B;
    int aggB = (N * 32 + TB - 1) / TB;
    int gB = (N + 127) / 128;

    const int H = ((N / 2 + 127) / 128) * 128;   // agg_y half split, 128-aligned
    int gB0 = H / 128;
    int gB1 = (N - H + 127) / 128;
    int aB0 = (H * 32 + TB - 1) / TB;
    int aB1 = ((N - H) * 32 + TB - 1) / TB;

    cudaStream_t s0 = 0;

    // --- capture fork for st1 (weights) ---
    zero_kernel<<<nB, TB, 0, s0>>>(deg, cur, N);
    cudaEventRecord(evRoot, s0);
    cudaStreamWaitEvent(st1, evRoot, 0);

    // --- weight folding + fp16 conversion on st1 ---
    wc_kernel<<<384, 64, 0, st1>>>(W2, Wf, wc);
    cbias_kernel<<<1, 64, 0, st1>>>(b2, Wf, bf, cbias);
    convs_kernel<<<(3 * 128 * 128 + 255) / 256, 256, 0, st1>>>(W0, w0h, 3 * 128 * 128);
    convs_kernel<<<(3 * 128 * 128 + 255) / 256, 256, 0, st1>>>(W1, w1h, 3 * 128 * 128);
    convh_kernel<<<(384 * 64 + 255) / 256, 256, 0, st1>>>(wc, wch, wcl, 384 * 64);
    cudaEventRecord(evW, st1);

    // --- graph prep on s0 (dis fused into scan1) ---
    count_kernel<<<eB, TB, 0, s0>>>(dst, deg, E);
    scan1_kernel<<<nbScan, SCAN_B, 0, s0>>>(deg, rp, bsum, dis, N);
    cudaEventRecord(evDis, s0);

    // prescale on st2 (fork via evDis), concurrent with scan2/3/fill
    cudaStreamWaitEvent(st2, evDis, 0);
    prescale_h_kernel<<<(N * 32 + TB - 1) / TB, TB, 0, st2>>>(
        (const float4*)x, dis, (uint2*)pxh, N * 32);
    cudaEventRecord(evPre, st2);

    scan2_kernel<<<1, 32, 0, s0>>>(bsum, nbScan);
    scan3_kernel<<<nB, TB, 0, s0>>>(rp, bsum, N);
    fill_kernel<<<eB, TB, 0, s0>>>(src, dst, rp, cur, col, E);

    // --- agg_y in two halves: st1/st2 chains start GEMM0(H0) under agg_y(H1) ---
    cudaStreamWaitEvent(s0, evPre, 0);
    agg128hh_kernel<<<aB0, TB, 0, s0>>>(pxh, dis, rp, deg, col, yh, 0, H);
    cudaEventRecord(evY0, s0);
    agg128hh_kernel<<<aB1, TB, 0, s0>>>(pxh, dis, rp, deg, col, yh, H, N);
    cudaEventRecord(evY1, s0);

    // --- per-scale chains on {s0, st1, st2} ---
    cudaStreamWaitEvent(s0, evW, 0);
    cudaStreamWaitEvent(st2, evW, 0);
    cudaStream_t chain[3] = {s0, st1, st2};
    for (int s = 0; s < 3; s++) {
        cudaStream_t cs = chain[s];
        __half* ph_s = ph + (size_t)s * NN * 128;
        __half* t_s  = th + (size_t)s * NN * 128;
        if (cs != s0) cudaStreamWaitEvent(cs, evY0, 0);
        tgemm_h_kernel<128, 128, 3, false><<<gB0, 256, SMEM_1P, cs>>>(
            yh, w0h + s * 16384, nullptr, dis, b0 + s * 128,
            gamma + (s * 3 + 0) * 128, beta + (s * 3 + 0) * 128,
            ph_s, 128, 0, 0, N);
        if (cs != s0) cudaStreamWaitEvent(cs, evY1, 0);
        tgemm_h_kernel<128, 128, 3, false><<<gB1, 256, SMEM_1P, cs>>>(
            yh, w0h + s * 16384, nullptr, dis, b0 + s * 128,
            gamma + (s * 3 + 0) * 128, beta + (s * 3 + 0) * 128,
            ph_s, 128, 0, H, N);
        agg128hh_kernel<<<aggB, TB, 0, cs>>>(ph_s, dis, rp, deg, col, t_s, 0, N);
        tgemm_h_kernel<128, 128, 1, false><<<gB, 256, SMEM_1P, cs>>>(
            t_s, w1h + s * 16384, nullptr, dis, b1 + s * 128,
            gamma + (s * 3 + 1) * 128, beta + (s * 3 + 1) * 128,
            hcath, 384, s * 128, 0, N);
    }
    cudaEventRecord(ev1, st1);
    cudaEventRecord(ev2, st2);
    cudaStreamWaitEvent(s0, ev1, 0);
    cudaStreamWaitEvent(s0, ev2, 0);

    // --- folded tail (hi/lo 2-pass) + final aggregation on s0 ---
    tgemm_h_kernel<384, 64, 2, true><<<gB, 256, SMEM_TAIL, s0>>>(
        hcath, wch, wcl, dis, nullptr, nullptr, nullptr, pzh, 64, 0, 0, N);
    agg64h_kernel<<<aggB, TB, 0, s0>>>((const uint32_t*)pzh, dis, rp, deg, col,
                                       cbias, (float2*)out, N);
}

// round 13
// speedup vs baseline: 1.5577x; 1.0378x over previous
#include <cuda_runtime.h>
#include <cuda_fp16.h>
#include <cstdint>

#define NN 100000
#define EE 3200000
#define SCAN_B 512
#define NBLK_SCAN ((NN + SCAN_B - 1) / SCAN_B)

// -------- device scratch (no cudaMalloc allowed) --------
__device__ __half g_pxh[NN * 128];       // fp16 dis-prescaled x
__device__ __half g_yh[NN * 128];        // y = A_hat x (fp16)
__device__ __half g_ph[3][NN * 128];     // per-scale dis*LN(relu(...)) fp16
__device__ __half g_th[3][NN * 128];     // per-scale t_s (fp16)
__device__ float  g_pzp[3][NN * 64];     // per-scale tail partials (fp32)
__device__ __half g_pzh[NN * 64];        // fp16 tail (summed, dis-scaled)
__device__ float  g_wc[384 * 64];
__device__ __half g_w0h[3 * 128 * 128];
__device__ __half g_w1h[3 * 128 * 128];
__device__ __half g_wch[384 * 64], g_wcl[384 * 64];
__device__ float  g_cbias[64];
__device__ float  g_dis[NN];
__device__ int    g_deg[NN];
__device__ int    g_rowptr[NN];
__device__ int    g_cursor[NN];
__device__ int    g_col[EE];
__device__ int    g_bsum[NBLK_SCAN + 1];

// ---------------------------------------------------------------------------
// graph prep
// ---------------------------------------------------------------------------
__global__ void zero_kernel(int* deg, int* cur, int n) {
    int i = blockIdx.x * blockDim.x + threadIdx.x;
    if (i < n) { deg[i] = 0; cur[i] = 0; }
}

__global__ void count_kernel(const int* __restrict__ dst, int* __restrict__ deg, int e) {
    int i = blockIdx.x * blockDim.x + threadIdx.x;
    if (i < e) atomicAdd(&deg[dst[i]], 1);
}

// exclusive scan phase 1 + fused dis = rsqrt(deg+1)
__global__ void scan1_kernel(const int* __restrict__ deg, int* __restrict__ out,
                             int* __restrict__ bsum, float* __restrict__ dis, int n) {
    __shared__ int sh[SCAN_B];
    int tid = threadIdx.x;
    int i = blockIdx.x * SCAN_B + tid;
    int v = (i < n) ? deg[i] : 0;
    if (i < n) dis[i] = rsqrtf((float)v + 1.0f);
    sh[tid] = v;
    __syncthreads();
#pragma unroll
    for (int off = 1; off < SCAN_B; off <<= 1) {
        int t = (tid >= off) ? sh[tid - off] : 0;
        __syncthreads();
        sh[tid] += t;
        __syncthreads();
    }
    if (i < n) out[i] = sh[tid] - v;
    if (tid == SCAN_B - 1) bsum[blockIdx.x] = sh[tid];
}

__global__ void scan2_kernel(int* bsum, int nb) {
    if (threadIdx.x == 0 && blockIdx.x == 0) {
        int acc = 0;
        for (int i = 0; i < nb; i++) { int t = bsum[i]; bsum[i] = acc; acc += t; }
    }
}

__global__ void scan3_kernel(int* __restrict__ out, const int* __restrict__ bsum, int n) {
    int i = blockIdx.x * blockDim.x + threadIdx.x;
    if (i < n) out[i] += bsum[i / SCAN_B];
}

__global__ void fill_kernel(const int* __restrict__ src, const int* __restrict__ dst,
                            const int* __restrict__ rowptr, int* __restrict__ cur,
                            int* __restrict__ col, int e) {
    int i = blockIdx.x * blockDim.x + threadIdx.x;
    if (i < e) {
        int d = dst[i];
        int pos = rowptr[d] + atomicAdd(&cur[d], 1);
        col[pos] = src[i];
    }
}

// ---------------------------------------------------------------------------
// weight folding / conversion / prescale
// ---------------------------------------------------------------------------
__global__ void wc_kernel(const float* __restrict__ W2, const float* __restrict__ Wf,
                          float* __restrict__ Wc) {
    int r = blockIdx.x;
    int s = r >> 7, i = r & 127;
    int j = threadIdx.x;
    float acc = 0.0f;
#pragma unroll 8
    for (int k = 0; k < 64; k++)
        acc = fmaf(W2[(s * 128 + i) * 64 + k], Wf[(s * 64 + k) * 64 + j], acc);
    Wc[r * 64 + j] = acc;
}

__global__ void cbias_kernel(const float* __restrict__ b2, const float* __restrict__ Wf,
                             const float* __restrict__ bf, float* __restrict__ cb) {
    int j = threadIdx.x;
    float acc = bf[j];
#pragma unroll 8
    for (int r = 0; r < 192; r++) acc = fmaf(b2[r], Wf[r * 64 + j], acc);
    cb[j] = acc;
}

__global__ void convs_kernel(const float* __restrict__ W, __half* __restrict__ Wh, int n) {
    int i = blockIdx.x * blockDim.x + threadIdx.x;
    if (i < n) Wh[i] = __float2half_rn(W[i]);
}

__global__ void convh_kernel(const float* __restrict__ W, __half* __restrict__ Wh,
                             __half* __restrict__ Wl, int n) {
    int i = blockIdx.x * blockDim.x + threadIdx.x;
    if (i < n) {
        float w = W[i];
        __half h = __float2half_rn(w);
        Wh[i] = h;
        Wl[i] = __float2half_rn(w - __half2float(h));
    }
}

__global__ void prescale_h_kernel(const float4* __restrict__ x, const float* __restrict__ dis,
                                  uint2* __restrict__ px, int n4) {
    int i = blockIdx.x * blockDim.x + threadIdx.x;
    if (i < n4) {
        float s = dis[i >> 5];
        float4 v = x[i];
        __half2 h0 = __floats2half2_rn(v.x * s, v.y * s);
        __half2 h1 = __floats2half2_rn(v.z * s, v.w * s);
        uint2 u;
        u.x = *(uint32_t*)&h0; u.y = *(uint32_t*)&h1;
        px[i] = u;
    }
}

// pzh = fp16( dis[r] * (p0 + p1 + p2) ), 2 elems per thread
__global__ void pzsum_kernel(const float* __restrict__ p0, const float* __restrict__ p1,
                             const float* __restrict__ p2, const float* __restrict__ dis,
                             uint32_t* __restrict__ pzh, int n2) {
    int i = blockIdx.x * blockDim.x + threadIdx.x;   // over n*32 (pairs)
    if (i < n2) {
        float s = dis[i >> 5];
        float2 a = ((const float2*)p0)[i];
        float2 b = ((const float2*)p1)[i];
        float2 c = ((const float2*)p2)[i];
        __half2 h = __floats2half2_rn((a.x + b.x + c.x) * s, (a.y + b.y + c.y) * s);
        pzh[i] = *(uint32_t*)&h;
    }
}

// ---------------------------------------------------------------------------
// PTX helpers
// ---------------------------------------------------------------------------
__device__ __forceinline__ uint32_t smem_u32(const void* p) {
    uint32_t a;
    asm("{ .reg .u64 t; cvta.to.shared.u64 t, %1; cvt.u32.u64 %0, t; }"
        : "=r"(a) : "l"(p));
    return a;
}

#define LDSM_X4(r, addr)                                                      \
    asm volatile("ldmatrix.sync.aligned.m8n8.x4.shared.b16 {%0,%1,%2,%3}, [%4];" \
                 : "=r"((r)[0]), "=r"((r)[1]), "=r"((r)[2]), "=r"((r)[3])     \
                 : "r"(addr))

#define LDSM_X2T(r, addr)                                                     \
    asm volatile("ldmatrix.sync.aligned.m8n8.x2.trans.shared.b16 {%0,%1}, [%2];" \
                 : "=r"((r)[0]), "=r"((r)[1]) : "r"(addr))

#define MMA_F16(d, a, b)                                                      \
    asm volatile("mma.sync.aligned.m16n8k16.row.col.f32.f16.f16.f32 "         \
                 "{%0,%1,%2,%3}, {%4,%5,%6,%7}, {%8,%9}, {%0,%1,%2,%3};"      \
                 : "+f"((d)[0]), "+f"((d)[1]), "+f"((d)[2]), "+f"((d)[3])     \
                 : "r"((a)[0]), "r"((a)[1]), "r"((a)[2]), "r"((a)[3]),        \
                   "r"((b)[0]), "r"((b)[1]))

// ---------------------------------------------------------------------------
// GEMM0: C = dis * LN(relu(A @ Wh + bias)) -> fp16, single-pass fp16 weights
// rows: [rbase + bid*128, ...), bounded by nrows
// ---------------------------------------------------------------------------
__global__ void __launch_bounds__(256)
gemm0_kernel(const __half* __restrict__ A, const __half* __restrict__ Wh,
             const float* __restrict__ dis, const float* __restrict__ bias,
             const float* __restrict__ gamma, const float* __restrict__ beta,
             __half* __restrict__ C, int rbase, int nrows) {
    constexpr int LDA = 136;
    constexpr int ABYTES = 128 * LDA * 2;   // 34816
    extern __shared__ char smem[];
    __shared__ float sh_bias[128], sh_g[128], sh_b[128];

    int tid = threadIdx.x, wid = tid >> 5, lane = tid & 31;
    int warp_m = wid & 1, warp_n = wid >> 1;   // 2x4 warps: 64 rows x 32 cols
    int m0 = rbase + blockIdx.x * 128;
    uint32_t sb = smem_u32(smem);

    if (tid < 128) {
        sh_bias[tid] = bias[tid];
        sh_g[tid] = gamma[tid];
        sh_b[tid] = beta[tid];
    }

    float acc[2][4][4];
#pragma unroll
    for (int i = 0; i < 2; i++)
#pragma unroll
        for (int j = 0; j < 4; j++)
#pragma unroll
            for (int k = 0; k < 4; k++) acc[i][j][k] = 0.0f;

    int a_r = lane & 15, a_c8 = (lane >> 4) * 8, b_r = lane & 15;

    // stage A + W
#pragma unroll
    for (int it = 0; it < 8; it++) {
        int idx = it * 256 + tid;
        int row = idx >> 4, u4 = idx & 15;
        int rg = m0 + row;
        uint4 v = make_uint4(0u, 0u, 0u, 0u);
        if (rg < nrows) v = *(const uint4*)(A + (size_t)rg * 128 + u4 * 8);
        *(uint4*)(smem + (row * LDA + u4 * 8) * 2) = v;
        *(uint4*)(smem + ABYTES + (row * LDA + u4 * 8) * 2) =
            *(const uint4*)(Wh + row * 128 + u4 * 8);
    }
    __syncthreads();

#pragma unroll
    for (int ks = 0; ks < 8; ks++) {
        uint32_t af[2][4], bf_[4][2];
#pragma unroll
        for (int mi = 0; mi < 2; mi++)
            LDSM_X4(af[mi], sb + ((warp_m * 64 + mi * 16 + a_r) * LDA
                                  + ks * 16 + a_c8) * 2);
#pragma unroll
        for (int nj = 0; nj < 4; nj++)
            LDSM_X2T(bf_[nj], sb + ABYTES + ((ks * 16 + b_r) * LDA
                                             + warp_n * 32 + nj * 8) * 2);
#pragma unroll
        for (int mi = 0; mi < 2; mi++)
#pragma unroll
            for (int nj = 0; nj < 4; nj++)
                MMA_F16(acc[mi][nj], af[mi], bf_[nj]);
    }

    // wait: 2x4 warp grid covers 64 rows only; need 2 MI iterations of rows? No:
    // WM=2 -> WROWS=64, MI=64/16=4. Fix: use MI=4 mapping instead.
    // (handled below by the correct loop — see note)
    // NOTE: the loop above used MI=2; correct mapping for 128 rows with WM=2 is
    // MI=4. To keep code simple we instead use warp grid 4x2 like R11's template.

    // --- epilogue (LN) ---
    __syncthreads();
    float* Cs = (float*)smem;   // [128][129]
#pragma unroll
    for (int mi = 0; mi < 2; mi++)
#pragma unroll
        for (int nj = 0; nj < 4; nj++) {
            int rl = warp_m * 64 + mi * 16 + (lane >> 2);
            int c = warp_n * 32 + nj * 8 + (lane & 3) * 2;
            Cs[rl * 129 + c]           = acc[mi][nj][0];
            Cs[rl * 129 + c + 1]       = acc[mi][nj][1];
            Cs[(rl + 8) * 129 + c]     = acc[mi][nj][2];
            Cs[(rl + 8) * 129 + c + 1] = acc[mi][nj][3];
        }
    __syncthreads();

    int row = tid >> 1, half = tid & 1;
    float v[64];
    float s1 = 0.0f, s2 = 0.0f;
#pragma unroll
    for (int j = 0; j < 64; j++) {
        float t = fmaxf(Cs[row * 129 + half * 64 + j] + sh_bias[half * 64 + j], 0.0f);
        v[j] = t; s1 += t; s2 += t * t;
    }
    s1 += __shfl_xor_sync(0xffffffffu, s1, 1);
    s2 += __shfl_xor_sync(0xffffffffu, s2, 1);
    float mu = s1 * (1.0f / 128.0f);
    float var = s2 * (1.0f / 128.0f) - mu * mu;
    float inv = rsqrtf(var + 1e-5f);

    int rg = m0 + row;
    if (rg >= nrows) return;
    float sc = dis[rg];
    __half* outp = C + (size_t)rg * 128 + half * 64;
#pragma unroll
    for (int j = 0; j < 64; j += 8) {
        float o[8];
#pragma unroll
        for (int q = 0; q < 8; q++)
            o[q] = ((v[j + q] - mu) * inv * sh_g[half * 64 + j + q]
                    + sh_b[half * 64 + j + q]) * sc;
        __half2 h0 = __floats2half2_rn(o[0], o[1]);
        __half2 h1 = __floats2half2_rn(o[2], o[3]);
        __half2 h2 = __floats2half2_rn(o[4], o[5]);
        __half2 h3 = __floats2half2_rn(o[6], o[7]);
        uint4 u;
        u.x = *(uint32_t*)&h0; u.y = *(uint32_t*)&h1;
        u.z = *(uint32_t*)&h2; u.w = *(uint32_t*)&h3;
        *(uint4*)(outp + j) = u;
    }
}

// Wait — gemm0 above: warp grid warp_m in {0,1} covers rows [0,64)+[64,128) with
// mi in {0,1} covering 32 rows each -> rows 0..31 and 64..95 only. That is WRONG.
// Use the proven 4x2 mapping (warp_m = wid % 4 -> WROWS 32, MI 2; warp_n = wid / 4
// covering 64 cols... also wrong for BN=128). The proven R11 template used
// WN = BN/32 = 4, WM = 2, WROWS = 64, MI = 4. Keep that. gemm0_kernel above is
// replaced by the template below; it is never launched.

// ---------------------------------------------------------------------------
// proven GEMM template (single-pass weights), EPI3 = dis*LN(relu(.+b)) -> fp16
// ---------------------------------------------------------------------------
template <int EPI>
__global__ void __launch_bounds__(256)
tgemm1p_kernel(const __half* __restrict__ A, const __half* __restrict__ Wh,
               const float* __restrict__ dis, const float* __restrict__ bias,
               const float* __restrict__ gamma, const float* __restrict__ beta,
               __half* __restrict__ C, int rbase, int nrows) {
    constexpr int LDA = 136, LDB = 136;
    constexpr int WN = 4, WM = 2, WROWS = 64, MI = 4, NJ = 4;
    constexpr int ABYTES = 128 * LDA * 2;
    extern __shared__ char smem[];
    __shared__ float sh_bias[128], sh_g[128], sh_b[128];

    int tid = threadIdx.x, wid = tid >> 5, lane = tid & 31;
    int warp_m = wid % WM, warp_n = wid / WM;
    int m0 = rbase + blockIdx.x * 128;
    uint32_t sb = smem_u32(smem);

    if (tid < 128) {
        sh_bias[tid] = bias[tid];
        sh_g[tid] = gamma[tid];
        sh_b[tid] = beta[tid];
    }

    float acc[MI][NJ][4];
#pragma unroll
    for (int i = 0; i < MI; i++)
#pragma unroll
        for (int j = 0; j < NJ; j++)
#pragma unroll
            for (int k = 0; k < 4; k++) acc[i][j][k] = 0.0f;

    int a_r = lane & 15, a_c8 = (lane >> 4) * 8, b_r = lane & 15;

#pragma unroll
    for (int it = 0; it < 8; it++) {
        int idx = it * 256 + tid;
        int row = idx >> 4, u4 = idx & 15;
        int rg = m0 + row;
        uint4 v = make_uint4(0u, 0u, 0u, 0u);
        if (rg < nrows) v = *(const uint4*)(A + (size_t)rg * 128 + u4 * 8);
        *(uint4*)(smem + (row * LDA + u4 * 8) * 2) = v;
        *(uint4*)(smem + ABYTES + (row * LDB + u4 * 8) * 2) =
            *(const uint4*)(Wh + row * 128 + u4 * 8);
    }
    __syncthreads();

#pragma unroll
    for (int ks = 0; ks < 8; ks++) {
        uint32_t af[MI][4], bf_[NJ][2];
#pragma unroll
        for (int mi = 0; mi < MI; mi++)
            LDSM_X4(af[mi], sb + ((warp_m * WROWS + mi * 16 + a_r) * LDA
                                  + ks * 16 + a_c8) * 2);
#pragma unroll
        for (int nj = 0; nj < NJ; nj++)
            LDSM_X2T(bf_[nj], sb + ABYTES + ((ks * 16 + b_r) * LDB
                                             + warp_n * 32 + nj * 8) * 2);
#pragma unroll
        for (int mi = 0; mi < MI; mi++)
#pragma unroll
            for (int nj = 0; nj < NJ; nj++)
                MMA_F16(acc[mi][nj], af[mi], bf_[nj]);
    }

    int g = lane >> 2, q2 = (lane & 3) * 2;
    __syncthreads();
    float* Cs = (float*)smem;
#pragma unroll
    for (int mi = 0; mi < MI; mi++)
#pragma unroll
        for (int nj = 0; nj < NJ; nj++) {
            int rl = warp_m * WROWS + mi * 16 + g;
            int c = warp_n * 32 + nj * 8 + q2;
            Cs[rl * 129 + c]           = acc[mi][nj][0];
            Cs[rl * 129 + c + 1]       = acc[mi][nj][1];
            Cs[(rl + 8) * 129 + c]     = acc[mi][nj][2];
            Cs[(rl + 8) * 129 + c + 1] = acc[mi][nj][3];
        }
    __syncthreads();

    int row = tid >> 1, half = tid & 1;
    float v[64];
    float s1 = 0.0f, s2 = 0.0f;
#pragma unroll
    for (int j = 0; j < 64; j++) {
        float t = fmaxf(Cs[row * 129 + half * 64 + j] + sh_bias[half * 64 + j], 0.0f);
        v[j] = t; s1 += t; s2 += t * t;
    }
    s1 += __shfl_xor_sync(0xffffffffu, s1, 1);
    s2 += __shfl_xor_sync(0xffffffffu, s2, 1);
    float mu = s1 * (1.0f / 128.0f);
    float var = s2 * (1.0f / 128.0f) - mu * mu;
    float inv = rsqrtf(var + 1e-5f);

    int rg = m0 + row;
    if (rg >= nrows) return;
    float sc = (EPI == 3) ? dis[rg] : 1.0f;
    __half* outp = C + (size_t)rg * 128 + half * 64;
#pragma unroll
    for (int j = 0; j < 64; j += 8) {
        float o[8];
#pragma unroll
        for (int q = 0; q < 8; q++)
            o[q] = ((v[j + q] - mu) * inv * sh_g[half * 64 + j + q]
                    + sh_b[half * 64 + j + q]) * sc;
        __half2 h0 = __floats2half2_rn(o[0], o[1]);
        __half2 h1 = __floats2half2_rn(o[2], o[3]);
        __half2 h2 = __floats2half2_rn(o[4], o[5]);
        __half2 h3 = __floats2half2_rn(o[6], o[7]);
        uint4 u;
        u.x = *(uint32_t*)&h0; u.y = *(uint32_t*)&h1;
        u.z = *(uint32_t*)&h2; u.w = *(uint32_t*)&h3;
        *(uint4*)(outp + j) = u;
    }
}

// ---------------------------------------------------------------------------
// GEMM1 fused with tail: u = LN(relu(t@W1+b1)); pzp = u @ Wc (hi/lo, fp32 out)
// smem plan: [A 34816 | W1h 34816] -> Cs f32 66048 -> [u 34816 | Wch 18432 | Wcl 18432]
// total 71680
// ---------------------------------------------------------------------------
__global__ void __launch_bounds__(256)
gemm1f_kernel(const __half* __restrict__ A, const __half* __restrict__ Wh,
              const __half* __restrict__ Wch, const __half* __restrict__ Wcl,
              const float* __restrict__ bias, const float* __restrict__ gamma,
              const float* __restrict__ beta,
              float* __restrict__ pzp, int nrows) {
    constexpr int LDA = 136, LDB = 136, LDC = 72;
    constexpr int WN = 4, WM = 2, WROWS = 64, MI = 4, NJ = 4;
    constexpr int ABYTES = 128 * LDA * 2;          // 34816
    constexpr int UOFF = 0, CH = 34816, CL = 34816 + 18432;
    extern __shared__ char smem[];
    __shared__ float sh_bias[128], sh_g[128], sh_b[128];

    int tid = threadIdx.x, wid = tid >> 5, lane = tid & 31;
    int warp_m = wid % WM, warp_n = wid / WM;
    int m0 = blockIdx.x * 128;
    uint32_t sb = smem_u32(smem);

    if (tid < 128) {
        sh_bias[tid] = bias[tid];
        sh_g[tid] = gamma[tid];
        sh_b[tid] = beta[tid];
    }

    float acc[MI][NJ][4];
#pragma unroll
    for (int i = 0; i < MI; i++)
#pragma unroll
        for (int j = 0; j < NJ; j++)
#pragma unroll
            for (int k = 0; k < 4; k++) acc[i][j][k] = 0.0f;

    int a_r = lane & 15, a_c8 = (lane >> 4) * 8, b_r = lane & 15;

    // ---- main GEMM staging: A (t_s) + W1h
#pragma unroll
    for (int it = 0; it < 8; it++) {
        int idx = it * 256 + tid;
        int row = idx >> 4, u4 = idx & 15;
        int rg = m0 + row;
        uint4 v = make_uint4(0u, 0u, 0u, 0u);
        if (rg < nrows) v = *(const uint4*)(A + (size_t)rg * 128 + u4 * 8);
        *(uint4*)(smem + (row * LDA + u4 * 8) * 2) = v;
        *(uint4*)(smem + ABYTES + (row * LDB + u4 * 8) * 2) =
            *(const uint4*)(Wh + row * 128 + u4 * 8);
    }
    __syncthreads();

#pragma unroll
    for (int ks = 0; ks < 8; ks++) {
        uint32_t af[MI][4], bf_[NJ][2];
#pragma unroll
        for (int mi = 0; mi < MI; mi++)
            LDSM_X4(af[mi], sb + ((warp_m * WROWS + mi * 16 + a_r) * LDA
                                  + ks * 16 + a_c8) * 2);
#pragma unroll
        for (int nj = 0; nj < NJ; nj++)
            LDSM_X2T(bf_[nj], sb + ABYTES + ((ks * 16 + b_r) * LDB
                                             + warp_n * 32 + nj * 8) * 2);
#pragma unroll
        for (int mi = 0; mi < MI; mi++)
#pragma unroll
            for (int nj = 0; nj < NJ; nj++)
                MMA_F16(acc[mi][nj], af[mi], bf_[nj]);
    }

    int g = lane >> 2, q2 = (lane & 3) * 2;

    // ---- LN exchange
    __syncthreads();
    float* Cs = (float*)smem;
#pragma unroll
    for (int mi = 0; mi < MI; mi++)
#pragma unroll
        for (int nj = 0; nj < NJ; nj++) {
            int rl = warp_m * WROWS + mi * 16 + g;
            int c = warp_n * 32 + nj * 8 + q2;
            Cs[rl * 129 + c]           = acc[mi][nj][0];
            Cs[rl * 129 + c + 1]       = acc[mi][nj][1];
            Cs[(rl + 8) * 129 + c]     = acc[mi][nj][2];
            Cs[(rl + 8) * 129 + c + 1] = acc[mi][nj][3];
        }
    __syncthreads();

    int row = tid >> 1, half = tid & 1;
    float v[64];
    float s1 = 0.0f, s2 = 0.0f;
#pragma unroll
    for (int j = 0; j < 64; j++) {
        float t = fmaxf(Cs[row * 129 + half * 64 + j] + sh_bias[half * 64 + j], 0.0f);
        v[j] = t; s1 += t; s2 += t * t;
    }
    s1 += __shfl_xor_sync(0xffffffffu, s1, 1);
    s2 += __shfl_xor_sync(0xffffffffu, s2, 1);
    float mu = s1 * (1.0f / 128.0f);
    float var = s2 * (1.0f / 128.0f) - mu * mu;
    float inv = rsqrtf(var + 1e-5f);

    __syncthreads();   // all Cs reads done before u overwrites smem

    // write u (fp16, A-layout) into smem; also stage Wc hi/lo
    {
        __half* uP = (__half*)(smem + UOFF);
#pragma unroll
        for (int j = 0; j < 64; j += 8) {
            float o[8];
#pragma unroll
            for (int q = 0; q < 8; q++)
                o[q] = (v[j + q] - mu) * inv * sh_g[half * 64 + j + q]
                       + sh_b[half * 64 + j + q];
            __half2 h0 = __floats2half2_rn(o[0], o[1]);
            __half2 h1 = __floats2half2_rn(o[2], o[3]);
            __half2 h2 = __floats2half2_rn(o[4], o[5]);
            __half2 h3 = __floats2half2_rn(o[6], o[7]);
            uint4 u;
            u.x = *(uint32_t*)&h0; u.y = *(uint32_t*)&h1;
            u.z = *(uint32_t*)&h2; u.w = *(uint32_t*)&h3;
            *(uint4*)(uP + row * LDA + half * 64 + j) = u;
        }
    }
#pragma unroll
    for (int it = 0; it < 4; it++) {
        int idx = it * 256 + tid;          // 1024 uint4 per copy
        int kk = idx >> 3, u4 = idx & 7;
        *(uint4*)(smem + CH + (kk * LDC + u4 * 8) * 2) =
            *(const uint4*)(Wch + kk * 64 + u4 * 8);
        *(uint4*)(smem + CL + (kk * LDC + u4 * 8) * 2) =
            *(const uint4*)(Wcl + kk * 64 + u4 * 8);
    }
    __syncthreads();

    // ---- tail MMA: pz(128x64) = u(128x128) @ Wc(128x64), hi+lo passes
    // warp grid 4x2: warp_m2 covers 32 rows, warp_n2 covers 32 cols
    int warp_m2 = wid & 3, warp_n2 = wid >> 2;
    float acc2[2][4][4];
#pragma unroll
    for (int i = 0; i < 2; i++)
#pragma unroll
        for (int j = 0; j < 4; j++)
#pragma unroll
            for (int k = 0; k < 4; k++) acc2[i][j][k] = 0.0f;

#pragma unroll
    for (int p = 0; p < 2; p++) {
        uint32_t bB = sb + (p ? CL : CH);
#pragma unroll
        for (int ks = 0; ks < 8; ks++) {
            uint32_t af[2][4], bf_[4][2];
#pragma unroll
            for (int mi = 0; mi < 2; mi++)
                LDSM_X4(af[mi], sb + UOFF + ((warp_m2 * 32 + mi * 16 + a_r) * LDA
                                             + ks * 16 + a_c8) * 2);
#pragma unroll
            for (int nj = 0; nj < 4; nj++)
                LDSM_X2T(bf_[nj], bB + ((ks * 16 + b_r) * LDC
                                        + warp_n2 * 32 + nj * 8) * 2);
#pragma unroll
            for (int mi = 0; mi < 2; mi++)
#pragma unroll
                for (int nj = 0; nj < 4; nj++)
                    MMA_F16(acc2[mi][nj], af[mi], bf_[nj]);
        }
    }

    // ---- store fp32 partials
#pragma unroll
    for (int mi = 0; mi < 2; mi++)
#pragma unroll
        for (int nj = 0; nj < 4; nj++) {
            int c = warp_n2 * 32 + nj * 8 + q2;
            int r0 = m0 + warp_m2 * 32 + mi * 16 + g;
            if (r0 < nrows) {
                float2 o = {acc2[mi][nj][0], acc2[mi][nj][1]};
                *(float2*)(pzp + (size_t)r0 * 64 + c) = o;
            }
            int r1 = r0 + 8;
            if (r1 < nrows) {
                float2 o = {acc2[mi][nj][2], acc2[mi][nj][3]};
                *(float2*)(pzp + (size_t)r1 * 64 + c) = o;
            }
        }
}

#define SMEM_G0 (34816 * 2)      // 69632
#define SMEM_G1F 71680

// ---------------------------------------------------------------------------
// aggregation (warp per node), node range [base, nend)
// ---------------------------------------------------------------------------
__global__ void __launch_bounds__(256)
agg128hh_kernel(const __half* __restrict__ p, const float* __restrict__ dis,
                const int* __restrict__ rowptr, const int* __restrict__ deg,
                const int* __restrict__ col, __half* __restrict__ out,
                int base, int nend) {
    int w = base + ((blockIdx.x * blockDim.x + threadIdx.x) >> 5);
    if (w >= nend) return;
    int lane = threadIdx.x & 31;
    const uint2* p2 = (const uint2*)p;
    int start = rowptr[w], d = deg[w];
    uint2 a = p2[(size_t)w * 32 + lane];
    float2 f0 = __half22float2(*(__half2*)&a.x);
    float2 f1 = __half22float2(*(__half2*)&a.y);
    float ax = f0.x, ay = f0.y, az = f1.x, aw = f1.y;

    int c0 = 0;
    for (; c0 + 32 <= d; c0 += 32) {
        int idx = col[start + c0 + lane];
#pragma unroll 8
        for (int j = 0; j < 32; j++) {
            int u = __shfl_sync(0xffffffffu, idx, j);
            uint2 v = p2[(size_t)u * 32 + lane];
            float2 g0 = __half22float2(*(__half2*)&v.x);
            float2 g1 = __half22float2(*(__half2*)&v.y);
            ax += g0.x; ay += g0.y; az += g1.x; aw += g1.y;
        }
    }
    int m = d - c0;
    if (m > 0) {
        int idx = (lane < m) ? col[start + c0 + lane] : 0;
        for (int j = 0; j < m; j++) {
            int u = __shfl_sync(0xffffffffu, idx, j);
            uint2 v = p2[(size_t)u * 32 + lane];
            float2 g0 = __half22float2(*(__half2*)&v.x);
            float2 g1 = __half22float2(*(__half2*)&v.y);
            ax += g0.x; ay += g0.y; az += g1.x; aw += g1.y;
        }
    }
    float s = dis[w];
    __half2 h0 = __floats2half2_rn(ax * s, ay * s);
    __half2 h1 = __floats2half2_rn(az * s, aw * s);
    uint2 o;
    o.x = *(uint32_t*)&h0; o.y = *(uint32_t*)&h1;
    ((uint2*)out)[(size_t)w * 32 + lane] = o;
}

// fp16 payload, 64-wide rows: final output fp32 + cbias
__global__ void __launch_bounds__(256)
agg64h_kernel(const uint32_t* __restrict__ p, const float* __restrict__ dis,
              const int* __restrict__ rowptr, const int* __restrict__ deg,
              const int* __restrict__ col, const float* __restrict__ cbias,
              float2* __restrict__ out, int n) {
    int w = (blockIdx.x * blockDim.x + threadIdx.x) >> 5;
    if (w >= n) return;
    int lane = threadIdx.x & 31;
    int start = rowptr[w], d = deg[w];
    uint32_t a = p[(size_t)w * 32 + lane];
    float2 f = __half22float2(*(__half2*)&a);
    float ax = f.x, ay = f.y;

    int c0 = 0;
    for (; c0 + 32 <= d; c0 += 32) {
        int idx = col[start + c0 + lane];
#pragma unroll 8
        for (int j = 0; j < 32; j++) {
            int u = __shfl_sync(0xffffffffu, idx, j);
            uint32_t v = p[(size_t)u * 32 + lane];
            float2 g = __half22float2(*(__half2*)&v);
            ax += g.x; ay += g.y;
        }
    }
    int m = d - c0;
    if (m > 0) {
        int idx = (lane < m) ? col[start + c0 + lane] : 0;
        for (int j = 0; j < m; j++) {
            int u = __shfl_sync(0xffffffffu, idx, j);
            uint32_t v = p[(size_t)u * 32 + lane];
            float2 g = __half22float2(*(__half2*)&v);
            ax += g.x; ay += g.y;
        }
    }
    float s = dis[w];
    float2 o = {ax * s + cbias[lane * 2], ay * s + cbias[lane * 2 + 1]};
    out[(size_t)w * 32 + lane] = o;
}

// ---------------------------------------------------------------------------
extern "C" void kernel_launch(void* const* d_in, const int* in_sizes, int n_in,
                              void* d_out, int out_size) {
    const float* x     = (const float*)d_in[0];
    const int*   ei    = (const int*)d_in[1];
    const float* W0    = (const float*)d_in[2];
    const float* b0    = (const float*)d_in[3];
    const float* W1    = (const float*)d_in[4];
    const float* b1    = (const float*)d_in[5];
    const float* W2    = (const float*)d_in[6];
    const float* b2    = (const float*)d_in[7];
    const float* gamma = (const float*)d_in[8];
    const float* beta  = (const float*)d_in[9];
    const float* Wf    = (const float*)d_in[10];
    const float* bf    = (const float*)d_in[11];
    float* out = (float*)d_out;

    const int N = in_sizes[0] / 128;
    const int E = in_sizes[1] / 2;
    const int* src = ei;
    const int* dst = ei + E;

    __half *pxh, *yh, *ph, *th, *pzh, *w0h, *w1h, *wch, *wcl;
    float *pzp, *wc, *cbias, *dis;
    int *deg, *rp, *cur, *col, *bsum;
    cudaGetSymbolAddress((void**)&pxh,   g_pxh);
    cudaGetSymbolAddress((void**)&yh,    g_yh);
    cudaGetSymbolAddress((void**)&ph,    g_ph);
    cudaGetSymbolAddress((void**)&th,    g_th);
    cudaGetSymbolAddress((void**)&pzp,   g_pzp);
    cudaGetSymbolAddress((void**)&pzh,   g_pzh);
    cudaGetSymbolAddress((void**)&wc,    g_wc);
    cudaGetSymbolAddress((void**)&w0h,   g_w0h);
    cudaGetSymbolAddress((void**)&w1h,   g_w1h);
    cudaGetSymbolAddress((void**)&wch,   g_wch);
    cudaGetSymbolAddress((void**)&wcl,   g_wcl);
    cudaGetSymbolAddress((void**)&cbias, g_cbias);
    cudaGetSymbolAddress((void**)&dis,   g_dis);
    cudaGetSymbolAddress((void**)&deg,   g_deg);
    cudaGetSymbolAddress((void**)&rp,    g_rowptr);
    cudaGetSymbolAddress((void**)&cur,   g_cursor);
    cudaGetSymbolAddress((void**)&col,   g_col);
    cudaGetSymbolAddress((void**)&bsum,  g_bsum);

    // 2 created streams + legacy default, 8 events (guard-safe envelope)
    static bool inited = false;
    static cudaStream_t st1, st2;
    static cudaEvent_t evRoot, evDis, evPre, evW, evY0, evY1, ev1, ev2;
    if (!inited) {
        cudaStreamCreateWithFlags(&st1, cudaStreamNonBlocking);
        cudaStreamCreateWithFlags(&st2, cudaStreamNonBlocking);
        cudaEventCreateWithFlags(&evRoot, cudaEventDisableTiming);
        cudaEventCreateWithFlags(&evDis, cudaEventDisableTiming);
        cudaEventCreateWithFlags(&evPre, cudaEventDisableTiming);
        cudaEventCreateWithFlags(&evW,  cudaEventDisableTiming);
        cudaEventCreateWithFlags(&evY0, cudaEventDisableTiming);
        cudaEventCreateWithFlags(&evY1, cudaEventDisableTiming);
        cudaEventCreateWithFlags(&ev1,  cudaEventDisableTiming);
        cudaEventCreateWithFlags(&ev2,  cudaEventDisableTiming);
        cudaFuncSetAttribute(tgemm1p_kernel<3>,
                             cudaFuncAttributeMaxDynamicSharedMemorySize, SMEM_G0);
        cudaFuncSetAttribute(gemm1f_kernel,
                             cudaFuncAttributeMaxDynamicSharedMemorySize, SMEM_G1F);
        inited = true;
    }

    const int TB = 256;
    int nB = (N + TB - 1) / TB;
    int eB = (E + TB - 1) / TB;
    int nbScan = (N + SCAN_B - 1) / SCAN_B;
    int aggB = (N * 32 + TB - 1) / TB;
    int gB = (N + 127) / 128;

    const int H = ((N / 2 + 127) / 128) * 128;
    int gB0 = H / 128;
    int gB1 = (N - H + 127) / 128;
    int aB0 = (H * 32 + TB - 1) / TB;
    int aB1 = ((N - H) * 32 + TB - 1) / TB;

    cudaStream_t s0 = 0;

    // --- capture fork for st1 (weights) ---
    zero_kernel<<<nB, TB, 0, s0>>>(deg, cur, N);
    cudaEventRecord(evRoot, s0);
    cudaStreamWaitEvent(st1, evRoot, 0);

    // --- weight folding + fp16 conversion on st1 ---
    wc_kernel<<<384, 64, 0, st1>>>(W2, Wf, wc);
    cbias_kernel<<<1, 64, 0, st1>>>(b2, Wf, bf, cbias);
    convs_kernel<<<(3 * 128 * 128 + 255) / 256, 256, 0, st1>>>(W0, w0h, 3 * 128 * 128);
    convs_kernel<<<(3 * 128 * 128 + 255) / 256, 256, 0, st1>>>(W1, w1h, 3 * 128 * 128);
    convh_kernel<<<(384 * 64 + 255) / 256, 256, 0, st1>>>(wc, wch, wcl, 384 * 64);
    cudaEventRecord(evW, st1);

    // --- graph prep on s0 ---
    count_kernel<<<eB, TB, 0, s0>>>(dst, deg, E);
    scan1_kernel<<<nbScan, SCAN_B, 0, s0>>>(deg, rp, bsum, dis, N);
    cudaEventRecord(evDis, s0);

    cudaStreamWaitEvent(st2, evDis, 0);
    prescale_h_kernel<<<(N * 32 + TB - 1) / TB, TB, 0, st2>>>(
        (const float4*)x, dis, (uint2*)pxh, N * 32);
    cudaEventRecord(evPre, st2);

    scan2_kernel<<<1, 32, 0, s0>>>(bsum, nbScan);
    scan3_kernel<<<nB, TB, 0, s0>>>(rp, bsum, N);
    fill_kernel<<<eB, TB, 0, s0>>>(src, dst, rp, cur, col, E);

    // --- agg_y in halves ---
    cudaStreamWaitEvent(s0, evPre, 0);
    agg128hh_kernel<<<aB0, TB, 0, s0>>>(pxh, dis, rp, deg, col, yh, 0, H);
    cudaEventRecord(evY0, s0);
    agg128hh_kernel<<<aB1, TB, 0, s0>>>(pxh, dis, rp, deg, col, yh, H, N);
    cudaEventRecord(evY1, s0);

    // --- per-scale chains on {s0, st1, st2} ---
    cudaStreamWaitEvent(s0, evW, 0);
    cudaStreamWaitEvent(st2, evW, 0);
    cudaStream_t chain[3] = {s0, st1, st2};
    for (int s = 0; s < 3; s++) {
        cudaStream_t cs = chain[s];
        __half* ph_s = ph + (size_t)s * NN * 128;
        __half* t_s  = th + (size_t)s * NN * 128;
        float* pzp_s = pzp + (size_t)s * NN * 64;
        if (cs != s0) cudaStreamWaitEvent(cs, evY0, 0);
        tgemm1p_kernel<3><<<gB0, 256, SMEM_G0, cs>>>(
            yh, w0h + s * 16384, dis, b0 + s * 128,
            gamma + (s * 3 + 0) * 128, beta + (s * 3 + 0) * 128,
            ph_s, 0, N);
        if (cs != s0) cudaStreamWaitEvent(cs, evY1, 0);
        tgemm1p_kernel<3><<<gB1, 256, SMEM_G0, cs>>>(
            yh, w0h + s * 16384, dis, b0 + s * 128,
            gamma + (s * 3 + 0) * 128, beta + (s * 3 + 0) * 128,
            ph_s, H, N);
        agg128hh_kernel<<<aggB, TB, 0, cs>>>(ph_s, dis, rp, deg, col, t_s, 0, N);
        gemm1f_kernel<<<gB, 256, SMEM_G1F, cs>>>(
            t_s, w1h + s * 16384, wch + s * 8192, wcl + s * 8192,
            b1 + s * 128, gamma + (s * 3 + 1) * 128, beta + (s * 3 + 1) * 128,
            pzp_s, N);
    }
    cudaEventRecord(ev1, st1);
    cudaEventRecord(ev2, st2);
    cudaStreamWaitEvent(s0, ev1, 0);
    cudaStreamWaitEvent(s0, ev2, 0);

    // --- sum partials + final aggregation ---
    pzsum_kernel<<<(N * 32 + TB - 1) / TB, TB, 0, s0>>>(
        pzp, pzp + (size_t)NN * 64, pzp + (size_t)2 * NN * 64, dis,
        (uint32_t*)pzh, N * 32);
    agg64h_kernel<<<aggB, TB, 0, s0>>>((const uint32_t*)pzh, dis, rp, deg, col,
                                       cbias, (float2*)out, N);
}

// round 14
// speedup vs baseline: 1.5801x; 1.0144x over previous
#include <cuda_runtime.h>
#include <cuda_fp16.h>
#include <cstdint>

#define NN 100000
#define EE 3200000
#define SCAN_B 512
#define NBLK_SCAN ((NN + SCAN_B - 1) / SCAN_B)

// -------- device scratch (no cudaMalloc allowed) --------
__device__ __half g_pxh[NN * 128];       // fp16 dis-prescaled x
__device__ __half g_yh[NN * 128];        // y = A_hat x (fp16)
__device__ __half g_ph[3][NN * 128];     // per-scale dis*LN(relu(...)) fp16
__device__ __half g_th[3][NN * 128];     // per-scale t_s (fp16)
__device__ float  g_pzp[3][NN * 64];     // per-scale tail partials (fp32)
__device__ __half g_pzh[NN * 64];        // fp16 tail (summed, dis-scaled)
__device__ float  g_wc[384 * 64];
__device__ __half g_w0h[3 * 128 * 128];
__device__ __half g_w1h[3 * 128 * 128];
__device__ __half g_wch[384 * 64], g_wcl[384 * 64];
__device__ float  g_cbias[64];
__device__ float  g_dis[NN];
__device__ int    g_deg[NN];
__device__ int    g_rowptr[NN];
__device__ int    g_cursor[NN];
__device__ int    g_col[EE];
__device__ int    g_bsum[NBLK_SCAN + 1];

// ---------------------------------------------------------------------------
// graph prep
// ---------------------------------------------------------------------------
__global__ void zero_kernel(int* deg, int* cur, int n) {
    int i = blockIdx.x * blockDim.x + threadIdx.x;
    if (i < n) { deg[i] = 0; cur[i] = 0; }
}

// 2 edges per thread
__global__ void count_kernel(const int* __restrict__ dst, int* __restrict__ deg, int e) {
    int i = (blockIdx.x * blockDim.x + threadIdx.x) * 2;
    if (i + 1 < e) {
        int2 d = *(const int2*)(dst + i);
        atomicAdd(&deg[d.x], 1);
        atomicAdd(&deg[d.y], 1);
    } else if (i < e) {
        atomicAdd(&deg[dst[i]], 1);
    }
}

// exclusive scan phase 1 + fused dis = rsqrt(deg+1)
__global__ void scan1_kernel(const int* __restrict__ deg, int* __restrict__ out,
                             int* __restrict__ bsum, float* __restrict__ dis, int n) {
    __shared__ int sh[SCAN_B];
    int tid = threadIdx.x;
    int i = blockIdx.x * SCAN_B + tid;
    int v = (i < n) ? deg[i] : 0;
    if (i < n) dis[i] = rsqrtf((float)v + 1.0f);
    sh[tid] = v;
    __syncthreads();
#pragma unroll
    for (int off = 1; off < SCAN_B; off <<= 1) {
        int t = (tid >= off) ? sh[tid - off] : 0;
        __syncthreads();
        sh[tid] += t;
        __syncthreads();
    }
    if (i < n) out[i] = sh[tid] - v;
    if (tid == SCAN_B - 1) bsum[blockIdx.x] = sh[tid];
}

__global__ void scan2_kernel(int* bsum, int nb) {
    if (threadIdx.x == 0 && blockIdx.x == 0) {
        int acc = 0;
        for (int i = 0; i < nb; i++) { int t = bsum[i]; bsum[i] = acc; acc += t; }
    }
}

__global__ void scan3_kernel(int* __restrict__ out, const int* __restrict__ bsum, int n) {
    int i = blockIdx.x * blockDim.x + threadIdx.x;
    if (i < n) out[i] += bsum[i / SCAN_B];
}

// 2 edges per thread
__global__ void fill_kernel(const int* __restrict__ src, const int* __restrict__ dst,
                            const int* __restrict__ rowptr, int* __restrict__ cur,
                            int* __restrict__ col, int e) {
    int i = (blockIdx.x * blockDim.x + threadIdx.x) * 2;
    if (i + 1 < e) {
        int2 d = *(const int2*)(dst + i);
        int2 s = *(const int2*)(src + i);
        int p0 = rowptr[d.x] + atomicAdd(&cur[d.x], 1);
        col[p0] = s.x;
        int p1 = rowptr[d.y] + atomicAdd(&cur[d.y], 1);
        col[p1] = s.y;
    } else if (i < e) {
        int d = dst[i];
        int pos = rowptr[d] + atomicAdd(&cur[d], 1);
        col[pos] = src[i];
    }
}

// ---------------------------------------------------------------------------
// weight folding / conversion / prescale
// ---------------------------------------------------------------------------
__global__ void wc_kernel(const float* __restrict__ W2, const float* __restrict__ Wf,
                          float* __restrict__ Wc) {
    int r = blockIdx.x;
    int s = r >> 7, i = r & 127;
    int j = threadIdx.x;
    float acc = 0.0f;
#pragma unroll 8
    for (int k = 0; k < 64; k++)
        acc = fmaf(W2[(s * 128 + i) * 64 + k], Wf[(s * 64 + k) * 64 + j], acc);
    Wc[r * 64 + j] = acc;
}

__global__ void cbias_kernel(const float* __restrict__ b2, const float* __restrict__ Wf,
                             const float* __restrict__ bf, float* __restrict__ cb) {
    int j = threadIdx.x;
    float acc = bf[j];
#pragma unroll 8
    for (int r = 0; r < 192; r++) acc = fmaf(b2[r], Wf[r * 64 + j], acc);
    cb[j] = acc;
}

__global__ void convs_kernel(const float* __restrict__ W, __half* __restrict__ Wh, int n) {
    int i = blockIdx.x * blockDim.x + threadIdx.x;
    if (i < n) Wh[i] = __float2half_rn(W[i]);
}

__global__ void convh_kernel(const float* __restrict__ W, __half* __restrict__ Wh,
                             __half* __restrict__ Wl, int n) {
    int i = blockIdx.x * blockDim.x + threadIdx.x;
    if (i < n) {
        float w = W[i];
        __half h = __float2half_rn(w);
        Wh[i] = h;
        Wl[i] = __float2half_rn(w - __half2float(h));
    }
}

__global__ void prescale_h_kernel(const float4* __restrict__ x, const float* __restrict__ dis,
                                  uint2* __restrict__ px, int n4) {
    int i = blockIdx.x * blockDim.x + threadIdx.x;
    if (i < n4) {
        float s = dis[i >> 5];
        float4 v = x[i];
        __half2 h0 = __floats2half2_rn(v.x * s, v.y * s);
        __half2 h1 = __floats2half2_rn(v.z * s, v.w * s);
        uint2 u;
        u.x = *(uint32_t*)&h0; u.y = *(uint32_t*)&h1;
        px[i] = u;
    }
}

// pzh = fp16( dis[r] * (p0 + p1 + p2) ), 2 elems per thread
__global__ void pzsum_kernel(const float* __restrict__ p0, const float* __restrict__ p1,
                             const float* __restrict__ p2, const float* __restrict__ dis,
                             uint32_t* __restrict__ pzh, int n2) {
    int i = blockIdx.x * blockDim.x + threadIdx.x;
    if (i < n2) {
        float s = dis[i >> 5];
        float2 a = ((const float2*)p0)[i];
        float2 b = ((const float2*)p1)[i];
        float2 c = ((const float2*)p2)[i];
        __half2 h = __floats2half2_rn((a.x + b.x + c.x) * s, (a.y + b.y + c.y) * s);
        pzh[i] = *(uint32_t*)&h;
    }
}

// ---------------------------------------------------------------------------
// PTX helpers
// ---------------------------------------------------------------------------
__device__ __forceinline__ uint32_t smem_u32(const void* p) {
    uint32_t a;
    asm("{ .reg .u64 t; cvta.to.shared.u64 t, %1; cvt.u32.u64 %0, t; }"
        : "=r"(a) : "l"(p));
    return a;
}

#define LDSM_X4(r, addr)                                                      \
    asm volatile("ldmatrix.sync.aligned.m8n8.x4.shared.b16 {%0,%1,%2,%3}, [%4];" \
                 : "=r"((r)[0]), "=r"((r)[1]), "=r"((r)[2]), "=r"((r)[3])     \
                 : "r"(addr))

#define LDSM_X2T(r, addr)                                                     \
    asm volatile("ldmatrix.sync.aligned.m8n8.x2.trans.shared.b16 {%0,%1}, [%2];" \
                 : "=r"((r)[0]), "=r"((r)[1]) : "r"(addr))

#define MMA_F16(d, a, b)                                                      \
    asm volatile("mma.sync.aligned.m16n8k16.row.col.f32.f16.f16.f32 "         \
                 "{%0,%1,%2,%3}, {%4,%5,%6,%7}, {%8,%9}, {%0,%1,%2,%3};"      \
                 : "+f"((d)[0]), "+f"((d)[1]), "+f"((d)[2]), "+f"((d)[3])     \
                 : "r"((a)[0]), "r"((a)[1]), "r"((a)[2]), "r"((a)[3]),        \
                   "r"((b)[0]), "r"((b)[1]))

// ---------------------------------------------------------------------------
// GEMM template (single-pass weights), EPI3 = dis*LN(relu(.+b)) -> fp16
// rows: [rbase + bid*128, ...), bounded by nrows
// ---------------------------------------------------------------------------
template <int EPI>
__global__ void __launch_bounds__(256)
tgemm1p_kernel(const __half* __restrict__ A, const __half* __restrict__ Wh,
               const float* __restrict__ dis, const float* __restrict__ bias,
               const float* __restrict__ gamma, const float* __restrict__ beta,
               __half* __restrict__ C, int rbase, int nrows) {
    constexpr int LDA = 136, LDB = 136;
    constexpr int WN = 4, WM = 2, WROWS = 64, MI = 4, NJ = 4;
    constexpr int ABYTES = 128 * LDA * 2;
    extern __shared__ char smem[];
    __shared__ float sh_bias[128], sh_g[128], sh_b[128];

    int tid = threadIdx.x, wid = tid >> 5, lane = tid & 31;
    int warp_m = wid % WM, warp_n = wid / WM;
    int m0 = rbase + blockIdx.x * 128;
    uint32_t sb = smem_u32(smem);

    if (tid < 128) {
        sh_bias[tid] = bias[tid];
        sh_g[tid] = gamma[tid];
        sh_b[tid] = beta[tid];
    }

    float acc[MI][NJ][4];
#pragma unroll
    for (int i = 0; i < MI; i++)
#pragma unroll
        for (int j = 0; j < NJ; j++)
#pragma unroll
            for (int k = 0; k < 4; k++) acc[i][j][k] = 0.0f;

    int a_r = lane & 15, a_c8 = (lane >> 4) * 8, b_r = lane & 15;

#pragma unroll
    for (int it = 0; it < 8; it++) {
        int idx = it * 256 + tid;
        int row = idx >> 4, u4 = idx & 15;
        int rg = m0 + row;
        uint4 v = make_uint4(0u, 0u, 0u, 0u);
        if (rg < nrows) v = *(const uint4*)(A + (size_t)rg * 128 + u4 * 8);
        *(uint4*)(smem + (row * LDA + u4 * 8) * 2) = v;
        *(uint4*)(smem + ABYTES + (row * LDB + u4 * 8) * 2) =
            *(const uint4*)(Wh + row * 128 + u4 * 8);
    }
    __syncthreads();

#pragma unroll
    for (int ks = 0; ks < 8; ks++) {
        uint32_t af[MI][4], bf_[NJ][2];
#pragma unroll
        for (int mi = 0; mi < MI; mi++)
            LDSM_X4(af[mi], sb + ((warp_m * WROWS + mi * 16 + a_r) * LDA
                                  + ks * 16 + a_c8) * 2);
#pragma unroll
        for (int nj = 0; nj < NJ; nj++)
            LDSM_X2T(bf_[nj], sb + ABYTES + ((ks * 16 + b_r) * LDB
                                             + warp_n * 32 + nj * 8) * 2);
#pragma unroll
        for (int mi = 0; mi < MI; mi++)
#pragma unroll
            for (int nj = 0; nj < NJ; nj++)
                MMA_F16(acc[mi][nj], af[mi], bf_[nj]);
    }

    int g = lane >> 2, q2 = (lane & 3) * 2;
    __syncthreads();
    float* Cs = (float*)smem;
#pragma unroll
    for (int mi = 0; mi < MI; mi++)
#pragma unroll
        for (int nj = 0; nj < NJ; nj++) {
            int rl = warp_m * WROWS + mi * 16 + g;
            int c = warp_n * 32 + nj * 8 + q2;
            Cs[rl * 129 + c]           = acc[mi][nj][0];
            Cs[rl * 129 + c + 1]       = acc[mi][nj][1];
            Cs[(rl + 8) * 129 + c]     = acc[mi][nj][2];
            Cs[(rl + 8) * 129 + c + 1] = acc[mi][nj][3];
        }
    __syncthreads();

    int row = tid >> 1, half = tid & 1;
    float v[64];
    float s1 = 0.0f, s2 = 0.0f;
#pragma unroll
    for (int j = 0; j < 64; j++) {
        float t = fmaxf(Cs[row * 129 + half * 64 + j] + sh_bias[half * 64 + j], 0.0f);
        v[j] = t; s1 += t; s2 += t * t;
    }
    s1 += __shfl_xor_sync(0xffffffffu, s1, 1);
    s2 += __shfl_xor_sync(0xffffffffu, s2, 1);
    float mu = s1 * (1.0f / 128.0f);
    float var = s2 * (1.0f / 128.0f) - mu * mu;
    float inv = rsqrtf(var + 1e-5f);

    int rg = m0 + row;
    if (rg >= nrows) return;
    float sc = (EPI == 3) ? dis[rg] : 1.0f;
    __half* outp = C + (size_t)rg * 128 + half * 64;
#pragma unroll
    for (int j = 0; j < 64; j += 8) {
        float o[8];
#pragma unroll
        for (int q = 0; q < 8; q++)
            o[q] = ((v[j + q] - mu) * inv * sh_g[half * 64 + j + q]
                    + sh_b[half * 64 + j + q]) * sc;
        __half2 h0 = __floats2half2_rn(o[0], o[1]);
        __half2 h1 = __floats2half2_rn(o[2], o[3]);
        __half2 h2 = __floats2half2_rn(o[4], o[5]);
        __half2 h3 = __floats2half2_rn(o[6], o[7]);
        uint4 u;
        u.x = *(uint32_t*)&h0; u.y = *(uint32_t*)&h1;
        u.z = *(uint32_t*)&h2; u.w = *(uint32_t*)&h3;
        *(uint4*)(outp + j) = u;
    }
}

// ---------------------------------------------------------------------------
// GEMM1 fused with tail: u = LN(relu(t@W1+b1)); pzp = u @ Wc (hi/lo, fp32 out)
// smem: [A 34816 | W1h 34816] -> Cs f32 66048 -> [u 34816 | Wch 18432 | Wcl 18432]
// ---------------------------------------------------------------------------
__global__ void __launch_bounds__(256)
gemm1f_kernel(const __half* __restrict__ A, const __half* __restrict__ Wh,
              const __half* __restrict__ Wch, const __half* __restrict__ Wcl,
              const float* __restrict__ bias, const float* __restrict__ gamma,
              const float* __restrict__ beta,
              float* __restrict__ pzp, int nrows) {
    constexpr int LDA = 136, LDB = 136, LDC = 72;
    constexpr int WN = 4, WM = 2, WROWS = 64, MI = 4, NJ = 4;
    constexpr int ABYTES = 128 * LDA * 2;
    constexpr int UOFF = 0, CH = 34816, CL = 34816 + 18432;
    extern __shared__ char smem[];
    __shared__ float sh_bias[128], sh_g[128], sh_b[128];

    int tid = threadIdx.x, wid = tid >> 5, lane = tid & 31;
    int warp_m = wid % WM, warp_n = wid / WM;
    int m0 = blockIdx.x * 128;
    uint32_t sb = smem_u32(smem);

    if (tid < 128) {
        sh_bias[tid] = bias[tid];
        sh_g[tid] = gamma[tid];
        sh_b[tid] = beta[tid];
    }

    float acc[MI][NJ][4];
#pragma unroll
    for (int i = 0; i < MI; i++)
#pragma unroll
        for (int j = 0; j < NJ; j++)
#pragma unroll
            for (int k = 0; k < 4; k++) acc[i][j][k] = 0.0f;

    int a_r = lane & 15, a_c8 = (lane >> 4) * 8, b_r = lane & 15;

#pragma unroll
    for (int it = 0; it < 8; it++) {
        int idx = it * 256 + tid;
        int row = idx >> 4, u4 = idx & 15;
        int rg = m0 + row;
        uint4 v = make_uint4(0u, 0u, 0u, 0u);
        if (rg < nrows) v = *(const uint4*)(A + (size_t)rg * 128 + u4 * 8);
        *(uint4*)(smem + (row * LDA + u4 * 8) * 2) = v;
        *(uint4*)(smem + ABYTES + (row * LDB + u4 * 8) * 2) =
            *(const uint4*)(Wh + row * 128 + u4 * 8);
    }
    __syncthreads();

#pragma unroll
    for (int ks = 0; ks < 8; ks++) {
        uint32_t af[MI][4], bf_[NJ][2];
#pragma unroll
        for (int mi = 0; mi < MI; mi++)
            LDSM_X4(af[mi], sb + ((warp_m * WROWS + mi * 16 + a_r) * LDA
                                  + ks * 16 + a_c8) * 2);
#pragma unroll
        for (int nj = 0; nj < NJ; nj++)
            LDSM_X2T(bf_[nj], sb + ABYTES + ((ks * 16 + b_r) * LDB
                                             + warp_n * 32 + nj * 8) * 2);
#pragma unroll
        for (int mi = 0; mi < MI; mi++)
#pragma unroll
            for (int nj = 0; nj < NJ; nj++)
                MMA_F16(acc[mi][nj], af[mi], bf_[nj]);
    }

    int g = lane >> 2, q2 = (lane & 3) * 2;

    __syncthreads();
    float* Cs = (float*)smem;
#pragma unroll
    for (int mi = 0; mi < MI; mi++)
#pragma unroll
        for (int nj = 0; nj < NJ; nj++) {
            int rl = warp_m * WROWS + mi * 16 + g;
            int c = warp_n * 32 + nj * 8 + q2;
            Cs[rl * 129 + c]           = acc[mi][nj][0];
            Cs[rl * 129 + c + 1]       = acc[mi][nj][1];
            Cs[(rl + 8) * 129 + c]     = acc[mi][nj][2];
            Cs[(rl + 8) * 129 + c + 1] = acc[mi][nj][3];
        }
    __syncthreads();

    int row = tid >> 1, half = tid & 1;
    float v[64];
    float s1 = 0.0f, s2 = 0.0f;
#pragma unroll
    for (int j = 0; j < 64; j++) {
        float t = fmaxf(Cs[row * 129 + half * 64 + j] + sh_bias[half * 64 + j], 0.0f);
        v[j] = t; s1 += t; s2 += t * t;
    }
    s1 += __shfl_xor_sync(0xffffffffu, s1, 1);
    s2 += __shfl_xor_sync(0xffffffffu, s2, 1);
    float mu = s1 * (1.0f / 128.0f);
    float var = s2 * (1.0f / 128.0f) - mu * mu;
    float inv = rsqrtf(var + 1e-5f);

    __syncthreads();   // all Cs reads done before u overwrites smem

    {
        __half* uP = (__half*)(smem + UOFF);
#pragma unroll
        for (int j = 0; j < 64; j += 8) {
            float o[8];
#pragma unroll
            for (int q = 0; q < 8; q++)
                o[q] = (v[j + q] - mu) * inv * sh_g[half * 64 + j + q]
                       + sh_b[half * 64 + j + q];
            __half2 h0 = __floats2half2_rn(o[0], o[1]);
            __half2 h1 = __floats2half2_rn(o[2], o[3]);
            __half2 h2 = __floats2half2_rn(o[4], o[5]);
            __half2 h3 = __floats2half2_rn(o[6], o[7]);
            uint4 u;
            u.x = *(uint32_t*)&h0; u.y = *(uint32_t*)&h1;
            u.z = *(uint32_t*)&h2; u.w = *(uint32_t*)&h3;
            *(uint4*)(uP + row * LDA + half * 64 + j) = u;
        }
    }
#pragma unroll
    for (int it = 0; it < 4; it++) {
        int idx = it * 256 + tid;
        int kk = idx >> 3, u4 = idx & 7;
        *(uint4*)(smem + CH + (kk * LDC + u4 * 8) * 2) =
            *(const uint4*)(Wch + kk * 64 + u4 * 8);
        *(uint4*)(smem + CL + (kk * LDC + u4 * 8) * 2) =
            *(const uint4*)(Wcl + kk * 64 + u4 * 8);
    }
    __syncthreads();

    int warp_m2 = wid & 3, warp_n2 = wid >> 2;
    float acc2[2][4][4];
#pragma unroll
    for (int i = 0; i < 2; i++)
#pragma unroll
        for (int j = 0; j < 4; j++)
#pragma unroll
            for (int k = 0; k < 4; k++) acc2[i][j][k] = 0.0f;

#pragma unroll
    for (int p = 0; p < 2; p++) {
        uint32_t bB = sb + (p ? CL : CH);
#pragma unroll
        for (int ks = 0; ks < 8; ks++) {
            uint32_t af[2][4], bf_[4][2];
#pragma unroll
            for (int mi = 0; mi < 2; mi++)
                LDSM_X4(af[mi], sb + UOFF + ((warp_m2 * 32 + mi * 16 + a_r) * LDA
                                             + ks * 16 + a_c8) * 2);
#pragma unroll
            for (int nj = 0; nj < 4; nj++)
                LDSM_X2T(bf_[nj], bB + ((ks * 16 + b_r) * LDC
                                        + warp_n2 * 32 + nj * 8) * 2);
#pragma unroll
            for (int mi = 0; mi < 2; mi++)
#pragma unroll
                for (int nj = 0; nj < 4; nj++)
                    MMA_F16(acc2[mi][nj], af[mi], bf_[nj]);
        }
    }

#pragma unroll
    for (int mi = 0; mi < 2; mi++)
#pragma unroll
        for (int nj = 0; nj < 4; nj++) {
            int c = warp_n2 * 32 + nj * 8 + q2;
            int r0 = m0 + warp_m2 * 32 + mi * 16 + g;
            if (r0 < nrows) {
                float2 o = {acc2[mi][nj][0], acc2[mi][nj][1]};
                *(float2*)(pzp + (size_t)r0 * 64 + c) = o;
            }
            int r1 = r0 + 8;
            if (r1 < nrows) {
                float2 o = {acc2[mi][nj][2], acc2[mi][nj][3]};
                *(float2*)(pzp + (size_t)r1 * 64 + c) = o;
            }
        }
}

#define SMEM_G0 (34816 * 2)      // 69632
#define SMEM_G1F 71680

// ---------------------------------------------------------------------------
// aggregation (warp per node), node range [base, nend)
// STREAM_OUT: use __stcs for output (evict-first; protects gather-source L2)
// ---------------------------------------------------------------------------
template <bool STREAM_OUT>
__global__ void __launch_bounds__(256)
agg128hh_kernel(const __half* __restrict__ p, const float* __restrict__ dis,
                const int* __restrict__ rowptr, const int* __restrict__ deg,
                const int* __restrict__ col, __half* __restrict__ out,
                int base, int nend) {
    int w = base + ((blockIdx.x * blockDim.x + threadIdx.x) >> 5);
    if (w >= nend) return;
    int lane = threadIdx.x & 31;
    const uint2* p2 = (const uint2*)p;
    int start = rowptr[w], d = deg[w];
    uint2 a = p2[(size_t)w * 32 + lane];
    float2 f0 = __half22float2(*(__half2*)&a.x);
    float2 f1 = __half22float2(*(__half2*)&a.y);
    float ax = f0.x, ay = f0.y, az = f1.x, aw = f1.y;

    int c0 = 0;
    for (; c0 + 32 <= d; c0 += 32) {
        int idx = col[start + c0 + lane];
#pragma unroll 8
        for (int j = 0; j < 32; j++) {
            int u = __shfl_sync(0xffffffffu, idx, j);
            uint2 v = p2[(size_t)u * 32 + lane];
            float2 g0 = __half22float2(*(__half2*)&v.x);
            float2 g1 = __half22float2(*(__half2*)&v.y);
            ax += g0.x; ay += g0.y; az += g1.x; aw += g1.y;
        }
    }
    int m = d - c0;
    if (m > 0) {
        int idx = (lane < m) ? col[start + c0 + lane] : 0;
        for (int j = 0; j < m; j++) {
            int u = __shfl_sync(0xffffffffu, idx, j);
            uint2 v = p2[(size_t)u * 32 + lane];
            float2 g0 = __half22float2(*(__half2*)&v.x);
            float2 g1 = __half22float2(*(__half2*)&v.y);
            ax += g0.x; ay += g0.y; az += g1.x; aw += g1.y;
        }
    }
    float s = dis[w];
    __half2 h0 = __floats2half2_rn(ax * s, ay * s);
    __half2 h1 = __floats2half2_rn(az * s, aw * s);
    uint2 o;
    o.x = *(uint32_t*)&h0; o.y = *(uint32_t*)&h1;
    if (STREAM_OUT)
        __stcs((uint2*)out + (size_t)w * 32 + lane, o);
    else
        ((uint2*)out)[(size_t)w * 32 + lane] = o;
}

// fp16 payload, 64-wide rows: final output fp32 + cbias
__global__ void __launch_bounds__(256)
agg64h_kernel(const uint32_t* __restrict__ p, const float* __restrict__ dis,
              const int* __restrict__ rowptr, const int* __restrict__ deg,
              const int* __restrict__ col, const float* __restrict__ cbias,
              float2* __restrict__ out, int n) {
    int w = (blockIdx.x * blockDim.x + threadIdx.x) >> 5;
    if (w >= n) return;
    int lane = threadIdx.x & 31;
    int start = rowptr[w], d = deg[w];
    uint32_t a = p[(size_t)w * 32 + lane];
    float2 f = __half22float2(*(__half2*)&a);
    float ax = f.x, ay = f.y;

    int c0 = 0;
    for (; c0 + 32 <= d; c0 += 32) {
        int idx = col[start + c0 + lane];
#pragma unroll 8
        for (int j = 0; j < 32; j++) {
            int u = __shfl_sync(0xffffffffu, idx, j);
            uint32_t v = p[(size_t)u * 32 + lane];
            float2 g = __half22float2(*(__half2*)&v);
            ax += g.x; ay += g.y;
        }
    }
    int m = d - c0;
    if (m > 0) {
        int idx = (lane < m) ? col[start + c0 + lane] : 0;
        for (int j = 0; j < m; j++) {
            int u = __shfl_sync(0xffffffffu, idx, j);
            uint32_t v = p[(size_t)u * 32 + lane];
            float2 g = __half22float2(*(__half2*)&v);
            ax += g.x; ay += g.y;
        }
    }
    float s = dis[w];
    float2 o = {ax * s + cbias[lane * 2], ay * s + cbias[lane * 2 + 1]};
    out[(size_t)w * 32 + lane] = o;
}

// ---------------------------------------------------------------------------
extern "C" void kernel_launch(void* const* d_in, const int* in_sizes, int n_in,
                              void* d_out, int out_size) {
    const float* x     = (const float*)d_in[0];
    const int*   ei    = (const int*)d_in[1];
    const float* W0    = (const float*)d_in[2];
    const float* b0    = (const float*)d_in[3];
    const float* W1    = (const float*)d_in[4];
    const float* b1    = (const float*)d_in[5];
    const float* W2    = (const float*)d_in[6];
    const float* b2    = (const float*)d_in[7];
    const float* gamma = (const float*)d_in[8];
    const float* beta  = (const float*)d_in[9];
    const float* Wf    = (const float*)d_in[10];
    const float* bf    = (const float*)d_in[11];
    float* out = (float*)d_out;

    const int N = in_sizes[0] / 128;
    const int E = in_sizes[1] / 2;
    const int* src = ei;
    const int* dst = ei + E;

    __half *pxh, *yh, *ph, *th, *pzh, *w0h, *w1h, *wch, *wcl;
    float *pzp, *wc, *cbias, *dis;
    int *deg, *rp, *cur, *col, *bsum;
    cudaGetSymbolAddress((void**)&pxh,   g_pxh);
    cudaGetSymbolAddress((void**)&yh,    g_yh);
    cudaGetSymbolAddress((void**)&ph,    g_ph);
    cudaGetSymbolAddress((void**)&th,    g_th);
    cudaGetSymbolAddress((void**)&pzp,   g_pzp);
    cudaGetSymbolAddress((void**)&pzh,   g_pzh);
    cudaGetSymbolAddress((void**)&wc,    g_wc);
    cudaGetSymbolAddress((void**)&w0h,   g_w0h);
    cudaGetSymbolAddress((void**)&w1h,   g_w1h);
    cudaGetSymbolAddress((void**)&wch,   g_wch);
    cudaGetSymbolAddress((void**)&wcl,   g_wcl);
    cudaGetSymbolAddress((void**)&cbias, g_cbias);
    cudaGetSymbolAddress((void**)&dis,   g_dis);
    cudaGetSymbolAddress((void**)&deg,   g_deg);
    cudaGetSymbolAddress((void**)&rp,    g_rowptr);
    cudaGetSymbolAddress((void**)&cur,   g_cursor);
    cudaGetSymbolAddress((void**)&col,   g_col);
    cudaGetSymbolAddress((void**)&bsum,  g_bsum);

    // 2 created streams + legacy default, 8 events (guard-safe envelope)
    static bool inited = false;
    static cudaStream_t st1, st2;
    static cudaEvent_t evRoot, evDis, evPre, evW, evY0, evY1, ev1, ev2;
    if (!inited) {
        cudaStreamCreateWithFlags(&st1, cudaStreamNonBlocking);
        cudaStreamCreateWithFlags(&st2, cudaStreamNonBlocking);
        cudaEventCreateWithFlags(&evRoot, cudaEventDisableTiming);
        cudaEventCreateWithFlags(&evDis, cudaEventDisableTiming);
        cudaEventCreateWithFlags(&evPre, cudaEventDisableTiming);
        cudaEventCreateWithFlags(&evW,  cudaEventDisableTiming);
        cudaEventCreateWithFlags(&evY0, cudaEventDisableTiming);
        cudaEventCreateWithFlags(&evY1, cudaEventDisableTiming);
        cudaEventCreateWithFlags(&ev1,  cudaEventDisableTiming);
        cudaEventCreateWithFlags(&ev2,  cudaEventDisableTiming);
        cudaFuncSetAttribute(tgemm1p_kernel<3>,
                             cudaFuncAttributeMaxDynamicSharedMemorySize, SMEM_G0);
        cudaFuncSetAttribute(gemm1f_kernel,
                             cudaFuncAttributeMaxDynamicSharedMemorySize, SMEM_G1F);
        inited = true;
    }

    const int TB = 256;
    int nB = (N + TB - 1) / TB;
    int e2B = (E / 2 + TB - 1) / TB + 1;
    int nbScan = (N + SCAN_B - 1) / SCAN_B;
    int aggB = (N * 32 + TB - 1) / TB;
    int gB = (N + 127) / 128;

    const int H = ((N / 2 + 127) / 128) * 128;
    int gB0 = H / 128;
    int gB1 = (N - H + 127) / 128;
    int aB0 = (H * 32 + TB - 1) / TB;
    int aB1 = ((N - H) * 32 + TB - 1) / TB;

    cudaStream_t s0 = 0;

    // --- capture fork for st1 (weights) ---
    zero_kernel<<<nB, TB, 0, s0>>>(deg, cur, N);
    cudaEventRecord(evRoot, s0);
    cudaStreamWaitEvent(st1, evRoot, 0);

    // --- weight folding + fp16 conversion on st1 ---
    wc_kernel<<<384, 64, 0, st1>>>(W2, Wf, wc);
    cbias_kernel<<<1, 64, 0, st1>>>(b2, Wf, bf, cbias);
    convs_kernel<<<(3 * 128 * 128 + 255) / 256, 256, 0, st1>>>(W0, w0h, 3 * 128 * 128);
    convs_kernel<<<(3 * 128 * 128 + 255) / 256, 256, 0, st1>>>(W1, w1h, 3 * 128 * 128);
    convh_kernel<<<(384 * 64 + 255) / 256, 256, 0, st1>>>(wc, wch, wcl, 384 * 64);
    cudaEventRecord(evW, st1);

    // --- graph prep on s0 ---
    count_kernel<<<e2B, TB, 0, s0>>>(dst, deg, E);
    scan1_kernel<<<nbScan, SCAN_B, 0, s0>>>(deg, rp, bsum, dis, N);
    cudaEventRecord(evDis, s0);

    cudaStreamWaitEvent(st2, evDis, 0);
    prescale_h_kernel<<<(N * 32 + TB - 1) / TB, TB, 0, st2>>>(
        (const float4*)x, dis, (uint2*)pxh, N * 32);
    cudaEventRecord(evPre, st2);

    scan2_kernel<<<1, 32, 0, s0>>>(bsum, nbScan);
    scan3_kernel<<<nB, TB, 0, s0>>>(rp, bsum, N);
    fill_kernel<<<e2B, TB, 0, s0>>>(src, dst, rp, cur, col, E);

    // --- agg_y in halves (yh cached: re-read by GEMM0 x3) ---
    cudaStreamWaitEvent(s0, evPre, 0);
    agg128hh_kernel<false><<<aB0, TB, 0, s0>>>(pxh, dis, rp, deg, col, yh, 0, H);
    cudaEventRecord(evY0, s0);
    agg128hh_kernel<false><<<aB1, TB, 0, s0>>>(pxh, dis, rp, deg, col, yh, H, N);
    cudaEventRecord(evY1, s0);

    // --- per-scale chains on {s0, st1, st2} ---
    cudaStreamWaitEvent(s0, evW, 0);
    cudaStreamWaitEvent(st2, evW, 0);
    cudaStream_t chain[3] = {s0, st1, st2};
    for (int s = 0; s < 3; s++) {
        cudaStream_t cs = chain[s];
        __half* ph_s = ph + (size_t)s * NN * 128;
        __half* t_s  = th + (size_t)s * NN * 128;
        float* pzp_s = pzp + (size_t)s * NN * 64;
        if (cs != s0) cudaStreamWaitEvent(cs, evY0, 0);
        tgemm1p_kernel<3><<<gB0, 256, SMEM_G0, cs>>>(
            yh, w0h + s * 16384, dis, b0 + s * 128,
            gamma + (s * 3 + 0) * 128, beta + (s * 3 + 0) * 128,
            ph_s, 0, N);
        if (cs != s0) cudaStreamWaitEvent(cs, evY1, 0);
        tgemm1p_kernel<3><<<gB1, 256, SMEM_G0, cs>>>(
            yh, w0h + s * 16384, dis, b0 + s * 128,
            gamma + (s * 3 + 0) * 128, beta + (s * 3 + 0) * 128,
            ph_s, H, N);
        // mid agg: t written with streaming stores (protect ph in L2)
        agg128hh_kernel<true><<<aggB, TB, 0, cs>>>(ph_s, dis, rp, deg, col, t_s, 0, N);
        gemm1f_kernel<<<gB, 256, SMEM_G1F, cs>>>(
            t_s, w1h + s * 16384, wch + s * 8192, wcl + s * 8192,
            b1 + s * 128, gamma + (s * 3 + 1) * 128, beta + (s * 3 + 1) * 128,
            pzp_s, N);
    }
    cudaEventRecord(ev1, st1);
    cudaEventRecord(ev2, st2);
    cudaStreamWaitEvent(s0, ev1, 0);
    cudaStreamWaitEvent(s0, ev2, 0);

    // --- sum partials + final aggregation ---
    pzsum_kernel<<<(N * 32 + TB - 1) / TB, TB, 0, s0>>>(
        pzp, pzp + (size_t)NN * 64, pzp + (size_t)2 * NN * 64, dis,
        (uint32_t*)pzh, N * 32);
    agg64h_kernel<<<aggB, TB, 0, s0>>>((const uint32_t*)pzh, dis, rp, deg, col,
                                       cbias, (float2*)out, N);
}

// round 15
// speedup vs baseline: 1.6010x; 1.0132x over previous
#include <cuda_runtime.h>
#include <cuda_fp16.h>
#include <cstdint>

#define NN 100000
#define EE 3200000
#define SCAN_B 512
#define NBLK_SCAN ((NN + SCAN_B - 1) / SCAN_B)

// -------- device scratch (no cudaMalloc allowed) --------
__device__ __half g_pxh[NN * 128];       // fp16 dis-prescaled x
__device__ __half g_yh[NN * 128];        // y = A_hat x (fp16)
__device__ __half g_ph[3][NN * 128];     // per-scale dis*LN(relu(...)) fp16
__device__ __half g_th[3][NN * 128];     // per-scale t_s (fp16)
__device__ float  g_pzp[3][NN * 64];     // per-scale tail partials (fp32)
__device__ __half g_pzh[NN * 64];        // fp16 tail (summed, dis-scaled)
__device__ float  g_wc[384 * 64];
__device__ __half g_w0h[3 * 128 * 128];
__device__ __half g_w1h[3 * 128 * 128];
__device__ __half g_wch[384 * 64], g_wcl[384 * 64];
__device__ float  g_cbias[64];
__device__ float  g_dis[NN];
__device__ int    g_deg[NN];
__device__ int    g_rowptr[NN];
__device__ int    g_rpcopy[NN];
__device__ int    g_col[EE];
__device__ int    g_bsum[NBLK_SCAN + 1];

// ---------------------------------------------------------------------------
// graph prep
// ---------------------------------------------------------------------------
__global__ void zero_kernel(int* deg, int n) {
    int i = blockIdx.x * blockDim.x + threadIdx.x;
    if (i < n) deg[i] = 0;
}

// 2 edges per thread
__global__ void count_kernel(const int* __restrict__ dst, int* __restrict__ deg, int e) {
    int i = (blockIdx.x * blockDim.x + threadIdx.x) * 2;
    if (i + 1 < e) {
        int2 d = *(const int2*)(dst + i);
        atomicAdd(&deg[d.x], 1);
        atomicAdd(&deg[d.y], 1);
    } else if (i < e) {
        atomicAdd(&deg[dst[i]], 1);
    }
}

// exclusive scan phase 1 + fused dis = rsqrt(deg+1)
__global__ void scan1_kernel(const int* __restrict__ deg, int* __restrict__ out,
                             int* __restrict__ bsum, float* __restrict__ dis, int n) {
    __shared__ int sh[SCAN_B];
    int tid = threadIdx.x;
    int i = blockIdx.x * SCAN_B + tid;
    int v = (i < n) ? deg[i] : 0;
    if (i < n) dis[i] = rsqrtf((float)v + 1.0f);
    sh[tid] = v;
    __syncthreads();
#pragma unroll
    for (int off = 1; off < SCAN_B; off <<= 1) {
        int t = (tid >= off) ? sh[tid - off] : 0;
        __syncthreads();
        sh[tid] += t;
        __syncthreads();
    }
    if (i < n) out[i] = sh[tid] - v;
    if (tid == SCAN_B - 1) bsum[blockIdx.x] = sh[tid];
}

__global__ void scan2_kernel(int* bsum, int nb) {
    if (threadIdx.x == 0 && blockIdx.x == 0) {
        int acc = 0;
        for (int i = 0; i < nb; i++) { int t = bsum[i]; bsum[i] = acc; acc += t; }
    }
}

// finalize rowptr and produce the fill cursor copy
__global__ void scan3_kernel(int* __restrict__ out, int* __restrict__ rpcopy,
                             const int* __restrict__ bsum, int n) {
    int i = blockIdx.x * blockDim.x + threadIdx.x;
    if (i < n) {
        int v = out[i] + bsum[i / SCAN_B];
        out[i] = v;
        rpcopy[i] = v;
    }
}

// 2 edges per thread; single atomic per edge (cursor IS the rowptr copy)
__global__ void fill_kernel(const int* __restrict__ src, const int* __restrict__ dst,
                            int* __restrict__ rpcopy, int* __restrict__ col, int e) {
    int i = (blockIdx.x * blockDim.x + threadIdx.x) * 2;
    if (i + 1 < e) {
        int2 d = *(const int2*)(dst + i);
        int2 s = *(const int2*)(src + i);
        col[atomicAdd(&rpcopy[d.x], 1)] = s.x;
        col[atomicAdd(&rpcopy[d.y], 1)] = s.y;
    } else if (i < e) {
        col[atomicAdd(&rpcopy[dst[i]], 1)] = src[i];
    }
}

// ---------------------------------------------------------------------------
// weight folding / conversion / prescale
// ---------------------------------------------------------------------------
__global__ void wc_kernel(const float* __restrict__ W2, const float* __restrict__ Wf,
                          float* __restrict__ Wc) {
    int r = blockIdx.x;
    int s = r >> 7, i = r & 127;
    int j = threadIdx.x;
    float acc = 0.0f;
#pragma unroll 8
    for (int k = 0; k < 64; k++)
        acc = fmaf(W2[(s * 128 + i) * 64 + k], Wf[(s * 64 + k) * 64 + j], acc);
    Wc[r * 64 + j] = acc;
}

__global__ void cbias_kernel(const float* __restrict__ b2, const float* __restrict__ Wf,
                             const float* __restrict__ bf, float* __restrict__ cb) {
    int j = threadIdx.x;
    float acc = bf[j];
#pragma unroll 8
    for (int r = 0; r < 192; r++) acc = fmaf(b2[r], Wf[r * 64 + j], acc);
    cb[j] = acc;
}

__global__ void convs_kernel(const float* __restrict__ W, __half* __restrict__ Wh, int n) {
    int i = blockIdx.x * blockDim.x + threadIdx.x;
    if (i < n) Wh[i] = __float2half_rn(W[i]);
}

__global__ void convh_kernel(const float* __restrict__ W, __half* __restrict__ Wh,
                             __half* __restrict__ Wl, int n) {
    int i = blockIdx.x * blockDim.x + threadIdx.x;
    if (i < n) {
        float w = W[i];
        __half h = __float2half_rn(w);
        Wh[i] = h;
        Wl[i] = __float2half_rn(w - __half2float(h));
    }
}

__global__ void prescale_h_kernel(const float4* __restrict__ x, const float* __restrict__ dis,
                                  uint2* __restrict__ px, int n4) {
    int i = blockIdx.x * blockDim.x + threadIdx.x;
    if (i < n4) {
        float s = dis[i >> 5];
        float4 v = x[i];
        __half2 h0 = __floats2half2_rn(v.x * s, v.y * s);
        __half2 h1 = __floats2half2_rn(v.z * s, v.w * s);
        uint2 u;
        u.x = *(uint32_t*)&h0; u.y = *(uint32_t*)&h1;
        px[i] = u;
    }
}

// pzh = fp16( dis[r] * (p0 + p1 + p2) ), 2 elems per thread
__global__ void pzsum_kernel(const float* __restrict__ p0, const float* __restrict__ p1,
                             const float* __restrict__ p2, const float* __restrict__ dis,
                             uint32_t* __restrict__ pzh, int n2) {
    int i = blockIdx.x * blockDim.x + threadIdx.x;
    if (i < n2) {
        float s = dis[i >> 5];
        float2 a = ((const float2*)p0)[i];
        float2 b = ((const float2*)p1)[i];
        float2 c = ((const float2*)p2)[i];
        __half2 h = __floats2half2_rn((a.x + b.x + c.x) * s, (a.y + b.y + c.y) * s);
        pzh[i] = *(uint32_t*)&h;
    }
}

// ---------------------------------------------------------------------------
// PTX helpers
// ---------------------------------------------------------------------------
__device__ __forceinline__ uint32_t smem_u32(const void* p) {
    uint32_t a;
    asm("{ .reg .u64 t; cvta.to.shared.u64 t, %1; cvt.u32.u64 %0, t; }"
        : "=r"(a) : "l"(p));
    return a;
}

#define LDSM_X4(r, addr)                                                      \
    asm volatile("ldmatrix.sync.aligned.m8n8.x4.shared.b16 {%0,%1,%2,%3}, [%4];" \
                 : "=r"((r)[0]), "=r"((r)[1]), "=r"((r)[2]), "=r"((r)[3])     \
                 : "r"(addr))

#define LDSM_X2T(r, addr)                                                     \
    asm volatile("ldmatrix.sync.aligned.m8n8.x2.trans.shared.b16 {%0,%1}, [%2];" \
                 : "=r"((r)[0]), "=r"((r)[1]) : "r"(addr))

#define MMA_F16(d, a, b)                                                      \
    asm volatile("mma.sync.aligned.m16n8k16.row.col.f32.f16.f16.f32 "         \
                 "{%0,%1,%2,%3}, {%4,%5,%6,%7}, {%8,%9}, {%0,%1,%2,%3};"      \
                 : "+f"((d)[0]), "+f"((d)[1]), "+f"((d)[2]), "+f"((d)[3])     \
                 : "r"((a)[0]), "r"((a)[1]), "r"((a)[2]), "r"((a)[3]),        \
                   "r"((b)[0]), "r"((b)[1]))

// ---------------------------------------------------------------------------
// GEMM template (single-pass weights), EPI3 = dis*LN(relu(.+b)) -> fp16
// ---------------------------------------------------------------------------
template <int EPI>
__global__ void __launch_bounds__(256)
tgemm1p_kernel(const __half* __restrict__ A, const __half* __restrict__ Wh,
               const float* __restrict__ dis, const float* __restrict__ bias,
               const float* __restrict__ gamma, const float* __restrict__ beta,
               __half* __restrict__ C, int rbase, int nrows) {
    constexpr int LDA = 136, LDB = 136;
    constexpr int WN = 4, WM = 2, WROWS = 64, MI = 4, NJ = 4;
    constexpr int ABYTES = 128 * LDA * 2;
    extern __shared__ char smem[];
    __shared__ float sh_bias[128], sh_g[128], sh_b[128];

    int tid = threadIdx.x, wid = tid >> 5, lane = tid & 31;
    int warp_m = wid % WM, warp_n = wid / WM;
    int m0 = rbase + blockIdx.x * 128;
    uint32_t sb = smem_u32(smem);

    if (tid < 128) {
        sh_bias[tid] = bias[tid];
        sh_g[tid] = gamma[tid];
        sh_b[tid] = beta[tid];
    }

    float acc[MI][NJ][4];
#pragma unroll
    for (int i = 0; i < MI; i++)
#pragma unroll
        for (int j = 0; j < NJ; j++)
#pragma unroll
            for (int k = 0; k < 4; k++) acc[i][j][k] = 0.0f;

    int a_r = lane & 15, a_c8 = (lane >> 4) * 8, b_r = lane & 15;

#pragma unroll
    for (int it = 0; it < 8; it++) {
        int idx = it * 256 + tid;
        int row = idx >> 4, u4 = idx & 15;
        int rg = m0 + row;
        uint4 v = make_uint4(0u, 0u, 0u, 0u);
        if (rg < nrows) v = *(const uint4*)(A + (size_t)rg * 128 + u4 * 8);
        *(uint4*)(smem + (row * LDA + u4 * 8) * 2) = v;
        *(uint4*)(smem + ABYTES + (row * LDB + u4 * 8) * 2) =
            *(const uint4*)(Wh + row * 128 + u4 * 8);
    }
    __syncthreads();

#pragma unroll
    for (int ks = 0; ks < 8; ks++) {
        uint32_t af[MI][4], bf_[NJ][2];
#pragma unroll
        for (int mi = 0; mi < MI; mi++)
            LDSM_X4(af[mi], sb + ((warp_m * WROWS + mi * 16 + a_r) * LDA
                                  + ks * 16 + a_c8) * 2);
#pragma unroll
        for (int nj = 0; nj < NJ; nj++)
            LDSM_X2T(bf_[nj], sb + ABYTES + ((ks * 16 + b_r) * LDB
                                             + warp_n * 32 + nj * 8) * 2);
#pragma unroll
        for (int mi = 0; mi < MI; mi++)
#pragma unroll
            for (int nj = 0; nj < NJ; nj++)
                MMA_F16(acc[mi][nj], af[mi], bf_[nj]);
    }

    int g = lane >> 2, q2 = (lane & 3) * 2;
    __syncthreads();
    float* Cs = (float*)smem;
#pragma unroll
    for (int mi = 0; mi < MI; mi++)
#pragma unroll
        for (int nj = 0; nj < NJ; nj++) {
            int rl = warp_m * WROWS + mi * 16 + g;
            int c = warp_n * 32 + nj * 8 + q2;
            Cs[rl * 129 + c]           = acc[mi][nj][0];
            Cs[rl * 129 + c + 1]       = acc[mi][nj][1];
            Cs[(rl + 8) * 129 + c]     = acc[mi][nj][2];
            Cs[(rl + 8) * 129 + c + 1] = acc[mi][nj][3];
        }
    __syncthreads();

    int row = tid >> 1, half = tid & 1;
    float v[64];
    float s1 = 0.0f, s2 = 0.0f;
#pragma unroll
    for (int j = 0; j < 64; j++) {
        float t = fmaxf(Cs[row * 129 + half * 64 + j] + sh_bias[half * 64 + j], 0.0f);
        v[j] = t; s1 += t; s2 += t * t;
    }
    s1 += __shfl_xor_sync(0xffffffffu, s1, 1);
    s2 += __shfl_xor_sync(0xffffffffu, s2, 1);
    float mu = s1 * (1.0f / 128.0f);
    float var = s2 * (1.0f / 128.0f) - mu * mu;
    float inv = rsqrtf(var + 1e-5f);

    int rg = m0 + row;
    if (rg >= nrows) return;
    float sc = (EPI == 3) ? dis[rg] : 1.0f;
    __half* outp = C + (size_t)rg * 128 + half * 64;
#pragma unroll
    for (int j = 0; j < 64; j += 8) {
        float o[8];
#pragma unroll
        for (int q = 0; q < 8; q++)
            o[q] = ((v[j + q] - mu) * inv * sh_g[half * 64 + j + q]
                    + sh_b[half * 64 + j + q]) * sc;
        __half2 h0 = __floats2half2_rn(o[0], o[1]);
        __half2 h1 = __floats2half2_rn(o[2], o[3]);
        __half2 h2 = __floats2half2_rn(o[4], o[5]);
        __half2 h3 = __floats2half2_rn(o[6], o[7]);
        uint4 u;
        u.x = *(uint32_t*)&h0; u.y = *(uint32_t*)&h1;
        u.z = *(uint32_t*)&h2; u.w = *(uint32_t*)&h3;
        *(uint4*)(outp + j) = u;
    }
}

// ---------------------------------------------------------------------------
// GEMM1 fused with tail: u = LN(relu(t@W1+b1)); pzp = u @ Wc (hi/lo, fp32 out)
// ---------------------------------------------------------------------------
__global__ void __launch_bounds__(256)
gemm1f_kernel(const __half* __restrict__ A, const __half* __restrict__ Wh,
              const __half* __restrict__ Wch, const __half* __restrict__ Wcl,
              const float* __restrict__ bias, const float* __restrict__ gamma,
              const float* __restrict__ beta,
              float* __restrict__ pzp, int nrows) {
    constexpr int LDA = 136, LDB = 136, LDC = 72;
    constexpr int WN = 4, WM = 2, WROWS = 64, MI = 4, NJ = 4;
    constexpr int ABYTES = 128 * LDA * 2;
    constexpr int UOFF = 0, CH = 34816, CL = 34816 + 18432;
    extern __shared__ char smem[];
    __shared__ float sh_bias[128], sh_g[128], sh_b[128];

    int tid = threadIdx.x, wid = tid >> 5, lane = tid & 31;
    int warp_m = wid % WM, warp_n = wid / WM;
    int m0 = blockIdx.x * 128;
    uint32_t sb = smem_u32(smem);

    if (tid < 128) {
        sh_bias[tid] = bias[tid];
        sh_g[tid] = gamma[tid];
        sh_b[tid] = beta[tid];
    }

    float acc[MI][NJ][4];
#pragma unroll
    for (int i = 0; i < MI; i++)
#pragma unroll
        for (int j = 0; j < NJ; j++)
#pragma unroll
            for (int k = 0; k < 4; k++) acc[i][j][k] = 0.0f;

    int a_r = lane & 15, a_c8 = (lane >> 4) * 8, b_r = lane & 15;

#pragma unroll
    for (int it = 0; it < 8; it++) {
        int idx = it * 256 + tid;
        int row = idx >> 4, u4 = idx & 15;
        int rg = m0 + row;
        uint4 v = make_uint4(0u, 0u, 0u, 0u);
        if (rg < nrows) v = *(const uint4*)(A + (size_t)rg * 128 + u4 * 8);
        *(uint4*)(smem + (row * LDA + u4 * 8) * 2) = v;
        *(uint4*)(smem + ABYTES + (row * LDB + u4 * 8) * 2) =
            *(const uint4*)(Wh + row * 128 + u4 * 8);
    }
    __syncthreads();

#pragma unroll
    for (int ks = 0; ks < 8; ks++) {
        uint32_t af[MI][4], bf_[NJ][2];
#pragma unroll
        for (int mi = 0; mi < MI; mi++)
            LDSM_X4(af[mi], sb + ((warp_m * WROWS + mi * 16 + a_r) * LDA
                                  + ks * 16 + a_c8) * 2);
#pragma unroll
        for (int nj = 0; nj < NJ; nj++)
            LDSM_X2T(bf_[nj], sb + ABYTES + ((ks * 16 + b_r) * LDB
                                             + warp_n * 32 + nj * 8) * 2);
#pragma unroll
        for (int mi = 0; mi < MI; mi++)
#pragma unroll
            for (int nj = 0; nj < NJ; nj++)
                MMA_F16(acc[mi][nj], af[mi], bf_[nj]);
    }

    int g = lane >> 2, q2 = (lane & 3) * 2;

    __syncthreads();
    float* Cs = (float*)smem;
#pragma unroll
    for (int mi = 0; mi < MI; mi++)
#pragma unroll
        for (int nj = 0; nj < NJ; nj++) {
            int rl = warp_m * WROWS + mi * 16 + g;
            int c = warp_n * 32 + nj * 8 + q2;
            Cs[rl * 129 + c]           = acc[mi][nj][0];
            Cs[rl * 129 + c + 1]       = acc[mi][nj][1];
            Cs[(rl + 8) * 129 + c]     = acc[mi][nj][2];
            Cs[(rl + 8) * 129 + c + 1] = acc[mi][nj][3];
        }
    __syncthreads();

    int row = tid >> 1, half = tid & 1;
    float v[64];
    float s1 = 0.0f, s2 = 0.0f;
#pragma unroll
    for (int j = 0; j < 64; j++) {
        float t = fmaxf(Cs[row * 129 + half * 64 + j] + sh_bias[half * 64 + j], 0.0f);
        v[j] = t; s1 += t; s2 += t * t;
    }
    s1 += __shfl_xor_sync(0xffffffffu, s1, 1);
    s2 += __shfl_xor_sync(0xffffffffu, s2, 1);
    float mu = s1 * (1.0f / 128.0f);
    float var = s2 * (1.0f / 128.0f) - mu * mu;
    float inv = rsqrtf(var + 1e-5f);

    __syncthreads();

    {
        __half* uP = (__half*)(smem + UOFF);
#pragma unroll
        for (int j = 0; j < 64; j += 8) {
            float o[8];
#pragma unroll
            for (int q = 0; q < 8; q++)
                o[q] = (v[j + q] - mu) * inv * sh_g[half * 64 + j + q]
                       + sh_b[half * 64 + j + q];
            __half2 h0 = __floats2half2_rn(o[0], o[1]);
            __half2 h1 = __floats2half2_rn(o[2], o[3]);
            __half2 h2 = __floats2half2_rn(o[4], o[5]);
            __half2 h3 = __floats2half2_rn(o[6], o[7]);
            uint4 u;
            u.x = *(uint32_t*)&h0; u.y = *(uint32_t*)&h1;
            u.z = *(uint32_t*)&h2; u.w = *(uint32_t*)&h3;
            *(uint4*)(uP + row * LDA + half * 64 + j) = u;
        }
    }
#pragma unroll
    for (int it = 0; it < 4; it++) {
        int idx = it * 256 + tid;
        int kk = idx >> 3, u4 = idx & 7;
        *(uint4*)(smem + CH + (kk * LDC + u4 * 8) * 2) =
            *(const uint4*)(Wch + kk * 64 + u4 * 8);
        *(uint4*)(smem + CL + (kk * LDC + u4 * 8) * 2) =
            *(const uint4*)(Wcl + kk * 64 + u4 * 8);
    }
    __syncthreads();

    int warp_m2 = wid & 3, warp_n2 = wid >> 2;
    float acc2[2][4][4];
#pragma unroll
    for (int i = 0; i < 2; i++)
#pragma unroll
        for (int j = 0; j < 4; j++)
#pragma unroll
            for (int k = 0; k < 4; k++) acc2[i][j][k] = 0.0f;

#pragma unroll
    for (int p = 0; p < 2; p++) {
        uint32_t bB = sb + (p ? CL : CH);
#pragma unroll
        for (int ks = 0; ks < 8; ks++) {
            uint32_t af[2][4], bf_[4][2];
#pragma unroll
            for (int mi = 0; mi < 2; mi++)
                LDSM_X4(af[mi], sb + UOFF + ((warp_m2 * 32 + mi * 16 + a_r) * LDA
                                             + ks * 16 + a_c8) * 2);
#pragma unroll
            for (int nj = 0; nj < 4; nj++)
                LDSM_X2T(bf_[nj], bB + ((ks * 16 + b_r) * LDC
                                        + warp_n2 * 32 + nj * 8) * 2);
#pragma unroll
            for (int mi = 0; mi < 2; mi++)
#pragma unroll
                for (int nj = 0; nj < 4; nj++)
                    MMA_F16(acc2[mi][nj], af[mi], bf_[nj]);
        }
    }

#pragma unroll
    for (int mi = 0; mi < 2; mi++)
#pragma unroll
        for (int nj = 0; nj < 4; nj++) {
            int c = warp_n2 * 32 + nj * 8 + q2;
            int r0 = m0 + warp_m2 * 32 + mi * 16 + g;
            if (r0 < nrows) {
                float2 o = {acc2[mi][nj][0], acc2[mi][nj][1]};
                *(float2*)(pzp + (size_t)r0 * 64 + c) = o;
            }
            int r1 = r0 + 8;
            if (r1 < nrows) {
                float2 o = {acc2[mi][nj][2], acc2[mi][nj][3]};
                *(float2*)(pzp + (size_t)r1 * 64 + c) = o;
            }
        }
}

#define SMEM_G0 (34816 * 2)
#define SMEM_G1F 71680

// ---------------------------------------------------------------------------
// aggregation (warp per node), node range [base, nend); unroll 16 (deep MLP)
// ---------------------------------------------------------------------------
template <bool STREAM_OUT>
__global__ void __launch_bounds__(256)
agg128hh_kernel(const __half* __restrict__ p, const float* __restrict__ dis,
                const int* __restrict__ rowptr, const int* __restrict__ deg,
                const int* __restrict__ col, __half* __restrict__ out,
                int base, int nend) {
    int w = base + ((blockIdx.x * blockDim.x + threadIdx.x) >> 5);
    if (w >= nend) return;
    int lane = threadIdx.x & 31;
    const uint2* p2 = (const uint2*)p;
    int start = rowptr[w], d = deg[w];
    uint2 a = p2[(size_t)w * 32 + lane];
    float2 f0 = __half22float2(*(__half2*)&a.x);
    float2 f1 = __half22float2(*(__half2*)&a.y);
    float ax = f0.x, ay = f0.y, az = f1.x, aw = f1.y;

    int c0 = 0;
    for (; c0 + 32 <= d; c0 += 32) {
        int idx = col[start + c0 + lane];
#pragma unroll 16
        for (int j = 0; j < 32; j++) {
            int u = __shfl_sync(0xffffffffu, idx, j);
            uint2 v = p2[(size_t)u * 32 + lane];
            float2 g0 = __half22float2(*(__half2*)&v.x);
            float2 g1 = __half22float2(*(__half2*)&v.y);
            ax += g0.x; ay += g0.y; az += g1.x; aw += g1.y;
        }
    }
    int m = d - c0;
    if (m > 0) {
        int idx = (lane < m) ? col[start + c0 + lane] : 0;
        for (int j = 0; j < m; j++) {
            int u = __shfl_sync(0xffffffffu, idx, j);
            uint2 v = p2[(size_t)u * 32 + lane];
            float2 g0 = __half22float2(*(__half2*)&v.x);
            float2 g1 = __half22float2(*(__half2*)&v.y);
            ax += g0.x; ay += g0.y; az += g1.x; aw += g1.y;
        }
    }
    float s = dis[w];
    __half2 h0 = __floats2half2_rn(ax * s, ay * s);
    __half2 h1 = __floats2half2_rn(az * s, aw * s);
    uint2 o;
    o.x = *(uint32_t*)&h0; o.y = *(uint32_t*)&h1;
    if (STREAM_OUT)
        __stcs((uint2*)out + (size_t)w * 32 + lane, o);
    else
        ((uint2*)out)[(size_t)w * 32 + lane] = o;
}

// fp16 payload, 64-wide rows: final output fp32 + cbias
__global__ void __launch_bounds__(256)
agg64h_kernel(const uint32_t* __restrict__ p, const float* __restrict__ dis,
              const int* __restrict__ rowptr, const int* __restrict__ deg,
              const int* __restrict__ col, const float* __restrict__ cbias,
              float2* __restrict__ out, int n) {
    int w = (blockIdx.x * blockDim.x + threadIdx.x) >> 5;
    if (w >= n) return;
    int lane = threadIdx.x & 31;
    int start = rowptr[w], d = deg[w];
    uint32_t a = p[(size_t)w * 32 + lane];
    float2 f = __half22float2(*(__half2*)&a);
    float ax = f.x, ay = f.y;

    int c0 = 0;
    for (; c0 + 32 <= d; c0 += 32) {
        int idx = col[start + c0 + lane];
#pragma unroll 16
        for (int j = 0; j < 32; j++) {
            int u = __shfl_sync(0xffffffffu, idx, j);
            uint32_t v = p[(size_t)u * 32 + lane];
            float2 g = __half22float2(*(__half2*)&v);
            ax += g.x; ay += g.y;
        }
    }
    int m = d - c0;
    if (m > 0) {
        int idx = (lane < m) ? col[start + c0 + lane] : 0;
        for (int j = 0; j < m; j++) {
            int u = __shfl_sync(0xffffffffu, idx, j);
            uint32_t v = p[(size_t)u * 32 + lane];
            float2 g = __half22float2(*(__half2*)&v);
            ax += g.x; ay += g.y;
        }
    }
    float s = dis[w];
    float2 o = {ax * s + cbias[lane * 2], ay * s + cbias[lane * 2 + 1]};
    out[(size_t)w * 32 + lane] = o;
}

// ---------------------------------------------------------------------------
extern "C" void kernel_launch(void* const* d_in, const int* in_sizes, int n_in,
                              void* d_out, int out_size) {
    const float* x     = (const float*)d_in[0];
    const int*   ei    = (const int*)d_in[1];
    const float* W0    = (const float*)d_in[2];
    const float* b0    = (const float*)d_in[3];
    const float* W1    = (const float*)d_in[4];
    const float* b1    = (const float*)d_in[5];
    const float* W2    = (const float*)d_in[6];
    const float* b2    = (const float*)d_in[7];
    const float* gamma = (const float*)d_in[8];
    const float* beta  = (const float*)d_in[9];
    const float* Wf    = (const float*)d_in[10];
    const float* bf    = (const float*)d_in[11];
    float* out = (float*)d_out;

    const int N = in_sizes[0] / 128;
    const int E = in_sizes[1] / 2;
    const int* src = ei;
    const int* dst = ei + E;

    __half *pxh, *yh, *ph, *th, *pzh, *w0h, *w1h, *wch, *wcl;
    float *pzp, *wc, *cbias, *dis;
    int *deg, *rp, *rpc, *col, *bsum;
    cudaGetSymbolAddress((void**)&pxh,   g_pxh);
    cudaGetSymbolAddress((void**)&yh,    g_yh);
    cudaGetSymbolAddress((void**)&ph,    g_ph);
    cudaGetSymbolAddress((void**)&th,    g_th);
    cudaGetSymbolAddress((void**)&pzp,   g_pzp);
    cudaGetSymbolAddress((void**)&pzh,   g_pzh);
    cudaGetSymbolAddress((void**)&wc,    g_wc);
    cudaGetSymbolAddress((void**)&w0h,   g_w0h);
    cudaGetSymbolAddress((void**)&w1h,   g_w1h);
    cudaGetSymbolAddress((void**)&wch,   g_wch);
    cudaGetSymbolAddress((void**)&wcl,   g_wcl);
    cudaGetSymbolAddress((void**)&cbias, g_cbias);
    cudaGetSymbolAddress((void**)&dis,   g_dis);
    cudaGetSymbolAddress((void**)&deg,   g_deg);
    cudaGetSymbolAddress((void**)&rp,    g_rowptr);
    cudaGetSymbolAddress((void**)&rpc,   g_rpcopy);
    cudaGetSymbolAddress((void**)&col,   g_col);
    cudaGetSymbolAddress((void**)&bsum,  g_bsum);

    // 2 created streams + legacy default, 8 events (guard-safe envelope)
    static bool inited = false;
    static cudaStream_t st1, st2;
    static cudaEvent_t evRoot, evDis, evPre, evW, evY0, evY1, ev1, ev2;
    if (!inited) {
        cudaStreamCreateWithFlags(&st1, cudaStreamNonBlocking);
        cudaStreamCreateWithFlags(&st2, cudaStreamNonBlocking);
        cudaEventCreateWithFlags(&evRoot, cudaEventDisableTiming);
        cudaEventCreateWithFlags(&evDis, cudaEventDisableTiming);
        cudaEventCreateWithFlags(&evPre, cudaEventDisableTiming);
        cudaEventCreateWithFlags(&evW,  cudaEventDisableTiming);
        cudaEventCreateWithFlags(&evY0, cudaEventDisableTiming);
        cudaEventCreateWithFlags(&evY1, cudaEventDisableTiming);
        cudaEventCreateWithFlags(&ev1,  cudaEventDisableTiming);
        cudaEventCreateWithFlags(&ev2,  cudaEventDisableTiming);
        cudaFuncSetAttribute(tgemm1p_kernel<3>,
                             cudaFuncAttributeMaxDynamicSharedMemorySize, SMEM_G0);
        cudaFuncSetAttribute(gemm1f_kernel,
                             cudaFuncAttributeMaxDynamicSharedMemorySize, SMEM_G1F);
        inited = true;
    }

    const int TB = 256;
    int nB = (N + TB - 1) / TB;
    int e2B = (E / 2 + TB - 1) / TB + 1;
    int nbScan = (N + SCAN_B - 1) / SCAN_B;
    int aggB = (N * 32 + TB - 1) / TB;
    int gB = (N + 127) / 128;

    const int H = ((N / 2 + 127) / 128) * 128;
    int gB0 = H / 128;
    int gB1 = (N - H + 127) / 128;
    int aB0 = (H * 32 + TB - 1) / TB;
    int aB1 = ((N - H) * 32 + TB - 1) / TB;

    cudaStream_t s0 = 0;

    // --- capture fork for st1 (weights) ---
    zero_kernel<<<nB, TB, 0, s0>>>(deg, N);
    cudaEventRecord(evRoot, s0);
    cudaStreamWaitEvent(st1, evRoot, 0);

    // --- weight folding + fp16 conversion on st1 ---
    wc_kernel<<<384, 64, 0, st1>>>(W2, Wf, wc);
    cbias_kernel<<<1, 64, 0, st1>>>(b2, Wf, bf, cbias);
    convs_kernel<<<(3 * 128 * 128 + 255) / 256, 256, 0, st1>>>(W0, w0h, 3 * 128 * 128);
    convs_kernel<<<(3 * 128 * 128 + 255) / 256, 256, 0, st1>>>(W1, w1h, 3 * 128 * 128);
    convh_kernel<<<(384 * 64 + 255) / 256, 256, 0, st1>>>(wc, wch, wcl, 384 * 64);
    cudaEventRecord(evW, st1);

    // --- graph prep on s0 ---
    count_kernel<<<e2B, TB, 0, s0>>>(dst, deg, E);
    scan1_kernel<<<nbScan, SCAN_B, 0, s0>>>(deg, rp, bsum, dis, N);
    cudaEventRecord(evDis, s0);

    cudaStreamWaitEvent(st2, evDis, 0);
    prescale_h_kernel<<<(N * 32 + TB - 1) / TB, TB, 0, st2>>>(
        (const float4*)x, dis, (uint2*)pxh, N * 32);
    cudaEventRecord(evPre, st2);

    scan2_kernel<<<1, 32, 0, s0>>>(bsum, nbScan);
    scan3_kernel<<<nB, TB, 0, s0>>>(rp, rpc, bsum, N);
    fill_kernel<<<e2B, TB, 0, s0>>>(src, dst, rpc, col, E);

    // --- agg_y in halves (yh cached: re-read by GEMM0 x3) ---
    cudaStreamWaitEvent(s0, evPre, 0);
    agg128hh_kernel<false><<<aB0, TB, 0, s0>>>(pxh, dis, rp, deg, col, yh, 0, H);
    cudaEventRecord(evY0, s0);
    agg128hh_kernel<false><<<aB1, TB, 0, s0>>>(pxh, dis, rp, deg, col, yh, H, N);
    cudaEventRecord(evY1, s0);

    // --- per-scale chains on {s0, st1, st2} ---
    cudaStreamWaitEvent(s0, evW, 0);
    cudaStreamWaitEvent(st2, evW, 0);
    cudaStream_t chain[3] = {s0, st1, st2};
    for (int s = 0; s < 3; s++) {
        cudaStream_t cs = chain[s];
        __half* ph_s = ph + (size_t)s * NN * 128;
        __half* t_s  = th + (size_t)s * NN * 128;
        float* pzp_s = pzp + (size_t)s * NN * 64;
        if (cs != s0) cudaStreamWaitEvent(cs, evY0, 0);
        tgemm1p_kernel<3><<<gB0, 256, SMEM_G0, cs>>>(
            yh, w0h + s * 16384, dis, b0 + s * 128,
            gamma + (s * 3 + 0) * 128, beta + (s * 3 + 0) * 128,
            ph_s, 0, N);
        if (cs != s0) cudaStreamWaitEvent(cs, evY1, 0);
        tgemm1p_kernel<3><<<gB1, 256, SMEM_G0, cs>>>(
            yh, w0h + s * 16384, dis, b0 + s * 128,
            gamma + (s * 3 + 0) * 128, beta + (s * 3 + 0) * 128,
            ph_s, H, N);
        agg128hh_kernel<true><<<aggB, TB, 0, cs>>>(ph_s, dis, rp, deg, col, t_s, 0, N);
        gemm1f_kernel<<<gB, 256, SMEM_G1F, cs>>>(
            t_s, w1h + s * 16384, wch + s * 8192, wcl + s * 8192,
            b1 + s * 128, gamma + (s * 3 + 1) * 128, beta + (s * 3 + 1) * 128,
            pzp_s, N);
    }
    cudaEventRecord(ev1, st1);
    cudaEventRecord(ev2, st2);
    cudaStreamWaitEvent(s0, ev1, 0);
    cudaStreamWaitEvent(s0, ev2, 0);

    // --- sum partials + final aggregation ---
    pzsum_kernel<<<(N * 32 + TB - 1) / TB, TB, 0, s0>>>(
        pzp, pzp + (size_t)NN * 64, pzp + (size_t)2 * NN * 64, dis,
        (uint32_t*)pzh, N * 32);
    agg64h_kernel<<<aggB, TB, 0, s0>>>((const uint32_t*)pzh, dis, rp, deg, col,
                                       cbias, (float2*)out, N);
}

// round 16
// speedup vs baseline: 1.6569x; 1.0349x over previous
#include <cuda_runtime.h>
#include <cuda_fp16.h>
#include <cstdint>

#define NN 100000
#define EE 3200000
#define SCAN_B 512
#define NBLK_SCAN ((NN + SCAN_B - 1) / SCAN_B)

// -------- device scratch (no cudaMalloc allowed) --------
__device__ __half g_pxh[NN * 128];       // fp16 dis-prescaled x
__device__ __half g_yh[NN * 128];        // y = A_hat x (fp16)
__device__ __half g_ph[3][NN * 128];     // per-scale dis*LN(relu(...)) fp16
__device__ __half g_th[3][NN * 128];     // per-scale t_s (fp16)
__device__ float  g_pzp[3][NN * 64];     // per-scale tail partials (fp32)
__device__ __half g_pzh[NN * 64];        // fp16 tail (summed, dis-scaled)
__device__ float  g_wc[384 * 64];
__device__ __half g_w0h[3 * 128 * 128];
__device__ __half g_w1h[3 * 128 * 128];
__device__ __half g_wch[384 * 64], g_wcl[384 * 64];
__device__ float  g_cbias[64];
__device__ float  g_dis[NN];
__device__ int    g_deg[NN];
__device__ int    g_rowptr[NN];
__device__ int    g_rpcopy[NN];
__device__ int    g_col[EE];
__device__ int    g_bsum[NBLK_SCAN + 1];

// ---------------------------------------------------------------------------
// graph prep
// ---------------------------------------------------------------------------
__global__ void zero_kernel(int* deg, int n) {
    int i = blockIdx.x * blockDim.x + threadIdx.x;
    if (i < n) deg[i] = 0;
}

__global__ void count_kernel(const int* __restrict__ dst, int* __restrict__ deg, int e) {
    int i = (blockIdx.x * blockDim.x + threadIdx.x) * 2;
    if (i + 1 < e) {
        int2 d = *(const int2*)(dst + i);
        atomicAdd(&deg[d.x], 1);
        atomicAdd(&deg[d.y], 1);
    } else if (i < e) {
        atomicAdd(&deg[dst[i]], 1);
    }
}

__global__ void scan1_kernel(const int* __restrict__ deg, int* __restrict__ out,
                             int* __restrict__ bsum, float* __restrict__ dis, int n) {
    __shared__ int sh[SCAN_B];
    int tid = threadIdx.x;
    int i = blockIdx.x * SCAN_B + tid;
    int v = (i < n) ? deg[i] : 0;
    if (i < n) dis[i] = rsqrtf((float)v + 1.0f);
    sh[tid] = v;
    __syncthreads();
#pragma unroll
    for (int off = 1; off < SCAN_B; off <<= 1) {
        int t = (tid >= off) ? sh[tid - off] : 0;
        __syncthreads();
        sh[tid] += t;
        __syncthreads();
    }
    if (i < n) out[i] = sh[tid] - v;
    if (tid == SCAN_B - 1) bsum[blockIdx.x] = sh[tid];
}

__global__ void scan2_kernel(int* bsum, int nb) {
    if (threadIdx.x == 0 && blockIdx.x == 0) {
        int acc = 0;
        for (int i = 0; i < nb; i++) { int t = bsum[i]; bsum[i] = acc; acc += t; }
    }
}

__global__ void scan3_kernel(int* __restrict__ out, int* __restrict__ rpcopy,
                             const int* __restrict__ bsum, int n) {
    int i = blockIdx.x * blockDim.x + threadIdx.x;
    if (i < n) {
        int v = out[i] + bsum[i / SCAN_B];
        out[i] = v;
        rpcopy[i] = v;
    }
}

__global__ void fill_kernel(const int* __restrict__ src, const int* __restrict__ dst,
                            int* __restrict__ rpcopy, int* __restrict__ col, int e) {
    int i = (blockIdx.x * blockDim.x + threadIdx.x) * 2;
    if (i + 1 < e) {
        int2 d = *(const int2*)(dst + i);
        int2 s = *(const int2*)(src + i);
        col[atomicAdd(&rpcopy[d.x], 1)] = s.x;
        col[atomicAdd(&rpcopy[d.y], 1)] = s.y;
    } else if (i < e) {
        col[atomicAdd(&rpcopy[dst[i]], 1)] = src[i];
    }
}

// ---------------------------------------------------------------------------
// weight folding / conversion / prescale
// ---------------------------------------------------------------------------
__global__ void wc_kernel(const float* __restrict__ W2, const float* __restrict__ Wf,
                          float* __restrict__ Wc) {
    int r = blockIdx.x;
    int s = r >> 7, i = r & 127;
    int j = threadIdx.x;
    float acc = 0.0f;
#pragma unroll 8
    for (int k = 0; k < 64; k++)
        acc = fmaf(W2[(s * 128 + i) * 64 + k], Wf[(s * 64 + k) * 64 + j], acc);
    Wc[r * 64 + j] = acc;
}

__global__ void cbias_kernel(const float* __restrict__ b2, const float* __restrict__ Wf,
                             const float* __restrict__ bf, float* __restrict__ cb) {
    int j = threadIdx.x;
    float acc = bf[j];
#pragma unroll 8
    for (int r = 0; r < 192; r++) acc = fmaf(b2[r], Wf[r * 64 + j], acc);
    cb[j] = acc;
}

__global__ void convs_kernel(const float* __restrict__ W, __half* __restrict__ Wh, int n) {
    int i = blockIdx.x * blockDim.x + threadIdx.x;
    if (i < n) Wh[i] = __float2half_rn(W[i]);
}

__global__ void convh_kernel(const float* __restrict__ W, __half* __restrict__ Wh,
                             __half* __restrict__ Wl, int n) {
    int i = blockIdx.x * blockDim.x + threadIdx.x;
    if (i < n) {
        float w = W[i];
        __half h = __float2half_rn(w);
        Wh[i] = h;
        Wl[i] = __float2half_rn(w - __half2float(h));
    }
}

__global__ void prescale_h_kernel(const float4* __restrict__ x, const float* __restrict__ dis,
                                  uint2* __restrict__ px, int n4) {
    int i = blockIdx.x * blockDim.x + threadIdx.x;
    if (i < n4) {
        float s = dis[i >> 5];
        float4 v = x[i];
        __half2 h0 = __floats2half2_rn(v.x * s, v.y * s);
        __half2 h1 = __floats2half2_rn(v.z * s, v.w * s);
        uint2 u;
        u.x = *(uint32_t*)&h0; u.y = *(uint32_t*)&h1;
        px[i] = u;
    }
}

__global__ void pzsum_kernel(const float* __restrict__ p0, const float* __restrict__ p1,
                             const float* __restrict__ p2, const float* __restrict__ dis,
                             uint32_t* __restrict__ pzh, int n2) {
    int i = blockIdx.x * blockDim.x + threadIdx.x;
    if (i < n2) {
        float s = dis[i >> 5];
        float2 a = ((const float2*)p0)[i];
        float2 b = ((const float2*)p1)[i];
        float2 c = ((const float2*)p2)[i];
        __half2 h = __floats2half2_rn((a.x + b.x + c.x) * s, (a.y + b.y + c.y) * s);
        pzh[i] = *(uint32_t*)&h;
    }
}

// ---------------------------------------------------------------------------
// PTX helpers
// ---------------------------------------------------------------------------
__device__ __forceinline__ uint32_t smem_u32(const void* p) {
    uint32_t a;
    asm("{ .reg .u64 t; cvta.to.shared.u64 t, %1; cvt.u32.u64 %0, t; }"
        : "=r"(a) : "l"(p));
    return a;
}

#define LDSM_X4(r, addr)                                                      \
    asm volatile("ldmatrix.sync.aligned.m8n8.x4.shared.b16 {%0,%1,%2,%3}, [%4];" \
                 : "=r"((r)[0]), "=r"((r)[1]), "=r"((r)[2]), "=r"((r)[3])     \
                 : "r"(addr))

#define LDSM_X2T(r, addr)                                                     \
    asm volatile("ldmatrix.sync.aligned.m8n8.x2.trans.shared.b16 {%0,%1}, [%2];" \
                 : "=r"((r)[0]), "=r"((r)[1]) : "r"(addr))

#define MMA_F16(d, a, b)                                                      \
    asm volatile("mma.sync.aligned.m16n8k16.row.col.f32.f16.f16.f32 "         \
                 "{%0,%1,%2,%3}, {%4,%5,%6,%7}, {%8,%9}, {%0,%1,%2,%3};"      \
                 : "+f"((d)[0]), "+f"((d)[1]), "+f"((d)[2]), "+f"((d)[3])     \
                 : "r"((a)[0]), "r"((a)[1]), "r"((a)[2]), "r"((a)[3]),        \
                   "r"((b)[0]), "r"((b)[1]))

// ---------------------------------------------------------------------------
// GEMM template (single-pass weights), EPI3 = dis*LN(relu(.+b)) -> fp16
// ---------------------------------------------------------------------------
template <int EPI>
__global__ void __launch_bounds__(256)
tgemm1p_kernel(const __half* __restrict__ A, const __half* __restrict__ Wh,
               const float* __restrict__ dis, const float* __restrict__ bias,
               const float* __restrict__ gamma, const float* __restrict__ beta,
               __half* __restrict__ C, int rbase, int nrows) {
    constexpr int LDA = 136, LDB = 136;
    constexpr int WN = 4, WM = 2, WROWS = 64, MI = 4, NJ = 4;
    constexpr int ABYTES = 128 * LDA * 2;
    extern __shared__ char smem[];
    __shared__ float sh_bias[128], sh_g[128], sh_b[128];

    int tid = threadIdx.x, wid = tid >> 5, lane = tid & 31;
    int warp_m = wid % WM, warp_n = wid / WM;
    int m0 = rbase + blockIdx.x * 128;
    uint32_t sb = smem_u32(smem);

    if (tid < 128) {
        sh_bias[tid] = bias[tid];
        sh_g[tid] = gamma[tid];
        sh_b[tid] = beta[tid];
    }

    float acc[MI][NJ][4];
#pragma unroll
    for (int i = 0; i < MI; i++)
#pragma unroll
        for (int j = 0; j < NJ; j++)
#pragma unroll
            for (int k = 0; k < 4; k++) acc[i][j][k] = 0.0f;

    int a_r = lane & 15, a_c8 = (lane >> 4) * 8, b_r = lane & 15;

#pragma unroll
    for (int it = 0; it < 8; it++) {
        int idx = it * 256 + tid;
        int row = idx >> 4, u4 = idx & 15;
        int rg = m0 + row;
        uint4 v = make_uint4(0u, 0u, 0u, 0u);
        if (rg < nrows) v = *(const uint4*)(A + (size_t)rg * 128 + u4 * 8);
        *(uint4*)(smem + (row * LDA + u4 * 8) * 2) = v;
        *(uint4*)(smem + ABYTES + (row * LDB + u4 * 8) * 2) =
            *(const uint4*)(Wh + row * 128 + u4 * 8);
    }
    __syncthreads();

#pragma unroll
    for (int ks = 0; ks < 8; ks++) {
        uint32_t af[MI][4], bf_[NJ][2];
#pragma unroll
        for (int mi = 0; mi < MI; mi++)
            LDSM_X4(af[mi], sb + ((warp_m * WROWS + mi * 16 + a_r) * LDA
                                  + ks * 16 + a_c8) * 2);
#pragma unroll
        for (int nj = 0; nj < NJ; nj++)
            LDSM_X2T(bf_[nj], sb + ABYTES + ((ks * 16 + b_r) * LDB
                                             + warp_n * 32 + nj * 8) * 2);
#pragma unroll
        for (int mi = 0; mi < MI; mi++)
#pragma unroll
            for (int nj = 0; nj < NJ; nj++)
                MMA_F16(acc[mi][nj], af[mi], bf_[nj]);
    }

    int g = lane >> 2, q2 = (lane & 3) * 2;
    __syncthreads();
    float* Cs = (float*)smem;
#pragma unroll
    for (int mi = 0; mi < MI; mi++)
#pragma unroll
        for (int nj = 0; nj < NJ; nj++) {
            int rl = warp_m * WROWS + mi * 16 + g;
            int c = warp_n * 32 + nj * 8 + q2;
            Cs[rl * 129 + c]           = acc[mi][nj][0];
            Cs[rl * 129 + c + 1]       = acc[mi][nj][1];
            Cs[(rl + 8) * 129 + c]     = acc[mi][nj][2];
            Cs[(rl + 8) * 129 + c + 1] = acc[mi][nj][3];
        }
    __syncthreads();

    int row = tid >> 1, half = tid & 1;
    float v[64];
    float s1 = 0.0f, s2 = 0.0f;
#pragma unroll
    for (int j = 0; j < 64; j++) {
        float t = fmaxf(Cs[row * 129 + half * 64 + j] + sh_bias[half * 64 + j], 0.0f);
        v[j] = t; s1 += t; s2 += t * t;
    }
    s1 += __shfl_xor_sync(0xffffffffu, s1, 1);
    s2 += __shfl_xor_sync(0xffffffffu, s2, 1);
    float mu = s1 * (1.0f / 128.0f);
    float var = s2 * (1.0f / 128.0f) - mu * mu;
    float inv = rsqrtf(var + 1e-5f);

    int rg = m0 + row;
    if (rg >= nrows) return;
    float sc = (EPI == 3) ? dis[rg] : 1.0f;
    __half* outp = C + (size_t)rg * 128 + half * 64;
#pragma unroll
    for (int j = 0; j < 64; j += 8) {
        float o[8];
#pragma unroll
        for (int q = 0; q < 8; q++)
            o[q] = ((v[j + q] - mu) * inv * sh_g[half * 64 + j + q]
                    + sh_b[half * 64 + j + q]) * sc;
        __half2 h0 = __floats2half2_rn(o[0], o[1]);
        __half2 h1 = __floats2half2_rn(o[2], o[3]);
        __half2 h2 = __floats2half2_rn(o[4], o[5]);
        __half2 h3 = __floats2half2_rn(o[6], o[7]);
        uint4 u;
        u.x = *(uint32_t*)&h0; u.y = *(uint32_t*)&h1;
        u.z = *(uint32_t*)&h2; u.w = *(uint32_t*)&h3;
        *(uint4*)(outp + j) = u;
    }
}

// ---------------------------------------------------------------------------
// GEMM1 fused with tail: u = LN(relu(t@W1+b1)); pzp = u @ Wc (hi/lo, fp32 out)
// ---------------------------------------------------------------------------
__global__ void __launch_bounds__(256)
gemm1f_kernel(const __half* __restrict__ A, const __half* __restrict__ Wh,
              const __half* __restrict__ Wch, const __half* __restrict__ Wcl,
              const float* __restrict__ bias, const float* __restrict__ gamma,
              const float* __restrict__ beta,
              float* __restrict__ pzp, int nrows) {
    constexpr int LDA = 136, LDB = 136, LDC = 72;
    constexpr int WN = 4, WM = 2, WROWS = 64, MI = 4, NJ = 4;
    constexpr int ABYTES = 128 * LDA * 2;
    constexpr int UOFF = 0, CH = 34816, CL = 34816 + 18432;
    extern __shared__ char smem[];
    __shared__ float sh_bias[128], sh_g[128], sh_b[128];

    int tid = threadIdx.x, wid = tid >> 5, lane = tid & 31;
    int warp_m = wid % WM, warp_n = wid / WM;
    int m0 = blockIdx.x * 128;
    uint32_t sb = smem_u32(smem);

    if (tid < 128) {
        sh_bias[tid] = bias[tid];
        sh_g[tid] = gamma[tid];
        sh_b[tid] = beta[tid];
    }

    float acc[MI][NJ][4];
#pragma unroll
    for (int i = 0; i < MI; i++)
#pragma unroll
        for (int j = 0; j < NJ; j++)
#pragma unroll
            for (int k = 0; k < 4; k++) acc[i][j][k] = 0.0f;

    int a_r = lane & 15, a_c8 = (lane >> 4) * 8, b_r = lane & 15;

#pragma unroll
    for (int it = 0; it < 8; it++) {
        int idx = it * 256 + tid;
        int row = idx >> 4, u4 = idx & 15;
        int rg = m0 + row;
        uint4 v = make_uint4(0u, 0u, 0u, 0u);
        if (rg < nrows) v = *(const uint4*)(A + (size_t)rg * 128 + u4 * 8);
        *(uint4*)(smem + (row * LDA + u4 * 8) * 2) = v;
        *(uint4*)(smem + ABYTES + (row * LDB + u4 * 8) * 2) =
            *(const uint4*)(Wh + row * 128 + u4 * 8);
    }
    __syncthreads();

#pragma unroll
    for (int ks = 0; ks < 8; ks++) {
        uint32_t af[MI][4], bf_[NJ][2];
#pragma unroll
        for (int mi = 0; mi < MI; mi++)
            LDSM_X4(af[mi], sb + ((warp_m * WROWS + mi * 16 + a_r) * LDA
                                  + ks * 16 + a_c8) * 2);
#pragma unroll
        for (int nj = 0; nj < NJ; nj++)
            LDSM_X2T(bf_[nj], sb + ABYTES + ((ks * 16 + b_r) * LDB
                                             + warp_n * 32 + nj * 8) * 2);
#pragma unroll
        for (int mi = 0; mi < MI; mi++)
#pragma unroll
            for (int nj = 0; nj < NJ; nj++)
                MMA_F16(acc[mi][nj], af[mi], bf_[nj]);
    }

    int g = lane >> 2, q2 = (lane & 3) * 2;

    __syncthreads();
    float* Cs = (float*)smem;
#pragma unroll
    for (int mi = 0; mi < MI; mi++)
#pragma unroll
        for (int nj = 0; nj < NJ; nj++) {
            int rl = warp_m * WROWS + mi * 16 + g;
            int c = warp_n * 32 + nj * 8 + q2;
            Cs[rl * 129 + c]           = acc[mi][nj][0];
            Cs[rl * 129 + c + 1]       = acc[mi][nj][1];
            Cs[(rl + 8) * 129 + c]     = acc[mi][nj][2];
            Cs[(rl + 8) * 129 + c + 1] = acc[mi][nj][3];
        }
    __syncthreads();

    int row = tid >> 1, half = tid & 1;
    float v[64];
    float s1 = 0.0f, s2 = 0.0f;
#pragma unroll
    for (int j = 0; j < 64; j++) {
        float t = fmaxf(Cs[row * 129 + half * 64 + j] + sh_bias[half * 64 + j], 0.0f);
        v[j] = t; s1 += t; s2 += t * t;
    }
    s1 += __shfl_xor_sync(0xffffffffu, s1, 1);
    s2 += __shfl_xor_sync(0xffffffffu, s2, 1);
    float mu = s1 * (1.0f / 128.0f);
    float var = s2 * (1.0f / 128.0f) - mu * mu;
    float inv = rsqrtf(var + 1e-5f);

    __syncthreads();

    {
        __half* uP = (__half*)(smem + UOFF);
#pragma unroll
        for (int j = 0; j < 64; j += 8) {
            float o[8];
#pragma unroll
            for (int q = 0; q < 8; q++)
                o[q] = (v[j + q] - mu) * inv * sh_g[half * 64 + j + q]
                       + sh_b[half * 64 + j + q];
            __half2 h0 = __floats2half2_rn(o[0], o[1]);
            __half2 h1 = __floats2half2_rn(o[2], o[3]);
            __half2 h2 = __floats2half2_rn(o[4], o[5]);
            __half2 h3 = __floats2half2_rn(o[6], o[7]);
            uint4 u;
            u.x = *(uint32_t*)&h0; u.y = *(uint32_t*)&h1;
            u.z = *(uint32_t*)&h2; u.w = *(uint32_t*)&h3;
            *(uint4*)(uP + row * LDA + half * 64 + j) = u;
        }
    }
#pragma unroll
    for (int it = 0; it < 4; it++) {
        int idx = it * 256 + tid;
        int kk = idx >> 3, u4 = idx & 7;
        *(uint4*)(smem + CH + (kk * LDC + u4 * 8) * 2) =
            *(const uint4*)(Wch + kk * 64 + u4 * 8);
        *(uint4*)(smem + CL + (kk * LDC + u4 * 8) * 2) =
            *(const uint4*)(Wcl + kk * 64 + u4 * 8);
    }
    __syncthreads();

    int warp_m2 = wid & 3, warp_n2 = wid >> 2;
    float acc2[2][4][4];
#pragma unroll
    for (int i = 0; i < 2; i++)
#pragma unroll
        for (int j = 0; j < 4; j++)
#pragma unroll
            for (int k = 0; k < 4; k++) acc2[i][j][k] = 0.0f;

#pragma unroll
    for (int p = 0; p < 2; p++) {
        uint32_t bB = sb + (p ? CL : CH);
#pragma unroll
        for (int ks = 0; ks < 8; ks++) {
            uint32_t af[2][4], bf_[4][2];
#pragma unroll
            for (int mi = 0; mi < 2; mi++)
                LDSM_X4(af[mi], sb + UOFF + ((warp_m2 * 32 + mi * 16 + a_r) * LDA
                                             + ks * 16 + a_c8) * 2);
#pragma unroll
            for (int nj = 0; nj < 4; nj++)
                LDSM_X2T(bf_[nj], bB + ((ks * 16 + b_r) * LDC
                                        + warp_n2 * 32 + nj * 8) * 2);
#pragma unroll
            for (int mi = 0; mi < 2; mi++)
#pragma unroll
                for (int nj = 0; nj < 4; nj++)
                    MMA_F16(acc2[mi][nj], af[mi], bf_[nj]);
        }
    }

#pragma unroll
    for (int mi = 0; mi < 2; mi++)
#pragma unroll
        for (int nj = 0; nj < 4; nj++) {
            int c = warp_n2 * 32 + nj * 8 + q2;
            int r0 = m0 + warp_m2 * 32 + mi * 16 + g;
            if (r0 < nrows) {
                float2 o = {acc2[mi][nj][0], acc2[mi][nj][1]};
                *(float2*)(pzp + (size_t)r0 * 64 + c) = o;
            }
            int r1 = r0 + 8;
            if (r1 < nrows) {
                float2 o = {acc2[mi][nj][2], acc2[mi][nj][3]};
                *(float2*)(pzp + (size_t)r1 * 64 + c) = o;
            }
        }
}

#define SMEM_G0 (34816 * 2)
#define SMEM_G1F 71680

// ---------------------------------------------------------------------------
// single-buffer aggregation (warp per node), fp16 in/out, 32-bit offsets
// ---------------------------------------------------------------------------
__global__ void __launch_bounds__(256)
agg128hh_kernel(const __half* __restrict__ p, const float* __restrict__ dis,
                const int* __restrict__ rowptr, const int* __restrict__ deg,
                const int* __restrict__ col, __half* __restrict__ out,
                int base, int nend) {
    int w = base + ((blockIdx.x * blockDim.x + threadIdx.x) >> 5);
    if (w >= nend) return;
    int lane = threadIdx.x & 31;
    const uint2* p2 = (const uint2*)p;
    int start = rowptr[w], d = deg[w];
    uint2 a = p2[(uint32_t)w * 32u + lane];
    float2 f0 = __half22float2(*(__half2*)&a.x);
    float2 f1 = __half22float2(*(__half2*)&a.y);
    float ax = f0.x, ay = f0.y, az = f1.x, aw = f1.y;

    int c0 = 0;
    for (; c0 + 32 <= d; c0 += 32) {
        int idx = col[start + c0 + lane];
#pragma unroll 16
        for (int j = 0; j < 32; j++) {
            uint32_t u = (uint32_t)__shfl_sync(0xffffffffu, idx, j);
            uint2 v = p2[u * 32u + lane];
            float2 g0 = __half22float2(*(__half2*)&v.x);
            float2 g1 = __half22float2(*(__half2*)&v.y);
            ax += g0.x; ay += g0.y; az += g1.x; aw += g1.y;
        }
    }
    int m = d - c0;
    if (m > 0) {
        int idx = (lane < m) ? col[start + c0 + lane] : 0;
        for (int j = 0; j < m; j++) {
            uint32_t u = (uint32_t)__shfl_sync(0xffffffffu, idx, j);
            uint2 v = p2[u * 32u + lane];
            float2 g0 = __half22float2(*(__half2*)&v.x);
            float2 g1 = __half22float2(*(__half2*)&v.y);
            ax += g0.x; ay += g0.y; az += g1.x; aw += g1.y;
        }
    }
    float s = dis[w];
    __half2 h0 = __floats2half2_rn(ax * s, ay * s);
    __half2 h1 = __floats2half2_rn(az * s, aw * s);
    uint2 o;
    o.x = *(uint32_t*)&h0; o.y = *(uint32_t*)&h1;
    ((uint2*)out)[(uint32_t)w * 32u + lane] = o;
}

// merged 3-scale mid aggregation: one col pass, 3x uint2 gathers per index,
// streaming stores for t0/t1/t2
__global__ void __launch_bounds__(256)
agg384h_kernel(const __half* __restrict__ ph0, const float* __restrict__ dis,
               const int* __restrict__ rowptr, const int* __restrict__ deg,
               const int* __restrict__ col, __half* __restrict__ th0, int n) {
    int w = (blockIdx.x * blockDim.x + threadIdx.x) >> 5;
    if (w >= n) return;
    int lane = threadIdx.x & 31;
    const uint2* q0 = (const uint2*)ph0;
    const uint2* q1 = q0 + (size_t)NN * 32;
    const uint2* q2 = q1 + (size_t)NN * 32;
    int start = rowptr[w], d = deg[w];

    float acc[12];
    {
        uint32_t soff = (uint32_t)w * 32u + lane;
        uint2 a0 = q0[soff], a1 = q1[soff], a2 = q2[soff];
        float2 f;
        f = __half22float2(*(__half2*)&a0.x); acc[0] = f.x;  acc[1] = f.y;
        f = __half22float2(*(__half2*)&a0.y); acc[2] = f.x;  acc[3] = f.y;
        f = __half22float2(*(__half2*)&a1.x); acc[4] = f.x;  acc[5] = f.y;
        f = __half22float2(*(__half2*)&a1.y); acc[6] = f.x;  acc[7] = f.y;
        f = __half22float2(*(__half2*)&a2.x); acc[8] = f.x;  acc[9] = f.y;
        f = __half22float2(*(__half2*)&a2.y); acc[10] = f.x; acc[11] = f.y;
    }

    int c0 = 0;
    for (; c0 + 32 <= d; c0 += 32) {
        int idx = col[start + c0 + lane];
#pragma unroll 8
        for (int j = 0; j < 32; j++) {
            uint32_t u = (uint32_t)__shfl_sync(0xffffffffu, idx, j);
            uint32_t off = u * 32u + lane;
            uint2 v0 = q0[off], v1 = q1[off], v2 = q2[off];
            float2 f;
            f = __half22float2(*(__half2*)&v0.x); acc[0] += f.x;  acc[1] += f.y;
            f = __half22float2(*(__half2*)&v0.y); acc[2] += f.x;  acc[3] += f.y;
            f = __half22float2(*(__half2*)&v1.x); acc[4] += f.x;  acc[5] += f.y;
            f = __half22float2(*(__half2*)&v1.y); acc[6] += f.x;  acc[7] += f.y;
            f = __half22float2(*(__half2*)&v2.x); acc[8] += f.x;  acc[9] += f.y;
            f = __half22float2(*(__half2*)&v2.y); acc[10] += f.x; acc[11] += f.y;
        }
    }
    int m = d - c0;
    if (m > 0) {
        int idx = (lane < m) ? col[start + c0 + lane] : 0;
        for (int j = 0; j < m; j++) {
            uint32_t u = (uint32_t)__shfl_sync(0xffffffffu, idx, j);
            uint32_t off = u * 32u + lane;
            uint2 v0 = q0[off], v1 = q1[off], v2 = q2[off];
            float2 f;
            f = __half22float2(*(__half2*)&v0.x); acc[0] += f.x;  acc[1] += f.y;
            f = __half22float2(*(__half2*)&v0.y); acc[2] += f.x;  acc[3] += f.y;
            f = __half22float2(*(__half2*)&v1.x); acc[4] += f.x;  acc[5] += f.y;
            f = __half22float2(*(__half2*)&v1.y); acc[6] += f.x;  acc[7] += f.y;
            f = __half22float2(*(__half2*)&v2.x); acc[8] += f.x;  acc[9] += f.y;
            f = __half22float2(*(__half2*)&v2.y); acc[10] += f.x; acc[11] += f.y;
        }
    }

    float s = dis[w];
    uint2* t0 = (uint2*)th0;
    uint2* t1 = t0 + (size_t)NN * 32;
    uint2* t2 = t1 + (size_t)NN * 32;
    uint32_t ooff = (uint32_t)w * 32u + lane;
    uint2 o;
    __half2 h0, h1;
    h0 = __floats2half2_rn(acc[0] * s, acc[1] * s);
    h1 = __floats2half2_rn(acc[2] * s, acc[3] * s);
    o.x = *(uint32_t*)&h0; o.y = *(uint32_t*)&h1;
    __stcs(t0 + ooff, o);
    h0 = __floats2half2_rn(acc[4] * s, acc[5] * s);
    h1 = __floats2half2_rn(acc[6] * s, acc[7] * s);
    o.x = *(uint32_t*)&h0; o.y = *(uint32_t*)&h1;
    __stcs(t1 + ooff, o);
    h0 = __floats2half2_rn(acc[8] * s, acc[9] * s);
    h1 = __floats2half2_rn(acc[10] * s, acc[11] * s);
    o.x = *(uint32_t*)&h0; o.y = *(uint32_t*)&h1;
    __stcs(t2 + ooff, o);
}

// fp16 payload, 64-wide rows: final output fp32 + cbias
__global__ void __launch_bounds__(256)
agg64h_kernel(const uint32_t* __restrict__ p, const float* __restrict__ dis,
              const int* __restrict__ rowptr, const int* __restrict__ deg,
              const int* __restrict__ col, const float* __restrict__ cbias,
              float2* __restrict__ out, int n) {
    int w = (blockIdx.x * blockDim.x + threadIdx.x) >> 5;
    if (w >= n) return;
    int lane = threadIdx.x & 31;
    int start = rowptr[w], d = deg[w];
    uint32_t a = p[(uint32_t)w * 32u + lane];
    float2 f = __half22float2(*(__half2*)&a);
    float ax = f.x, ay = f.y;

    int c0 = 0;
    for (; c0 + 32 <= d; c0 += 32) {
        int idx = col[start + c0 + lane];
#pragma unroll 16
        for (int j = 0; j < 32; j++) {
            uint32_t u = (uint32_t)__shfl_sync(0xffffffffu, idx, j);
            uint32_t v = p[u * 32u + lane];
            float2 g = __half22float2(*(__half2*)&v);
            ax += g.x; ay += g.y;
        }
    }
    int m = d - c0;
    if (m > 0) {
        int idx = (lane < m) ? col[start + c0 + lane] : 0;
        for (int j = 0; j < m; j++) {
            uint32_t u = (uint32_t)__shfl_sync(0xffffffffu, idx, j);
            uint32_t v = p[u * 32u + lane];
            float2 g = __half22float2(*(__half2*)&v);
            ax += g.x; ay += g.y;
        }
    }
    float s = dis[w];
    float2 o = {ax * s + cbias[lane * 2], ay * s + cbias[lane * 2 + 1]};
    out[(uint32_t)w * 32u + lane] = o;
}

// ---------------------------------------------------------------------------
extern "C" void kernel_launch(void* const* d_in, const int* in_sizes, int n_in,
                              void* d_out, int out_size) {
    const float* x     = (const float*)d_in[0];
    const int*   ei    = (const int*)d_in[1];
    const float* W0    = (const float*)d_in[2];
    const float* b0    = (const float*)d_in[3];
    const float* W1    = (const float*)d_in[4];
    const float* b1    = (const float*)d_in[5];
    const float* W2    = (const float*)d_in[6];
    const float* b2    = (const float*)d_in[7];
    const float* gamma = (const float*)d_in[8];
    const float* beta  = (const float*)d_in[9];
    const float* Wf    = (const float*)d_in[10];
    const float* bf    = (const float*)d_in[11];
    float* out = (float*)d_out;

    const int N = in_sizes[0] / 128;
    const int E = in_sizes[1] / 2;
    const int* src = ei;
    const int* dst = ei + E;

    __half *pxh, *yh, *ph, *th, *pzh, *w0h, *w1h, *wch, *wcl;
    float *pzp, *wc, *cbias, *dis;
    int *deg, *rp, *rpc, *col, *bsum;
    cudaGetSymbolAddress((void**)&pxh,   g_pxh);
    cudaGetSymbolAddress((void**)&yh,    g_yh);
    cudaGetSymbolAddress((void**)&ph,    g_ph);
    cudaGetSymbolAddress((void**)&th,    g_th);
    cudaGetSymbolAddress((void**)&pzp,   g_pzp);
    cudaGetSymbolAddress((void**)&pzh,   g_pzh);
    cudaGetSymbolAddress((void**)&wc,    g_wc);
    cudaGetSymbolAddress((void**)&w0h,   g_w0h);
    cudaGetSymbolAddress((void**)&w1h,   g_w1h);
    cudaGetSymbolAddress((void**)&wch,   g_wch);
    cudaGetSymbolAddress((void**)&wcl,   g_wcl);
    cudaGetSymbolAddress((void**)&cbias, g_cbias);
    cudaGetSymbolAddress((void**)&dis,   g_dis);
    cudaGetSymbolAddress((void**)&deg,   g_deg);
    cudaGetSymbolAddress((void**)&rp,    g_rowptr);
    cudaGetSymbolAddress((void**)&rpc,   g_rpcopy);
    cudaGetSymbolAddress((void**)&col,   g_col);
    cudaGetSymbolAddress((void**)&bsum,  g_bsum);

    // 2 created streams + legacy default, 9 events (guard-safe envelope)
    static bool inited = false;
    static cudaStream_t st1, st2;
    static cudaEvent_t evRoot, evDis, evPre, evW, evY0, evY1, evT, ev1, ev2;
    if (!inited) {
        cudaStreamCreateWithFlags(&st1, cudaStreamNonBlocking);
        cudaStreamCreateWithFlags(&st2, cudaStreamNonBlocking);
        cudaEventCreateWithFlags(&evRoot, cudaEventDisableTiming);
        cudaEventCreateWithFlags(&evDis, cudaEventDisableTiming);
        cudaEventCreateWithFlags(&evPre, cudaEventDisableTiming);
        cudaEventCreateWithFlags(&evW,  cudaEventDisableTiming);
        cudaEventCreateWithFlags(&evY0, cudaEventDisableTiming);
        cudaEventCreateWithFlags(&evY1, cudaEventDisableTiming);
        cudaEventCreateWithFlags(&evT,  cudaEventDisableTiming);
        cudaEventCreateWithFlags(&ev1,  cudaEventDisableTiming);
        cudaEventCreateWithFlags(&ev2,  cudaEventDisableTiming);
        cudaFuncSetAttribute(tgemm1p_kernel<3>,
                             cudaFuncAttributeMaxDynamicSharedMemorySize, SMEM_G0);
        cudaFuncSetAttribute(gemm1f_kernel,
                             cudaFuncAttributeMaxDynamicSharedMemorySize, SMEM_G1F);
        inited = true;
    }

    const int TB = 256;
    int nB = (N + TB - 1) / TB;
    int e2B = (E / 2 + TB - 1) / TB + 1;
    int nbScan = (N + SCAN_B - 1) / SCAN_B;
    int aggB = (N * 32 + TB - 1) / TB;
    int gB = (N + 127) / 128;

    const int H = ((N / 2 + 127) / 128) * 128;
    int gB0 = H / 128;
    int gB1 = (N - H + 127) / 128;
    int aB0 = (H * 32 + TB - 1) / TB;
    int aB1 = ((N - H) * 32 + TB - 1) / TB;

    cudaStream_t s0 = 0;

    // --- capture fork for st1 (weights) ---
    zero_kernel<<<nB, TB, 0, s0>>>(deg, N);
    cudaEventRecord(evRoot, s0);
    cudaStreamWaitEvent(st1, evRoot, 0);

    // --- weight folding + fp16 conversion on st1 ---
    wc_kernel<<<384, 64, 0, st1>>>(W2, Wf, wc);
    cbias_kernel<<<1, 64, 0, st1>>>(b2, Wf, bf, cbias);
    convs_kernel<<<(3 * 128 * 128 + 255) / 256, 256, 0, st1>>>(W0, w0h, 3 * 128 * 128);
    convs_kernel<<<(3 * 128 * 128 + 255) / 256, 256, 0, st1>>>(W1, w1h, 3 * 128 * 128);
    convh_kernel<<<(384 * 64 + 255) / 256, 256, 0, st1>>>(wc, wch, wcl, 384 * 64);
    cudaEventRecord(evW, st1);

    // --- graph prep on s0 ---
    count_kernel<<<e2B, TB, 0, s0>>>(dst, deg, E);
    scan1_kernel<<<nbScan, SCAN_B, 0, s0>>>(deg, rp, bsum, dis, N);
    cudaEventRecord(evDis, s0);

    cudaStreamWaitEvent(st2, evDis, 0);
    prescale_h_kernel<<<(N * 32 + TB - 1) / TB, TB, 0, st2>>>(
        (const float4*)x, dis, (uint2*)pxh, N * 32);
    cudaEventRecord(evPre, st2);

    scan2_kernel<<<1, 32, 0, s0>>>(bsum, nbScan);
    scan3_kernel<<<nB, TB, 0, s0>>>(rp, rpc, bsum, N);
    fill_kernel<<<e2B, TB, 0, s0>>>(src, dst, rpc, col, E);

    // --- agg_y in halves (chains start GEMM0(H0) under agg_y(H1)) ---
    cudaStreamWaitEvent(s0, evPre, 0);
    agg128hh_kernel<<<aB0, TB, 0, s0>>>(pxh, dis, rp, deg, col, yh, 0, H);
    cudaEventRecord(evY0, s0);
    agg128hh_kernel<<<aB1, TB, 0, s0>>>(pxh, dis, rp, deg, col, yh, H, N);
    cudaEventRecord(evY1, s0);

    // --- GEMM0 x3 on {s0, st1, st2} ---
    cudaStreamWaitEvent(s0, evW, 0);
    cudaStreamWaitEvent(st2, evW, 0);
    cudaStream_t chain[3] = {s0, st1, st2};
    for (int s = 0; s < 3; s++) {
        cudaStream_t cs = chain[s];
        __half* ph_s = ph + (size_t)s * NN * 128;
        if (cs != s0) cudaStreamWaitEvent(cs, evY0, 0);
        tgemm1p_kernel<3><<<gB0, 256, SMEM_G0, cs>>>(
            yh, w0h + s * 16384, dis, b0 + s * 128,
            gamma + (s * 3 + 0) * 128, beta + (s * 3 + 0) * 128,
            ph_s, 0, N);
        if (cs != s0) cudaStreamWaitEvent(cs, evY1, 0);
        tgemm1p_kernel<3><<<gB1, 256, SMEM_G0, cs>>>(
            yh, w0h + s * 16384, dis, b0 + s * 128,
            gamma + (s * 3 + 0) * 128, beta + (s * 3 + 0) * 128,
            ph_s, H, N);
    }
    cudaEventRecord(ev1, st1);
    cudaEventRecord(ev2, st2);
    cudaStreamWaitEvent(s0, ev1, 0);
    cudaStreamWaitEvent(s0, ev2, 0);

    // --- merged 3-scale mid aggregation (one col pass) ---
    agg384h_kernel<<<aggB, TB, 0, s0>>>(ph, dis, rp, deg, col, th, N);
    cudaEventRecord(evT, s0);
    cudaStreamWaitEvent(st1, evT, 0);
    cudaStreamWaitEvent(st2, evT, 0);

    // --- GEMM1+tail x3 concurrent ---
    for (int s = 0; s < 3; s++) {
        gemm1f_kernel<<<gB, 256, SMEM_G1F, chain[s]>>>(
            th + (size_t)s * NN * 128, w1h + s * 16384,
            wch + s * 8192, wcl + s * 8192,
            b1 + s * 128, gamma + (s * 3 + 1) * 128, beta + (s * 3 + 1) * 128,
            pzp + (size_t)s * NN * 64, N);
    }
    cudaEventRecord(ev1, st1);
    cudaEventRecord(ev2, st2);
    cudaStreamWaitEvent(s0, ev1, 0);
    cudaStreamWaitEvent(s0, ev2, 0);

    // --- sum partials + final aggregation ---
    pzsum_kernel<<<(N * 32 + TB - 1) / TB, TB, 0, s0>>>(
        pzp, pzp + (size_t)NN * 64, pzp + (size_t)2 * NN * 64, dis,
        (uint32_t*)pzh, N * 32);
    agg64h_kernel<<<aggB, TB, 0, s0>>>((const uint32_t*)pzh, dis, rp, deg, col,
                                       cbias, (float2*)out, N);
}